// round 11
// baseline (speedup 1.0000x reference)
#include <cuda_runtime.h>
#include <cuda_bf16.h>
#include <cstdint>
#include <stdint.h>
#include <math.h>

#define Bz 64
#define Ss 784
#define Cc 256
#define Hh 8
#define BH 512

// ---------------- scratch ----------------
__device__ float g_qpool[Bz*Ss*Cc];
__device__ float g_kpool[Bz*Ss*Cc];
__device__ float g_vconv[Bz*Ss*Cc];
__device__ float g_q[BH*Cc*128];
__device__ float g_k[BH*Cc*128];
__device__ float g_invden[BH*Cc];
__device__ __nv_bfloat16 g_xh[Bz*Ss*Cc];
__device__ __nv_bfloat16 g_xl[Bz*Ss*Cc];
__device__ __nv_bfloat16 g_wth[Cc*2304];
__device__ __nv_bfloat16 g_wtl[Cc*2304];
__device__ __nv_bfloat16 g_qpTh[BH*Cc*112];
__device__ __nv_bfloat16 g_qpTl[BH*Cc*112];
__device__ __nv_bfloat16 g_kpTh[BH*Cc*112];
__device__ __nv_bfloat16 g_kpTl[BH*Cc*112];
__device__ __nv_bfloat16 g_wqkTh[Hh*128*112];
__device__ __nv_bfloat16 g_wqkTl[Hh*128*112];
__device__ __nv_bfloat16 g_qsh[BH*Cc*128];
__device__ __nv_bfloat16 g_qsl[BH*Cc*128];
__device__ __nv_bfloat16 g_ksh[BH*Cc*128];
__device__ __nv_bfloat16 g_ksl[BH*Cc*128];
__device__ __nv_bfloat16 g_wh[(size_t)BH*Cc*Cc];
__device__ __nv_bfloat16 g_wl[(size_t)BH*Cc*Cc];
__device__ __nv_bfloat16 g_vph[Bz*Ss*Cc + 8192];
__device__ __nv_bfloat16 g_vpl[Bz*Ss*Cc + 8192];

// ---------------- helpers ----------------
__device__ __forceinline__ uint32_t smem_u32(const void* p) {
    uint32_t a;
    asm("{ .reg .u64 t; cvta.to.shared.u64 t, %1; cvt.u32.u64 %0, t; }" : "=r"(a) : "l"(p));
    return a;
}
__device__ __forceinline__ void cp16(uint32_t dst, const void* src, uint32_t srcsize) {
    asm volatile("cp.async.cg.shared.global [%0], [%1], 16, %2;"
                 :: "r"(dst), "l"(src), "r"(srcsize) : "memory");
}
__device__ __forceinline__ void ldsm_x4(uint32_t* r, uint32_t addr) {
    asm volatile("ldmatrix.sync.aligned.m8n8.x4.shared.b16 {%0,%1,%2,%3}, [%4];"
                 : "=r"(r[0]), "=r"(r[1]), "=r"(r[2]), "=r"(r[3]) : "r"(addr));
}
__device__ __forceinline__ void mma16816(float* c, const uint32_t* a, const uint32_t* b) {
    asm volatile("mma.sync.aligned.m16n8k16.row.col.f32.bf16.bf16.f32 "
                 "{%0,%1,%2,%3}, {%4,%5,%6,%7}, {%8,%9}, {%0,%1,%2,%3};"
                 : "+f"(c[0]), "+f"(c[1]), "+f"(c[2]), "+f"(c[3])
                 : "r"(a[0]), "r"(a[1]), "r"(a[2]), "r"(a[3]), "r"(b[0]), "r"(b[1]));
}
__device__ __forceinline__ void split2(float v, __nv_bfloat16& h, __nv_bfloat16& l) {
    h = __float2bfloat16(v);
    l = __float2bfloat16(v - __bfloat162float(h));
}
__device__ __forceinline__ uint32_t pack2(float v0, float v1, uint32_t& lo) {
    __nv_bfloat16 h0, h1, l0, l1;
    split2(v0, h0, l0); split2(v1, h1, l1);
    lo = (uint32_t)__bfloat16_as_ushort(l0) | ((uint32_t)__bfloat16_as_ushort(l1) << 16);
    return (uint32_t)__bfloat16_as_ushort(h0) | ((uint32_t)__bfloat16_as_ushort(h1) << 16);
}

// ---------------- conv w split ----------------
__global__ __launch_bounds__(256) void split_w_kernel(const float* __restrict__ w) {
    int k = blockIdx.x;
    int co = threadIdx.x;
    float v = w[(size_t)k * 256 + co];
    __nv_bfloat16 h, l;
    split2(v, h, l);
    g_wth[(size_t)co * 2304 + k] = h;
    g_wtl[(size_t)co * 2304 + k] = l;
}

// ---------------- fused pools + x split ----------------
__global__ __launch_bounds__(256) void pool_split_kernel(const float* __restrict__ x) {
    int bs = blockIdx.x;
    int c  = threadIdx.x;
    int b  = bs / 784;
    int pix = bs - b * 784;
    int i = pix / 28, j = pix - i * 28;
    const float* xb = x + (size_t)b * 784 * 256;
    float sum = 0.f, mx = -INFINITY, center = 0.f;
    int cnt = 0;
    #pragma unroll
    for (int di = -1; di <= 1; di++) {
        #pragma unroll
        for (int dj = -1; dj <= 1; dj++) {
            int ii = i + di, jj = j + dj;
            if ((unsigned)ii < 28u && (unsigned)jj < 28u) {
                float v = xb[(size_t)(ii * 28 + jj) * 256 + c];
                sum += v;
                mx = fmaxf(mx, v);
                cnt++;
                if (di == 0 && dj == 0) center = v;
            }
        }
    }
    size_t o = (size_t)bs * 256 + c;
    g_qpool[o] = sum / (float)cnt;
    g_kpool[o] = mx;
    __nv_bfloat16 h, l;
    split2(center, h, l);
    g_xh[o] = h;
    g_xl[o] = l;
}

// ---------------- conv mma: CTA tile 128(m) x 128(n), K staged 64 ----------------
#define CROW 72
#define CA_HI 0
#define CA_LO 18432
#define CB_HI 36864
#define CB_LO 55296
#define CSTAGE 73728
#define CONV_SMEM (2*CSTAGE)

__device__ __forceinline__ void conv_load_stage(
    int s, uint32_t sb, int row2, int half2, int bb, int pi, int pj, int n0g)
{
    uint32_t bufo = sb + (uint32_t)(s & 1) * CSTAGE;
    int tap = s >> 2;
    int di = tap / 3, dj = tap - di * 3;
    int ii = pi + di - 1, jj = pj + dj - 1;
    bool valid = ((unsigned)ii < 28u) && ((unsigned)jj < 28u);
    int ci0 = ((s & 3) << 6) + half2 * 32;
    size_t ga = ((size_t)(bb * 784 + (valid ? ii * 28 + jj : 0)) << 8) + ci0;
    uint32_t rowoff = (uint32_t)(row2 * CROW + half2 * 32) * 2;
    uint32_t vs = valid ? 16u : 0u;
    #pragma unroll
    for (int q = 0; q < 4; q++) {
        cp16(bufo + CA_HI + rowoff + q * 16, g_xh + ga + q * 8, vs);
        cp16(bufo + CA_LO + rowoff + q * 16, g_xl + ga + q * 8, vs);
    }
    // B: 128 rows (cout) x 64 k — same 2-threads-per-row geometry
    size_t gb = (size_t)(n0g + row2) * 2304 + (size_t)s * 64 + half2 * 32;
    #pragma unroll
    for (int q = 0; q < 4; q++) {
        cp16(bufo + CB_HI + rowoff + q * 16, g_wth + gb + q * 8, 16u);
        cp16(bufo + CB_LO + rowoff + q * 16, g_wtl + gb + q * 8, 16u);
    }
    asm volatile("cp.async.commit_group;" ::: "memory");
}

__global__ __launch_bounds__(256) void conv_mma_kernel(const float* __restrict__ bias) {
    extern __shared__ char smem[];
    uint32_t sb = smem_u32(smem);
    int t = threadIdx.x, lane = t & 31, wid = t >> 5;
    int warp_m = wid >> 2, warp_n = wid & 3;      // 2 x 4, warp tile 64x32
    int m0 = blockIdx.x << 7;
    int n0g = blockIdx.y << 7;

    int row2 = t >> 1, half2 = t & 1;
    int m = m0 + row2;
    int bb = m / 784;
    int pix = m - bb * 784;
    int pi = pix / 28, pj = pix - pi * 28;

    float c[4][4][4];
    #pragma unroll
    for (int mb = 0; mb < 4; mb++)
        #pragma unroll
        for (int nb = 0; nb < 4; nb++)
            #pragma unroll
            for (int r = 0; r < 4; r++) c[mb][nb][r] = 0.f;

    int a_r = lane & 15;
    int a_c = (lane >> 4) << 3;
    int b_r = (lane & 7) | ((lane & 16) >> 1);
    int b_c = lane & 8;

    conv_load_stage(0, sb, row2, half2, bb, pi, pj, n0g);

    for (int s = 0; s < 36; s++) {
        if (s + 1 < 36) {
            conv_load_stage(s + 1, sb, row2, half2, bb, pi, pj, n0g);
            asm volatile("cp.async.wait_group 1;" ::: "memory");
        } else {
            asm volatile("cp.async.wait_group 0;" ::: "memory");
        }
        __syncthreads();

        uint32_t bufo = sb + (uint32_t)(s & 1) * CSTAGE;
        #pragma unroll
        for (int kk = 0; kk < 4; kk++) {
            int k0 = kk << 4;
            uint32_t a_hi[4][4], a_lo[4][4];
            #pragma unroll
            for (int mb = 0; mb < 4; mb++) {
                uint32_t off = (uint32_t)((warp_m * 64 + mb * 16 + a_r) * CROW + k0 + a_c) * 2;
                ldsm_x4(a_hi[mb], bufo + CA_HI + off);
                ldsm_x4(a_lo[mb], bufo + CA_LO + off);
            }
            uint32_t b_hi[4][2], b_lo[4][2];
            #pragma unroll
            for (int nb2 = 0; nb2 < 2; nb2++) {
                uint32_t off = (uint32_t)((warp_n * 32 + nb2 * 16 + b_r) * CROW + k0 + b_c) * 2;
                uint32_t r4[4];
                ldsm_x4(r4, bufo + CB_HI + off);
                b_hi[nb2*2][0] = r4[0]; b_hi[nb2*2][1] = r4[1];
                b_hi[nb2*2+1][0] = r4[2]; b_hi[nb2*2+1][1] = r4[3];
                ldsm_x4(r4, bufo + CB_LO + off);
                b_lo[nb2*2][0] = r4[0]; b_lo[nb2*2][1] = r4[1];
                b_lo[nb2*2+1][0] = r4[2]; b_lo[nb2*2+1][1] = r4[3];
            }
            #pragma unroll
            for (int mb = 0; mb < 4; mb++)
                #pragma unroll
                for (int nb = 0; nb < 4; nb++) {
                    mma16816(c[mb][nb], a_hi[mb], b_hi[nb]);
                    mma16816(c[mb][nb], a_hi[mb], b_lo[nb]);
                    mma16816(c[mb][nb], a_lo[mb], b_hi[nb]);
                }
        }
        __syncthreads();
    }

    #pragma unroll
    for (int mb = 0; mb < 4; mb++) {
        int rg = m0 + warp_m * 64 + mb * 16 + (lane >> 2);
        #pragma unroll
        for (int nb = 0; nb < 4; nb++) {
            int cg = n0g + warp_n * 32 + nb * 8 + ((lane & 3) << 1);
            float2 bz = *(const float2*)(bias + cg);
            *(float2*)(g_vconv + (size_t)rg * 256 + cg) =
                make_float2(c[mb][nb][0] + bz.x, c[mb][nb][1] + bz.y);
            *(float2*)(g_vconv + (size_t)(rg + 8) * 256 + cg) =
                make_float2(c[mb][nb][2] + bz.x, c[mb][nb][3] + bz.y);
        }
    }
}

// ---------------- pool of conv output -> bf16 splits ----------------
__global__ __launch_bounds__(256) void pool_v_kernel() {
    int bs = blockIdx.x;
    int c  = threadIdx.x;
    int b  = bs / 784;
    int pix = bs - b * 784;
    int i = pix / 28, j = pix - i * 28;
    const float* xb = g_vconv + (size_t)b * 784 * 256;
    float sum = 0.f;
    int cnt = 0;
    #pragma unroll
    for (int di = -1; di <= 1; di++) {
        #pragma unroll
        for (int dj = -1; dj <= 1; dj++) {
            int ii = i + di, jj = j + dj;
            if ((unsigned)ii < 28u && (unsigned)jj < 28u) {
                sum += xb[(size_t)(ii * 28 + jj) * 256 + c];
                cnt++;
            }
        }
    }
    __nv_bfloat16 h, l;
    split2(sum / (float)cnt, h, l);
    size_t o = (size_t)bs * 256 + c;
    g_vph[o] = h;
    g_vpl[o] = l;
}

// ---------------- pool transpose+split ----------------
__global__ __launch_bounds__(256) void poolT_kernel() {
    __shared__ float tile[32][33];
    int bh = blockIdx.x;
    int which = blockIdx.y;
    int b = bh >> 3, h = bh & 7;
    const float* src = (which ? g_kpool : g_qpool) + ((size_t)b * 784 + h * 98) * 256;
    __nv_bfloat16* dsth = which ? g_kpTh : g_qpTh;
    __nv_bfloat16* dstl = which ? g_kpTl : g_qpTl;
    int t = threadIdx.x;
    int r8 = t >> 5, cl = t & 31;
    for (int dt = 0; dt < 4; dt++) {
        int d0 = dt << 5;
        for (int ct = 0; ct < 8; ct++) {
            int c0 = ct << 5;
            #pragma unroll
            for (int p = 0; p < 4; p++) {
                int dl = r8 + p * 8;
                int d = d0 + dl;
                tile[dl][cl] = (d < 98) ? src[(size_t)d * 256 + c0 + cl] : 0.f;
            }
            __syncthreads();
            #pragma unroll
            for (int p = 0; p < 4; p++) {
                int cr = r8 + p * 8;
                int d = d0 + cl;
                if (d < 112) {
                    __nv_bfloat16 hh, ll;
                    split2(tile[cl][cr], hh, ll);
                    size_t o = ((size_t)bh * 256 + c0 + cr) * 112 + d;
                    dsth[o] = hh;
                    dstl[o] = ll;
                }
            }
            __syncthreads();
        }
    }
}

// ---------------- wqk transpose+split ----------------
__global__ __launch_bounds__(128) void wqkT_kernel(const float* __restrict__ wqk) {
    int h = blockIdx.x;
    int e = threadIdx.x;
    for (int d = 0; d < 112; d++) {
        float v = (d < 98) ? wqk[((size_t)h * 98 + d) * 128 + e] : 0.f;
        __nv_bfloat16 hh, ll;
        split2(v, hh, ll);
        size_t o = ((size_t)h * 128 + e) * 112 + d;
        g_wqkTh[o] = hh;
        g_wqkTl[o] = ll;
    }
}

// ---------------- proj mma ----------------
#define PROW 120
#define PA_HI 0
#define PA_LO 30720
#define PB_HI 61440
#define PB_LO 92160
#define PROJ_SMEM 122880

__global__ __launch_bounds__(256) void proj_mma_kernel(const float* __restrict__ bias) {
    extern __shared__ char smem[];
    uint32_t sb = smem_u32(smem);
    int t = threadIdx.x, lane = t & 31, wid = t >> 5;
    int warp_m = wid >> 1, warp_n = wid & 1;
    int bh = blockIdx.x, chalf = blockIdx.y, which = blockIdx.z;
    int h = bh & 7;
    const __nv_bfloat16* Ah = (which ? g_kpTh : g_qpTh) + ((size_t)bh * 256 + chalf * 128) * 112;
    const __nv_bfloat16* Al = (which ? g_kpTl : g_qpTl) + ((size_t)bh * 256 + chalf * 128) * 112;
    const __nv_bfloat16* Bh = g_wqkTh + (size_t)h * 128 * 112;
    const __nv_bfloat16* Bl = g_wqkTl + (size_t)h * 128 * 112;
    float* outf = which ? g_k : g_q;
    __nv_bfloat16* outh = which ? g_ksh : g_qsh;
    __nv_bfloat16* outl = which ? g_ksl : g_qsl;

    #pragma unroll
    for (int it = 0; it < 7; it++) {
        int idx = t + (it << 8);
        int row = idx / 14, ch = idx - row * 14;
        uint32_t doff = (uint32_t)(row * PROW * 2 + ch * 16);
        cp16(sb + PA_HI + doff, Ah + (size_t)row * 112 + ch * 8, 16u);
        cp16(sb + PA_LO + doff, Al + (size_t)row * 112 + ch * 8, 16u);
        cp16(sb + PB_HI + doff, Bh + (size_t)row * 112 + ch * 8, 16u);
        cp16(sb + PB_LO + doff, Bl + (size_t)row * 112 + ch * 8, 16u);
    }
    asm volatile("cp.async.commit_group;" ::: "memory");
    asm volatile("cp.async.wait_group 0;" ::: "memory");
    __syncthreads();

    float c[2][8][4];
    #pragma unroll
    for (int mb = 0; mb < 2; mb++)
        #pragma unroll
        for (int nb = 0; nb < 8; nb++)
            #pragma unroll
            for (int r = 0; r < 4; r++) c[mb][nb][r] = 0.f;

    int a_r = lane & 15;
    int a_c = (lane >> 4) << 3;
    int b_r = (lane & 7) | ((lane & 16) >> 1);
    int b_c = lane & 8;

    #pragma unroll
    for (int kk = 0; kk < 7; kk++) {
        int k0 = kk << 4;
        uint32_t a_hi[2][4], a_lo[2][4];
        #pragma unroll
        for (int mb = 0; mb < 2; mb++) {
            uint32_t off = (uint32_t)((warp_m * 32 + mb * 16 + a_r) * PROW + k0 + a_c) * 2;
            ldsm_x4(a_hi[mb], sb + PA_HI + off);
            ldsm_x4(a_lo[mb], sb + PA_LO + off);
        }
        uint32_t b_hi[8][2], b_lo[8][2];
        #pragma unroll
        for (int nb2 = 0; nb2 < 4; nb2++) {
            uint32_t off = (uint32_t)((warp_n * 64 + nb2 * 16 + b_r) * PROW + k0 + b_c) * 2;
            uint32_t r4[4];
            ldsm_x4(r4, sb + PB_HI + off);
            b_hi[nb2*2][0] = r4[0]; b_hi[nb2*2][1] = r4[1];
            b_hi[nb2*2+1][0] = r4[2]; b_hi[nb2*2+1][1] = r4[3];
            ldsm_x4(r4, sb + PB_LO + off);
            b_lo[nb2*2][0] = r4[0]; b_lo[nb2*2][1] = r4[1];
            b_lo[nb2*2+1][0] = r4[2]; b_lo[nb2*2+1][1] = r4[3];
        }
        #pragma unroll
        for (int mb = 0; mb < 2; mb++)
            #pragma unroll
            for (int nb = 0; nb < 8; nb++) {
                mma16816(c[mb][nb], a_hi[mb], b_hi[nb]);
                mma16816(c[mb][nb], a_hi[mb], b_lo[nb]);
                mma16816(c[mb][nb], a_lo[mb], b_hi[nb]);
            }
    }

    #pragma unroll
    for (int mb = 0; mb < 2; mb++) {
        #pragma unroll
        for (int half = 0; half < 2; half++) {
            int cr = chalf * 128 + warp_m * 32 + mb * 16 + (lane >> 2) + half * 8;
            size_t rowo = ((size_t)bh * 256 + cr) * 128;
            #pragma unroll
            for (int nb = 0; nb < 8; nb++) {
                int e = warp_n * 64 + nb * 8 + ((lane & 3) << 1);
                float2 bz = *(const float2*)(bias + h * 128 + e);
                float v0 = c[mb][nb][half*2+0] + bz.x;
                float v1 = c[mb][nb][half*2+1] + bz.y;
                *(float2*)(outf + rowo + e) = make_float2(v0, v1);
                uint32_t lo;
                uint32_t hi = pack2(v0, v1, lo);
                *(uint32_t*)(outh + rowo + e) = hi;
                *(uint32_t*)(outl + rowo + e) = lo;
            }
        }
    }
}

// ---------------- temperature ----------------
__global__ __launch_bounds__(256) void temp_kernel(const float* __restrict__ wp_w,
                                                   const float* __restrict__ wp_b) {
    __shared__ float kbar[128];
    __shared__ float part[256];
    __shared__ float rowmean[256];
    int bh = blockIdx.x;
    int t = threadIdx.x;
    const float* kb = g_k + (size_t)bh * Cc * 128;
    const float* qb = g_q + (size_t)bh * Cc * 128;
    {
        int col = t & 127, half = t >> 7;
        float s = 0.f;
        for (int f = half * 128; f < half * 128 + 128; f++) s += kb[(size_t)f * 128 + col];
        part[t] = s;
    }
    __syncthreads();
    if (t < 128) kbar[t] = (part[t] + part[t + 128]) * (1.f / 256.f);
    __syncthreads();
    int w = t >> 5, lane = t & 31;
    float4 kv = *(const float4*)&kbar[lane << 2];
    for (int r = 0; r < 32; r++) {
        int c = (w << 5) + r;
        float4 qv = *(const float4*)(qb + (size_t)c * 128 + (lane << 2));
        float p = qv.x * kv.x + qv.y * kv.y + qv.z * kv.z + qv.w * kv.w;
        #pragma unroll
        for (int o = 16; o; o >>= 1) p += __shfl_xor_sync(0xFFFFFFFFu, p, o);
        if (lane == 0) rowmean[c] = p;
    }
    __syncthreads();
    float s = wp_b[t];
    for (int cc = 0; cc < 256; cc++) s += rowmean[cc] * wp_w[(size_t)cc * 256 + t];
    float sig = 1.f / (1.f + expf(-s));
    g_invden[(size_t)bh * 256 + t] = exp2f(-7.f * (0.2f + sig));
}

// ---------------- fused scores + softmax -> bf16 weight splits ----------------
#define SROW 136
#define SQ_HI 0
#define SQ_LO 17408
#define SK_HI 34816
#define SK_LO 104448
#define SRED  174080
#define SS_SMEM 176128

__global__ __launch_bounds__(256) void scores_softmax_kernel() {
    extern __shared__ char smem[];
    uint32_t sb = smem_u32(smem);
    float* red = (float*)(smem + SRED);
    int t = threadIdx.x, lane = t & 31, wid = t >> 5;
    int warp_m = wid >> 2, warp_n = wid & 3;
    int bh = blockIdx.x, c0 = blockIdx.y << 6;

    #pragma unroll
    for (int it = 0; it < 4; it++) {
        int idx = t + (it << 8);
        int row = idx >> 4, u = idx & 15;
        size_t src = ((size_t)(bh * 256 + c0 + row)) * 128 + u * 8;
        uint32_t off = (uint32_t)(row * SROW + u * 8) * 2;
        *(uint4*)(smem + SQ_HI + off) = *(const uint4*)(g_qsh + src);
        *(uint4*)(smem + SQ_LO + off) = *(const uint4*)(g_qsl + src);
    }
    #pragma unroll
    for (int it = 0; it < 16; it++) {
        int idx = t + (it << 8);
        int row = idx >> 4, u = idx & 15;
        size_t src = ((size_t)(bh * 256 + row)) * 128 + u * 8;
        uint32_t off = (uint32_t)(row * SROW + u * 8) * 2;
        *(uint4*)(smem + SK_HI + off) = *(const uint4*)(g_ksh + src);
        *(uint4*)(smem + SK_LO + off) = *(const uint4*)(g_ksl + src);
    }
    __syncthreads();

    float c[2][8][4];
    #pragma unroll
    for (int mb = 0; mb < 2; mb++)
        #pragma unroll
        for (int nb = 0; nb < 8; nb++)
            #pragma unroll
            for (int r = 0; r < 4; r++) c[mb][nb][r] = 0.f;

    int a_r = lane & 15;
    int a_c = (lane >> 4) << 3;
    int b_r = (lane & 7) | ((lane & 16) >> 1);
    int b_c = lane & 8;

    #pragma unroll
    for (int kk = 0; kk < 8; kk++) {
        int k0 = kk << 4;
        uint32_t a_hi[2][4], a_lo[2][4];
        #pragma unroll
        for (int mb = 0; mb < 2; mb++) {
            uint32_t off = (uint32_t)((warp_m * 32 + mb * 16 + a_r) * SROW + k0 + a_c) * 2;
            ldsm_x4(a_hi[mb], sb + SQ_HI + off);
            ldsm_x4(a_lo[mb], sb + SQ_LO + off);
        }
        uint32_t b_hi[8][2], b_lo[8][2];
        #pragma unroll
        for (int nb2 = 0; nb2 < 4; nb2++) {
            uint32_t off = (uint32_t)((warp_n * 64 + nb2 * 16 + b_r) * SROW + k0 + b_c) * 2;
            uint32_t r4[4];
            ldsm_x4(r4, sb + SK_HI + off);
            b_hi[nb2*2][0] = r4[0]; b_hi[nb2*2][1] = r4[1];
            b_hi[nb2*2+1][0] = r4[2]; b_hi[nb2*2+1][1] = r4[3];
            ldsm_x4(r4, sb + SK_LO + off);
            b_lo[nb2*2][0] = r4[0]; b_lo[nb2*2][1] = r4[1];
            b_lo[nb2*2+1][0] = r4[2]; b_lo[nb2*2+1][1] = r4[3];
        }
        #pragma unroll
        for (int mb = 0; mb < 2; mb++)
            #pragma unroll
            for (int nb = 0; nb < 8; nb++) {
                mma16816(c[mb][nb], a_hi[mb], b_hi[nb]);
                mma16816(c[mb][nb], a_hi[mb], b_lo[nb]);
                mma16816(c[mb][nb], a_lo[mb], b_hi[nb]);
            }
    }

    float invd[2][2];
    #pragma unroll
    for (int mb = 0; mb < 2; mb++) {
        int rb = warp_m * 32 + mb * 16 + (lane >> 2);
        invd[mb][0] = g_invden[(size_t)bh * 256 + c0 + rb];
        invd[mb][1] = g_invden[(size_t)bh * 256 + c0 + rb + 8];
    }
    #pragma unroll
    for (int mb = 0; mb < 2; mb++)
        #pragma unroll
        for (int nb = 0; nb < 8; nb++) {
            c[mb][nb][0] *= invd[mb][0];
            c[mb][nb][1] *= invd[mb][0];
            c[mb][nb][2] *= invd[mb][1];
            c[mb][nb][3] *= invd[mb][1];
        }

    #pragma unroll
    for (int mb = 0; mb < 2; mb++)
        #pragma unroll
        for (int half = 0; half < 2; half++) {
            float mx = -INFINITY;
            #pragma unroll
            for (int nb = 0; nb < 8; nb++) {
                mx = fmaxf(mx, c[mb][nb][half*2+0]);
                mx = fmaxf(mx, c[mb][nb][half*2+1]);
            }
            mx = fmaxf(mx, __shfl_xor_sync(0xFFFFFFFFu, mx, 1));
            mx = fmaxf(mx, __shfl_xor_sync(0xFFFFFFFFu, mx, 2));
            if ((lane & 3) == 0) {
                int r = warp_m * 32 + mb * 16 + (lane >> 2) + half * 8;
                red[r * 8 + warp_n] = mx;
            }
        }
    __syncthreads();
    float bm[2][2];
    #pragma unroll
    for (int mb = 0; mb < 2; mb++)
        #pragma unroll
        for (int half = 0; half < 2; half++) {
            int r = warp_m * 32 + mb * 16 + (lane >> 2) + half * 8;
            bm[mb][half] = fmaxf(fmaxf(red[r*8+0], red[r*8+1]), fmaxf(red[r*8+2], red[r*8+3]));
        }
    #pragma unroll
    for (int mb = 0; mb < 2; mb++)
        #pragma unroll
        for (int half = 0; half < 2; half++) {
            float s = 0.f;
            #pragma unroll
            for (int nb = 0; nb < 8; nb++) {
                float e0 = expf(c[mb][nb][half*2+0] - bm[mb][half]);
                float e1 = expf(c[mb][nb][half*2+1] - bm[mb][half]);
                c[mb][nb][half*2+0] = e0;
                c[mb][nb][half*2+1] = e1;
                s += e0 + e1;
            }
            s += __shfl_xor_sync(0xFFFFFFFFu, s, 1);
            s += __shfl_xor_sync(0xFFFFFFFFu, s, 2);
            if ((lane & 3) == 0) {
                int r = warp_m * 32 + mb * 16 + (lane >> 2) + half * 8;
                red[r * 8 + 4 + warp_n] = s;
            }
        }
    __syncthreads();
    #pragma unroll
    for (int mb = 0; mb < 2; mb++)
        #pragma unroll
        for (int half = 0; half < 2; half++) {
            int r = warp_m * 32 + mb * 16 + (lane >> 2) + half * 8;
            float tot = red[r*8+4] + red[r*8+5] + red[r*8+6] + red[r*8+7];
            float inv = 1.f / tot;
            size_t rowbase = ((size_t)bh * 256 + c0 + r) * 256;
            #pragma unroll
            for (int nb = 0; nb < 8; nb++) {
                int f = warp_n * 64 + nb * 8 + ((lane & 3) << 1);
                uint32_t lo;
                uint32_t hi = pack2(c[mb][nb][half*2+0] * inv, c[mb][nb][half*2+1] * inv, lo);
                *(uint32_t*)(g_wh + rowbase + f) = hi;
                *(uint32_t*)(g_wl + rowbase + f) = lo;
            }
        }
}

// ---------------- att mma (transposed) ----------------
#define AROW 72
#define AA_HI 0
#define AA_LO 18432
#define AB_HI 36864
#define AB_LO 55296
#define ASTAGE 73728
#define ATT_SMEM (2*ASTAGE)

__device__ __forceinline__ void att_load_stage(
    uint32_t bufo, int f0, size_t abase, size_t bbase, int lrow, int lch)
{
    #pragma unroll
    for (int p = 0; p < 4; p++) {
        int row = lrow + p * 32;
        size_t asrc = abase + (size_t)row * 256 + f0 + lch * 8;
        size_t bsrc = bbase + (size_t)row * 256 + f0 + lch * 8;
        uint32_t doff = (uint32_t)(row * AROW + lch * 8) * 2;
        cp16(bufo + AA_HI + doff, g_vph + asrc, 16u);
        cp16(bufo + AA_LO + doff, g_vpl + asrc, 16u);
        cp16(bufo + AB_HI + doff, g_wh + bsrc, 16u);
        cp16(bufo + AB_LO + doff, g_wl + bsrc, 16u);
    }
    asm volatile("cp.async.commit_group;" ::: "memory");
}

__global__ __launch_bounds__(256) void att_mma_kernel(const float* __restrict__ x,
                                                      float* __restrict__ out) {
    extern __shared__ char smem[];
    uint32_t sb = smem_u32(smem);
    int t = threadIdx.x, lane = t & 31, wid = t >> 5;
    int warp_m = wid >> 1, warp_n = wid & 1;
    int bh = blockIdx.x, chalf = blockIdx.y;
    int b = bh >> 3, h = bh & 7;
    size_t abase = ((size_t)b * 784 + h * 98) * 256;
    size_t bbase = ((size_t)bh * 256 + chalf * 128) * 256;

    int lrow = t >> 3, lch = t & 7;

    att_load_stage(sb, 0, abase, bbase, lrow, lch);

    float c[2][8][4];
    #pragma unroll
    for (int mb = 0; mb < 2; mb++)
        #pragma unroll
        for (int nb = 0; nb < 8; nb++)
            #pragma unroll
            for (int r = 0; r < 4; r++) c[mb][nb][r] = 0.f;

    int a_r = lane & 15;
    int a_c = (lane >> 4) << 3;
    int b_r = (lane & 7) | ((lane & 16) >> 1);
    int b_c = lane & 8;

    for (int s = 0; s < 4; s++) {
        if (s + 1 < 4) {
            att_load_stage(sb + (uint32_t)((s + 1) & 1) * ASTAGE, (s + 1) << 6,
                           abase, bbase, lrow, lch);
            asm volatile("cp.async.wait_group 1;" ::: "memory");
        } else {
            asm volatile("cp.async.wait_group 0;" ::: "memory");
        }
        __syncthreads();

        uint32_t bufo = sb + (uint32_t)(s & 1) * ASTAGE;
        #pragma unroll
        for (int kk = 0; kk < 4; kk++) {
            int k0 = kk << 4;
            uint32_t a_hi[2][4], a_lo[2][4];
            #pragma unroll
            for (int mb = 0; mb < 2; mb++) {
                uint32_t off = (uint32_t)((warp_m * 32 + mb * 16 + a_r) * AROW + k0 + a_c) * 2;
                ldsm_x4(a_hi[mb], bufo + AA_HI + off);
                ldsm_x4(a_lo[mb], bufo + AA_LO + off);
            }
            uint32_t b_hi[8][2], b_lo[8][2];
            #pragma unroll
            for (int nb2 = 0; nb2 < 4; nb2++) {
                uint32_t off = (uint32_t)((warp_n * 64 + nb2 * 16 + b_r) * AROW + k0 + b_c) * 2;
                uint32_t r4[4];
                ldsm_x4(r4, bufo + AB_HI + off);
                b_hi[nb2*2][0] = r4[0]; b_hi[nb2*2][1] = r4[1];
                b_hi[nb2*2+1][0] = r4[2]; b_hi[nb2*2+1][1] = r4[3];
                ldsm_x4(r4, bufo + AB_LO + off);
                b_lo[nb2*2][0] = r4[0]; b_lo[nb2*2][1] = r4[1];
                b_lo[nb2*2+1][0] = r4[2]; b_lo[nb2*2+1][1] = r4[3];
            }
            #pragma unroll
            for (int mb = 0; mb < 2; mb++)
                #pragma unroll
                for (int nb = 0; nb < 8; nb++) {
                    mma16816(c[mb][nb], a_hi[mb], b_hi[nb]);
                    mma16816(c[mb][nb], a_hi[mb], b_lo[nb]);
                    mma16816(c[mb][nb], a_lo[mb], b_hi[nb]);
                }
        }
        __syncthreads();
    }

    #pragma unroll
    for (int mb = 0; mb < 2; mb++)
        #pragma unroll
        for (int half = 0; half < 2; half++) {
            int d = warp_m * 32 + mb * 16 + (lane >> 2) + half * 8;
            if (d < 98) {
                size_t rowo = abase + (size_t)d * 256 + chalf * 128;
                #pragma unroll
                for (int nb = 0; nb < 8; nb++) {
                    int cg = warp_n * 64 + nb * 8 + ((lane & 3) << 1);
                    float2 xv = *(const float2*)(x + rowo + cg);
                    *(float2*)(out + rowo + cg) =
                        make_float2(xv.x + c[mb][nb][half*2+0], xv.y + c[mb][nb][half*2+1]);
                }
            }
        }
}

// ---------------- launch ----------------
extern "C" void kernel_launch(void* const* d_in, const int* in_sizes, int n_in,
                              void* d_out, int out_size) {
    const float* x     = (const float*)d_in[0];
    const float* wqk_w = (const float*)d_in[1];
    const float* wqk_b = (const float*)d_in[2];
    const float* wp_w  = (const float*)d_in[3];
    const float* wp_b  = (const float*)d_in[4];
    const float* wv_w  = (const float*)d_in[5];
    const float* wv_b  = (const float*)d_in[6];
    float* out = (float*)d_out;

    cudaFuncSetAttribute(conv_mma_kernel, cudaFuncAttributeMaxDynamicSharedMemorySize, CONV_SMEM);
    cudaFuncSetAttribute(scores_softmax_kernel, cudaFuncAttributeMaxDynamicSharedMemorySize, SS_SMEM);
    cudaFuncSetAttribute(proj_mma_kernel, cudaFuncAttributeMaxDynamicSharedMemorySize, PROJ_SMEM);
    cudaFuncSetAttribute(att_mma_kernel, cudaFuncAttributeMaxDynamicSharedMemorySize, ATT_SMEM);

    pool_split_kernel<<<Bz * Ss, 256>>>(x);
    split_w_kernel<<<2304, 256>>>(wv_w);
    conv_mma_kernel<<<dim3(392, 2), 256, CONV_SMEM>>>(wv_b);
    pool_v_kernel<<<Bz * Ss, 256>>>();
    poolT_kernel<<<dim3(512, 2), 256>>>();
    wqkT_kernel<<<8, 128>>>(wqk_w);
    proj_mma_kernel<<<dim3(512, 2, 2), 256, PROJ_SMEM>>>(wqk_b);
    temp_kernel<<<512, 256>>>(wp_w, wp_b);
    scores_softmax_kernel<<<dim3(512, 4), 256, SS_SMEM>>>();
    att_mma_kernel<<<dim3(512, 2), 256, ATT_SMEM>>>(x, out);
}

// round 12
// speedup vs baseline: 1.0097x; 1.0097x over previous
#include <cuda_runtime.h>
#include <cuda_bf16.h>
#include <cstdint>
#include <stdint.h>
#include <math.h>

#define Bz 64
#define Ss 784
#define Cc 256
#define Hh 8
#define BH 512

// ---------------- scratch ----------------
__device__ float g_vconv[Bz*Ss*Cc];
__device__ float g_q[BH*Cc*128];
__device__ float g_k[BH*Cc*128];
__device__ float g_invden[BH*Cc];
__device__ __nv_bfloat16 g_xh[Bz*Ss*Cc];
__device__ __nv_bfloat16 g_xl[Bz*Ss*Cc];
__device__ __nv_bfloat16 g_wth[Cc*2304];
__device__ __nv_bfloat16 g_wtl[Cc*2304];
__device__ __nv_bfloat16 g_qpTh[BH*Cc*112];
__device__ __nv_bfloat16 g_qpTl[BH*Cc*112];
__device__ __nv_bfloat16 g_kpTh[BH*Cc*112];
__device__ __nv_bfloat16 g_kpTl[BH*Cc*112];
__device__ __nv_bfloat16 g_wqkTh[Hh*128*112];
__device__ __nv_bfloat16 g_wqkTl[Hh*128*112];
__device__ __nv_bfloat16 g_qsh[BH*Cc*128];
__device__ __nv_bfloat16 g_qsl[BH*Cc*128];
__device__ __nv_bfloat16 g_ksh[BH*Cc*128];
__device__ __nv_bfloat16 g_ksl[BH*Cc*128];
__device__ __nv_bfloat16 g_wh[(size_t)BH*Cc*Cc];   // weights hi only
__device__ __nv_bfloat16 g_vph[Bz*Ss*Cc + 8192];
__device__ __nv_bfloat16 g_vpl[Bz*Ss*Cc + 8192];

// ---------------- helpers ----------------
__device__ __forceinline__ uint32_t smem_u32(const void* p) {
    uint32_t a;
    asm("{ .reg .u64 t; cvta.to.shared.u64 t, %1; cvt.u32.u64 %0, t; }" : "=r"(a) : "l"(p));
    return a;
}
__device__ __forceinline__ void cp16(uint32_t dst, const void* src, uint32_t srcsize) {
    asm volatile("cp.async.cg.shared.global [%0], [%1], 16, %2;"
                 :: "r"(dst), "l"(src), "r"(srcsize) : "memory");
}
__device__ __forceinline__ void ldsm_x4(uint32_t* r, uint32_t addr) {
    asm volatile("ldmatrix.sync.aligned.m8n8.x4.shared.b16 {%0,%1,%2,%3}, [%4];"
                 : "=r"(r[0]), "=r"(r[1]), "=r"(r[2]), "=r"(r[3]) : "r"(addr));
}
__device__ __forceinline__ void mma16816(float* c, const uint32_t* a, const uint32_t* b) {
    asm volatile("mma.sync.aligned.m16n8k16.row.col.f32.bf16.bf16.f32 "
                 "{%0,%1,%2,%3}, {%4,%5,%6,%7}, {%8,%9}, {%0,%1,%2,%3};"
                 : "+f"(c[0]), "+f"(c[1]), "+f"(c[2]), "+f"(c[3])
                 : "r"(a[0]), "r"(a[1]), "r"(a[2]), "r"(a[3]), "r"(b[0]), "r"(b[1]));
}
__device__ __forceinline__ void split2(float v, __nv_bfloat16& h, __nv_bfloat16& l) {
    h = __float2bfloat16(v);
    l = __float2bfloat16(v - __bfloat162float(h));
}
__device__ __forceinline__ uint32_t pack2(float v0, float v1, uint32_t& lo) {
    __nv_bfloat16 h0, h1, l0, l1;
    split2(v0, h0, l0); split2(v1, h1, l1);
    lo = (uint32_t)__bfloat16_as_ushort(l0) | ((uint32_t)__bfloat16_as_ushort(l1) << 16);
    return (uint32_t)__bfloat16_as_ushort(h0) | ((uint32_t)__bfloat16_as_ushort(h1) << 16);
}

// ---------------- x split (vectorized single pass) ----------------
__global__ __launch_bounds__(256) void split_x_kernel(const float* __restrict__ x) {
    int idx4 = blockIdx.x * 256 + threadIdx.x;
    float4 v = ((const float4*)x)[idx4];
    uint32_t l01, l23;
    uint32_t h01 = pack2(v.x, v.y, l01);
    uint32_t h23 = pack2(v.z, v.w, l23);
    ((uint2*)g_xh)[idx4] = make_uint2(h01, h23);
    ((uint2*)g_xl)[idx4] = make_uint2(l01, l23);
}

// ---------------- conv w split ----------------
__global__ __launch_bounds__(256) void split_w_kernel(const float* __restrict__ w) {
    int k = blockIdx.x;
    int co = threadIdx.x;
    float v = w[(size_t)k * 256 + co];
    __nv_bfloat16 h, l;
    split2(v, h, l);
    g_wth[(size_t)co * 2304 + k] = h;
    g_wtl[(size_t)co * 2304 + k] = l;
}

// ---------------- fused avg/max pool + transpose + split: x -> [bh][c][112] ----------------
__global__ __launch_bounds__(256) void poolqkT_kernel(const float* __restrict__ x) {
    __shared__ float ta[32][33];
    __shared__ float tm[32][33];
    int bh = blockIdx.x;
    int b = bh >> 3, h = bh & 7;
    const float* xb = x + (size_t)b * 784 * 256;
    int t = threadIdx.x;
    int r8 = t >> 5, cl = t & 31;
    for (int dt = 0; dt < 4; dt++) {
        int d0 = dt << 5;
        for (int ct = 0; ct < 8; ct++) {
            int c0 = ct << 5;
            #pragma unroll
            for (int p = 0; p < 4; p++) {
                int dl = r8 + p * 8;
                int d = d0 + dl;
                float sum = 0.f, mx = -INFINITY;
                int cnt = 0;
                if (d < 98) {
                    int s = h * 98 + d;
                    int i = s / 28, j = s - i * 28;
                    #pragma unroll
                    for (int di = -1; di <= 1; di++)
                        #pragma unroll
                        for (int dj = -1; dj <= 1; dj++) {
                            int ii = i + di, jj = j + dj;
                            if ((unsigned)ii < 28u && (unsigned)jj < 28u) {
                                float v = xb[(size_t)(ii * 28 + jj) * 256 + c0 + cl];
                                sum += v;
                                mx = fmaxf(mx, v);
                                cnt++;
                            }
                        }
                    ta[dl][cl] = sum / (float)cnt;
                    tm[dl][cl] = mx;
                } else {
                    ta[dl][cl] = 0.f;
                    tm[dl][cl] = 0.f;
                }
            }
            __syncthreads();
            #pragma unroll
            for (int p = 0; p < 4; p++) {
                int cr = r8 + p * 8;
                int d = d0 + cl;
                if (d < 112) {
                    size_t o = ((size_t)bh * 256 + c0 + cr) * 112 + d;
                    __nv_bfloat16 hh, ll;
                    split2(ta[cl][cr], hh, ll);
                    g_qpTh[o] = hh; g_qpTl[o] = ll;
                    split2(tm[cl][cr], hh, ll);
                    g_kpTh[o] = hh; g_kpTl[o] = ll;
                }
            }
            __syncthreads();
        }
    }
}

// ---------------- conv mma: CTA tile 128x128, K staged 64 ----------------
#define CROW 72
#define CA_HI 0
#define CA_LO 18432
#define CB_HI 36864
#define CB_LO 55296
#define CSTAGE 73728
#define CONV_SMEM (2*CSTAGE)

__device__ __forceinline__ void conv_load_stage(
    int s, uint32_t sb, int row2, int half2, int bb, int pi, int pj, int n0g)
{
    uint32_t bufo = sb + (uint32_t)(s & 1) * CSTAGE;
    int tap = s >> 2;
    int di = tap / 3, dj = tap - di * 3;
    int ii = pi + di - 1, jj = pj + dj - 1;
    bool valid = ((unsigned)ii < 28u) && ((unsigned)jj < 28u);
    int ci0 = ((s & 3) << 6) + half2 * 32;
    size_t ga = ((size_t)(bb * 784 + (valid ? ii * 28 + jj : 0)) << 8) + ci0;
    uint32_t rowoff = (uint32_t)(row2 * CROW + half2 * 32) * 2;
    uint32_t vs = valid ? 16u : 0u;
    #pragma unroll
    for (int q = 0; q < 4; q++) {
        cp16(bufo + CA_HI + rowoff + q * 16, g_xh + ga + q * 8, vs);
        cp16(bufo + CA_LO + rowoff + q * 16, g_xl + ga + q * 8, vs);
    }
    size_t gb = (size_t)(n0g + row2) * 2304 + (size_t)s * 64 + half2 * 32;
    #pragma unroll
    for (int q = 0; q < 4; q++) {
        cp16(bufo + CB_HI + rowoff + q * 16, g_wth + gb + q * 8, 16u);
        cp16(bufo + CB_LO + rowoff + q * 16, g_wtl + gb + q * 8, 16u);
    }
    asm volatile("cp.async.commit_group;" ::: "memory");
}

__global__ __launch_bounds__(256) void conv_mma_kernel(const float* __restrict__ bias) {
    extern __shared__ char smem[];
    uint32_t sb = smem_u32(smem);
    int t = threadIdx.x, lane = t & 31, wid = t >> 5;
    int warp_m = wid >> 2, warp_n = wid & 3;
    int m0 = blockIdx.x << 7;
    int n0g = blockIdx.y << 7;

    int row2 = t >> 1, half2 = t & 1;
    int m = m0 + row2;
    int bb = m / 784;
    int pix = m - bb * 784;
    int pi = pix / 28, pj = pix - pi * 28;

    float c[4][4][4];
    #pragma unroll
    for (int mb = 0; mb < 4; mb++)
        #pragma unroll
        for (int nb = 0; nb < 4; nb++)
            #pragma unroll
            for (int r = 0; r < 4; r++) c[mb][nb][r] = 0.f;

    int a_r = lane & 15;
    int a_c = (lane >> 4) << 3;
    int b_r = (lane & 7) | ((lane & 16) >> 1);
    int b_c = lane & 8;

    conv_load_stage(0, sb, row2, half2, bb, pi, pj, n0g);

    for (int s = 0; s < 36; s++) {
        if (s + 1 < 36) {
            conv_load_stage(s + 1, sb, row2, half2, bb, pi, pj, n0g);
            asm volatile("cp.async.wait_group 1;" ::: "memory");
        } else {
            asm volatile("cp.async.wait_group 0;" ::: "memory");
        }
        __syncthreads();

        uint32_t bufo = sb + (uint32_t)(s & 1) * CSTAGE;
        #pragma unroll
        for (int kk = 0; kk < 4; kk++) {
            int k0 = kk << 4;
            uint32_t a_hi[4][4], a_lo[4][4];
            #pragma unroll
            for (int mb = 0; mb < 4; mb++) {
                uint32_t off = (uint32_t)((warp_m * 64 + mb * 16 + a_r) * CROW + k0 + a_c) * 2;
                ldsm_x4(a_hi[mb], bufo + CA_HI + off);
                ldsm_x4(a_lo[mb], bufo + CA_LO + off);
            }
            uint32_t b_hi[4][2], b_lo[4][2];
            #pragma unroll
            for (int nb2 = 0; nb2 < 2; nb2++) {
                uint32_t off = (uint32_t)((warp_n * 32 + nb2 * 16 + b_r) * CROW + k0 + b_c) * 2;
                uint32_t r4[4];
                ldsm_x4(r4, bufo + CB_HI + off);
                b_hi[nb2*2][0] = r4[0]; b_hi[nb2*2][1] = r4[1];
                b_hi[nb2*2+1][0] = r4[2]; b_hi[nb2*2+1][1] = r4[3];
                ldsm_x4(r4, bufo + CB_LO + off);
                b_lo[nb2*2][0] = r4[0]; b_lo[nb2*2][1] = r4[1];
                b_lo[nb2*2+1][0] = r4[2]; b_lo[nb2*2+1][1] = r4[3];
            }
            #pragma unroll
            for (int mb = 0; mb < 4; mb++)
                #pragma unroll
                for (int nb = 0; nb < 4; nb++) {
                    mma16816(c[mb][nb], a_hi[mb], b_hi[nb]);
                    mma16816(c[mb][nb], a_hi[mb], b_lo[nb]);
                    mma16816(c[mb][nb], a_lo[mb], b_hi[nb]);
                }
        }
        __syncthreads();
    }

    #pragma unroll
    for (int mb = 0; mb < 4; mb++) {
        int rg = m0 + warp_m * 64 + mb * 16 + (lane >> 2);
        #pragma unroll
        for (int nb = 0; nb < 4; nb++) {
            int cg = n0g + warp_n * 32 + nb * 8 + ((lane & 3) << 1);
            float2 bz = *(const float2*)(bias + cg);
            *(float2*)(g_vconv + (size_t)rg * 256 + cg) =
                make_float2(c[mb][nb][0] + bz.x, c[mb][nb][1] + bz.y);
            *(float2*)(g_vconv + (size_t)(rg + 8) * 256 + cg) =
                make_float2(c[mb][nb][2] + bz.x, c[mb][nb][3] + bz.y);
        }
    }
}

// ---------------- pool of conv output -> bf16 splits ----------------
__global__ __launch_bounds__(256) void pool_v_kernel() {
    int bs = blockIdx.x;
    int c  = threadIdx.x;
    int b  = bs / 784;
    int pix = bs - b * 784;
    int i = pix / 28, j = pix - i * 28;
    const float* xb = g_vconv + (size_t)b * 784 * 256;
    float sum = 0.f;
    int cnt = 0;
    #pragma unroll
    for (int di = -1; di <= 1; di++) {
        #pragma unroll
        for (int dj = -1; dj <= 1; dj++) {
            int ii = i + di, jj = j + dj;
            if ((unsigned)ii < 28u && (unsigned)jj < 28u) {
                sum += xb[(size_t)(ii * 28 + jj) * 256 + c];
                cnt++;
            }
        }
    }
    __nv_bfloat16 h, l;
    split2(sum / (float)cnt, h, l);
    size_t o = (size_t)bs * 256 + c;
    g_vph[o] = h;
    g_vpl[o] = l;
}

// ---------------- wqk transpose+split ----------------
__global__ __launch_bounds__(128) void wqkT_kernel(const float* __restrict__ wqk) {
    int h = blockIdx.x;
    int e = threadIdx.x;
    for (int d = 0; d < 112; d++) {
        float v = (d < 98) ? wqk[((size_t)h * 98 + d) * 128 + e] : 0.f;
        __nv_bfloat16 hh, ll;
        split2(v, hh, ll);
        size_t o = ((size_t)h * 128 + e) * 112 + d;
        g_wqkTh[o] = hh;
        g_wqkTl[o] = ll;
    }
}

// ---------------- proj mma ----------------
#define PROW 120
#define PA_HI 0
#define PA_LO 30720
#define PB_HI 61440
#define PB_LO 92160
#define PROJ_SMEM 122880

__global__ __launch_bounds__(256) void proj_mma_kernel(const float* __restrict__ bias) {
    extern __shared__ char smem[];
    uint32_t sb = smem_u32(smem);
    int t = threadIdx.x, lane = t & 31, wid = t >> 5;
    int warp_m = wid >> 1, warp_n = wid & 1;
    int bh = blockIdx.x, chalf = blockIdx.y, which = blockIdx.z;
    int h = bh & 7;
    const __nv_bfloat16* Ah = (which ? g_kpTh : g_qpTh) + ((size_t)bh * 256 + chalf * 128) * 112;
    const __nv_bfloat16* Al = (which ? g_kpTl : g_qpTl) + ((size_t)bh * 256 + chalf * 128) * 112;
    const __nv_bfloat16* Bh = g_wqkTh + (size_t)h * 128 * 112;
    const __nv_bfloat16* Bl = g_wqkTl + (size_t)h * 128 * 112;
    float* outf = which ? g_k : g_q;
    __nv_bfloat16* outh = which ? g_ksh : g_qsh;
    __nv_bfloat16* outl = which ? g_ksl : g_qsl;

    #pragma unroll
    for (int it = 0; it < 7; it++) {
        int idx = t + (it << 8);
        int row = idx / 14, ch = idx - row * 14;
        uint32_t doff = (uint32_t)(row * PROW * 2 + ch * 16);
        cp16(sb + PA_HI + doff, Ah + (size_t)row * 112 + ch * 8, 16u);
        cp16(sb + PA_LO + doff, Al + (size_t)row * 112 + ch * 8, 16u);
        cp16(sb + PB_HI + doff, Bh + (size_t)row * 112 + ch * 8, 16u);
        cp16(sb + PB_LO + doff, Bl + (size_t)row * 112 + ch * 8, 16u);
    }
    asm volatile("cp.async.commit_group;" ::: "memory");
    asm volatile("cp.async.wait_group 0;" ::: "memory");
    __syncthreads();

    float c[2][8][4];
    #pragma unroll
    for (int mb = 0; mb < 2; mb++)
        #pragma unroll
        for (int nb = 0; nb < 8; nb++)
            #pragma unroll
            for (int r = 0; r < 4; r++) c[mb][nb][r] = 0.f;

    int a_r = lane & 15;
    int a_c = (lane >> 4) << 3;
    int b_r = (lane & 7) | ((lane & 16) >> 1);
    int b_c = lane & 8;

    #pragma unroll
    for (int kk = 0; kk < 7; kk++) {
        int k0 = kk << 4;
        uint32_t a_hi[2][4], a_lo[2][4];
        #pragma unroll
        for (int mb = 0; mb < 2; mb++) {
            uint32_t off = (uint32_t)((warp_m * 32 + mb * 16 + a_r) * PROW + k0 + a_c) * 2;
            ldsm_x4(a_hi[mb], sb + PA_HI + off);
            ldsm_x4(a_lo[mb], sb + PA_LO + off);
        }
        uint32_t b_hi[8][2], b_lo[8][2];
        #pragma unroll
        for (int nb2 = 0; nb2 < 4; nb2++) {
            uint32_t off = (uint32_t)((warp_n * 64 + nb2 * 16 + b_r) * PROW + k0 + b_c) * 2;
            uint32_t r4[4];
            ldsm_x4(r4, sb + PB_HI + off);
            b_hi[nb2*2][0] = r4[0]; b_hi[nb2*2][1] = r4[1];
            b_hi[nb2*2+1][0] = r4[2]; b_hi[nb2*2+1][1] = r4[3];
            ldsm_x4(r4, sb + PB_LO + off);
            b_lo[nb2*2][0] = r4[0]; b_lo[nb2*2][1] = r4[1];
            b_lo[nb2*2+1][0] = r4[2]; b_lo[nb2*2+1][1] = r4[3];
        }
        #pragma unroll
        for (int mb = 0; mb < 2; mb++)
            #pragma unroll
            for (int nb = 0; nb < 8; nb++) {
                mma16816(c[mb][nb], a_hi[mb], b_hi[nb]);
                mma16816(c[mb][nb], a_hi[mb], b_lo[nb]);
                mma16816(c[mb][nb], a_lo[mb], b_hi[nb]);
            }
    }

    #pragma unroll
    for (int mb = 0; mb < 2; mb++) {
        #pragma unroll
        for (int half = 0; half < 2; half++) {
            int cr = chalf * 128 + warp_m * 32 + mb * 16 + (lane >> 2) + half * 8;
            size_t rowo = ((size_t)bh * 256 + cr) * 128;
            #pragma unroll
            for (int nb = 0; nb < 8; nb++) {
                int e = warp_n * 64 + nb * 8 + ((lane & 3) << 1);
                float2 bz = *(const float2*)(bias + h * 128 + e);
                float v0 = c[mb][nb][half*2+0] + bz.x;
                float v1 = c[mb][nb][half*2+1] + bz.y;
                *(float2*)(outf + rowo + e) = make_float2(v0, v1);
                uint32_t lo;
                uint32_t hi = pack2(v0, v1, lo);
                *(uint32_t*)(outh + rowo + e) = hi;
                *(uint32_t*)(outl + rowo + e) = lo;
            }
        }
    }
}

// ---------------- temperature ----------------
__global__ __launch_bounds__(256) void temp_kernel(const float* __restrict__ wp_w,
                                                   const float* __restrict__ wp_b) {
    __shared__ float kbar[128];
    __shared__ float part[256];
    __shared__ float rowmean[256];
    int bh = blockIdx.x;
    int t = threadIdx.x;
    const float* kb = g_k + (size_t)bh * Cc * 128;
    const float* qb = g_q + (size_t)bh * Cc * 128;
    {
        int col = t & 127, half = t >> 7;
        float s = 0.f;
        for (int f = half * 128; f < half * 128 + 128; f++) s += kb[(size_t)f * 128 + col];
        part[t] = s;
    }
    __syncthreads();
    if (t < 128) kbar[t] = (part[t] + part[t + 128]) * (1.f / 256.f);
    __syncthreads();
    int w = t >> 5, lane = t & 31;
    float4 kv = *(const float4*)&kbar[lane << 2];
    for (int r = 0; r < 32; r++) {
        int c = (w << 5) + r;
        float4 qv = *(const float4*)(qb + (size_t)c * 128 + (lane << 2));
        float p = qv.x * kv.x + qv.y * kv.y + qv.z * kv.z + qv.w * kv.w;
        #pragma unroll
        for (int o = 16; o; o >>= 1) p += __shfl_xor_sync(0xFFFFFFFFu, p, o);
        if (lane == 0) rowmean[c] = p;
    }
    __syncthreads();
    float s = wp_b[t];
    for (int cc = 0; cc < 256; cc++) s += rowmean[cc] * wp_w[(size_t)cc * 256 + t];
    float sig = 1.f / (1.f + expf(-s));
    g_invden[(size_t)bh * 256 + t] = exp2f(-7.f * (0.2f + sig));
}

// ---------------- fused scores + softmax -> bf16 weights (hi only) ----------------
#define SROW 136
#define SQ_HI 0
#define SQ_LO 17408
#define SK_HI 34816
#define SK_LO 104448
#define SRED  174080
#define SS_SMEM 176128

__global__ __launch_bounds__(256) void scores_softmax_kernel() {
    extern __shared__ char smem[];
    uint32_t sb = smem_u32(smem);
    float* red = (float*)(smem + SRED);
    int t = threadIdx.x, lane = t & 31, wid = t >> 5;
    int warp_m = wid >> 2, warp_n = wid & 3;
    int bh = blockIdx.x, c0 = blockIdx.y << 6;

    #pragma unroll
    for (int it = 0; it < 4; it++) {
        int idx = t + (it << 8);
        int row = idx >> 4, u = idx & 15;
        size_t src = ((size_t)(bh * 256 + c0 + row)) * 128 + u * 8;
        uint32_t off = (uint32_t)(row * SROW + u * 8) * 2;
        *(uint4*)(smem + SQ_HI + off) = *(const uint4*)(g_qsh + src);
        *(uint4*)(smem + SQ_LO + off) = *(const uint4*)(g_qsl + src);
    }
    #pragma unroll
    for (int it = 0; it < 16; it++) {
        int idx = t + (it << 8);
        int row = idx >> 4, u = idx & 15;
        size_t src = ((size_t)(bh * 256 + row)) * 128 + u * 8;
        uint32_t off = (uint32_t)(row * SROW + u * 8) * 2;
        *(uint4*)(smem + SK_HI + off) = *(const uint4*)(g_ksh + src);
        *(uint4*)(smem + SK_LO + off) = *(const uint4*)(g_ksl + src);
    }
    __syncthreads();

    float c[2][8][4];
    #pragma unroll
    for (int mb = 0; mb < 2; mb++)
        #pragma unroll
        for (int nb = 0; nb < 8; nb++)
            #pragma unroll
            for (int r = 0; r < 4; r++) c[mb][nb][r] = 0.f;

    int a_r = lane & 15;
    int a_c = (lane >> 4) << 3;
    int b_r = (lane & 7) | ((lane & 16) >> 1);
    int b_c = lane & 8;

    #pragma unroll
    for (int kk = 0; kk < 8; kk++) {
        int k0 = kk << 4;
        uint32_t a_hi[2][4], a_lo[2][4];
        #pragma unroll
        for (int mb = 0; mb < 2; mb++) {
            uint32_t off = (uint32_t)((warp_m * 32 + mb * 16 + a_r) * SROW + k0 + a_c) * 2;
            ldsm_x4(a_hi[mb], sb + SQ_HI + off);
            ldsm_x4(a_lo[mb], sb + SQ_LO + off);
        }
        uint32_t b_hi[8][2], b_lo[8][2];
        #pragma unroll
        for (int nb2 = 0; nb2 < 4; nb2++) {
            uint32_t off = (uint32_t)((warp_n * 64 + nb2 * 16 + b_r) * SROW + k0 + b_c) * 2;
            uint32_t r4[4];
            ldsm_x4(r4, sb + SK_HI + off);
            b_hi[nb2*2][0] = r4[0]; b_hi[nb2*2][1] = r4[1];
            b_hi[nb2*2+1][0] = r4[2]; b_hi[nb2*2+1][1] = r4[3];
            ldsm_x4(r4, sb + SK_LO + off);
            b_lo[nb2*2][0] = r4[0]; b_lo[nb2*2][1] = r4[1];
            b_lo[nb2*2+1][0] = r4[2]; b_lo[nb2*2+1][1] = r4[3];
        }
        #pragma unroll
        for (int mb = 0; mb < 2; mb++)
            #pragma unroll
            for (int nb = 0; nb < 8; nb++) {
                mma16816(c[mb][nb], a_hi[mb], b_hi[nb]);
                mma16816(c[mb][nb], a_hi[mb], b_lo[nb]);
                mma16816(c[mb][nb], a_lo[mb], b_hi[nb]);
            }
    }

    float invd[2][2];
    #pragma unroll
    for (int mb = 0; mb < 2; mb++) {
        int rb = warp_m * 32 + mb * 16 + (lane >> 2);
        invd[mb][0] = g_invden[(size_t)bh * 256 + c0 + rb];
        invd[mb][1] = g_invden[(size_t)bh * 256 + c0 + rb + 8];
    }
    #pragma unroll
    for (int mb = 0; mb < 2; mb++)
        #pragma unroll
        for (int nb = 0; nb < 8; nb++) {
            c[mb][nb][0] *= invd[mb][0];
            c[mb][nb][1] *= invd[mb][0];
            c[mb][nb][2] *= invd[mb][1];
            c[mb][nb][3] *= invd[mb][1];
        }

    #pragma unroll
    for (int mb = 0; mb < 2; mb++)
        #pragma unroll
        for (int half = 0; half < 2; half++) {
            float mx = -INFINITY;
            #pragma unroll
            for (int nb = 0; nb < 8; nb++) {
                mx = fmaxf(mx, c[mb][nb][half*2+0]);
                mx = fmaxf(mx, c[mb][nb][half*2+1]);
            }
            mx = fmaxf(mx, __shfl_xor_sync(0xFFFFFFFFu, mx, 1));
            mx = fmaxf(mx, __shfl_xor_sync(0xFFFFFFFFu, mx, 2));
            if ((lane & 3) == 0) {
                int r = warp_m * 32 + mb * 16 + (lane >> 2) + half * 8;
                red[r * 8 + warp_n] = mx;
            }
        }
    __syncthreads();
    float bm[2][2];
    #pragma unroll
    for (int mb = 0; mb < 2; mb++)
        #pragma unroll
        for (int half = 0; half < 2; half++) {
            int r = warp_m * 32 + mb * 16 + (lane >> 2) + half * 8;
            bm[mb][half] = fmaxf(fmaxf(red[r*8+0], red[r*8+1]), fmaxf(red[r*8+2], red[r*8+3]));
        }
    #pragma unroll
    for (int mb = 0; mb < 2; mb++)
        #pragma unroll
        for (int half = 0; half < 2; half++) {
            float s = 0.f;
            #pragma unroll
            for (int nb = 0; nb < 8; nb++) {
                float e0 = expf(c[mb][nb][half*2+0] - bm[mb][half]);
                float e1 = expf(c[mb][nb][half*2+1] - bm[mb][half]);
                c[mb][nb][half*2+0] = e0;
                c[mb][nb][half*2+1] = e1;
                s += e0 + e1;
            }
            s += __shfl_xor_sync(0xFFFFFFFFu, s, 1);
            s += __shfl_xor_sync(0xFFFFFFFFu, s, 2);
            if ((lane & 3) == 0) {
                int r = warp_m * 32 + mb * 16 + (lane >> 2) + half * 8;
                red[r * 8 + 4 + warp_n] = s;
            }
        }
    __syncthreads();
    #pragma unroll
    for (int mb = 0; mb < 2; mb++)
        #pragma unroll
        for (int half = 0; half < 2; half++) {
            int r = warp_m * 32 + mb * 16 + (lane >> 2) + half * 8;
            float tot = red[r*8+4] + red[r*8+5] + red[r*8+6] + red[r*8+7];
            float inv = 1.f / tot;
            size_t rowbase = ((size_t)bh * 256 + c0 + r) * 256;
            #pragma unroll
            for (int nb = 0; nb < 8; nb++) {
                int f = warp_n * 64 + nb * 8 + ((lane & 3) << 1);
                uint32_t lo;
                uint32_t hi = pack2(c[mb][nb][half*2+0] * inv, c[mb][nb][half*2+1] * inv, lo);
                *(uint32_t*)(g_wh + rowbase + f) = hi;
            }
        }
}

// ---------------- att mma: A=vpool(hi+lo), B=weights(hi only) -> 2 mma ----------------
#define AROW 72
#define AA_HI 0
#define AA_LO 18432
#define AB_HI 36864
#define ASTAGE 55296
#define ATT_SMEM (2*ASTAGE)

__device__ __forceinline__ void att_load_stage(
    uint32_t bufo, int f0, size_t abase, size_t bbase, int lrow, int lch)
{
    #pragma unroll
    for (int p = 0; p < 4; p++) {
        int row = lrow + p * 32;
        size_t asrc = abase + (size_t)row * 256 + f0 + lch * 8;
        size_t bsrc = bbase + (size_t)row * 256 + f0 + lch * 8;
        uint32_t doff = (uint32_t)(row * AROW + lch * 8) * 2;
        cp16(bufo + AA_HI + doff, g_vph + asrc, 16u);
        cp16(bufo + AA_LO + doff, g_vpl + asrc, 16u);
        cp16(bufo + AB_HI + doff, g_wh + bsrc, 16u);
    }
    asm volatile("cp.async.commit_group;" ::: "memory");
}

__global__ __launch_bounds__(256) void att_mma_kernel(const float* __restrict__ x,
                                                      float* __restrict__ out) {
    extern __shared__ char smem[];
    uint32_t sb = smem_u32(smem);
    int t = threadIdx.x, lane = t & 31, wid = t >> 5;
    int warp_m = wid >> 1, warp_n = wid & 1;
    int bh = blockIdx.x, chalf = blockIdx.y;
    int b = bh >> 3, h = bh & 7;
    size_t abase = ((size_t)b * 784 + h * 98) * 256;
    size_t bbase = ((size_t)bh * 256 + chalf * 128) * 256;

    int lrow = t >> 3, lch = t & 7;

    att_load_stage(sb, 0, abase, bbase, lrow, lch);

    float c[2][8][4];
    #pragma unroll
    for (int mb = 0; mb < 2; mb++)
        #pragma unroll
        for (int nb = 0; nb < 8; nb++)
            #pragma unroll
            for (int r = 0; r < 4; r++) c[mb][nb][r] = 0.f;

    int a_r = lane & 15;
    int a_c = (lane >> 4) << 3;
    int b_r = (lane & 7) | ((lane & 16) >> 1);
    int b_c = lane & 8;

    for (int s = 0; s < 4; s++) {
        if (s + 1 < 4) {
            att_load_stage(sb + (uint32_t)((s + 1) & 1) * ASTAGE, (s + 1) << 6,
                           abase, bbase, lrow, lch);
            asm volatile("cp.async.wait_group 1;" ::: "memory");
        } else {
            asm volatile("cp.async.wait_group 0;" ::: "memory");
        }
        __syncthreads();

        uint32_t bufo = sb + (uint32_t)(s & 1) * ASTAGE;
        #pragma unroll
        for (int kk = 0; kk < 4; kk++) {
            int k0 = kk << 4;
            uint32_t a_hi[2][4], a_lo[2][4];
            #pragma unroll
            for (int mb = 0; mb < 2; mb++) {
                uint32_t off = (uint32_t)((warp_m * 32 + mb * 16 + a_r) * AROW + k0 + a_c) * 2;
                ldsm_x4(a_hi[mb], bufo + AA_HI + off);
                ldsm_x4(a_lo[mb], bufo + AA_LO + off);
            }
            uint32_t b_hi[8][2];
            #pragma unroll
            for (int nb2 = 0; nb2 < 4; nb2++) {
                uint32_t off = (uint32_t)((warp_n * 64 + nb2 * 16 + b_r) * AROW + k0 + b_c) * 2;
                uint32_t r4[4];
                ldsm_x4(r4, bufo + AB_HI + off);
                b_hi[nb2*2][0] = r4[0]; b_hi[nb2*2][1] = r4[1];
                b_hi[nb2*2+1][0] = r4[2]; b_hi[nb2*2+1][1] = r4[3];
            }
            #pragma unroll
            for (int mb = 0; mb < 2; mb++)
                #pragma unroll
                for (int nb = 0; nb < 8; nb++) {
                    mma16816(c[mb][nb], a_hi[mb], b_hi[nb]);
                    mma16816(c[mb][nb], a_lo[mb], b_hi[nb]);
                }
        }
        __syncthreads();
    }

    #pragma unroll
    for (int mb = 0; mb < 2; mb++)
        #pragma unroll
        for (int half = 0; half < 2; half++) {
            int d = warp_m * 32 + mb * 16 + (lane >> 2) + half * 8;
            if (d < 98) {
                size_t rowo = abase + (size_t)d * 256 + chalf * 128;
                #pragma unroll
                for (int nb = 0; nb < 8; nb++) {
                    int cg = warp_n * 64 + nb * 8 + ((lane & 3) << 1);
                    float2 xv = *(const float2*)(x + rowo + cg);
                    *(float2*)(out + rowo + cg) =
                        make_float2(xv.x + c[mb][nb][half*2+0], xv.y + c[mb][nb][half*2+1]);
                }
            }
        }
}

// ---------------- launch ----------------
extern "C" void kernel_launch(void* const* d_in, const int* in_sizes, int n_in,
                              void* d_out, int out_size) {
    const float* x     = (const float*)d_in[0];
    const float* wqk_w = (const float*)d_in[1];
    const float* wqk_b = (const float*)d_in[2];
    const float* wp_w  = (const float*)d_in[3];
    const float* wp_b  = (const float*)d_in[4];
    const float* wv_w  = (const float*)d_in[5];
    const float* wv_b  = (const float*)d_in[6];
    float* out = (float*)d_out;

    cudaFuncSetAttribute(conv_mma_kernel, cudaFuncAttributeMaxDynamicSharedMemorySize, CONV_SMEM);
    cudaFuncSetAttribute(scores_softmax_kernel, cudaFuncAttributeMaxDynamicSharedMemorySize, SS_SMEM);
    cudaFuncSetAttribute(proj_mma_kernel, cudaFuncAttributeMaxDynamicSharedMemorySize, PROJ_SMEM);
    cudaFuncSetAttribute(att_mma_kernel, cudaFuncAttributeMaxDynamicSharedMemorySize, ATT_SMEM);

    split_x_kernel<<<12544, 256>>>(x);
    split_w_kernel<<<2304, 256>>>(wv_w);
    conv_mma_kernel<<<dim3(392, 2), 256, CONV_SMEM>>>(wv_b);
    pool_v_kernel<<<Bz * Ss, 256>>>();
    poolqkT_kernel<<<512, 256>>>(x);
    wqkT_kernel<<<8, 128>>>(wqk_w);
    proj_mma_kernel<<<dim3(512, 2, 2), 256, PROJ_SMEM>>>(wqk_b);
    temp_kernel<<<512, 256>>>(wp_w, wp_b);
    scores_softmax_kernel<<<dim3(512, 4), 256, SS_SMEM>>>();
    att_mma_kernel<<<dim3(512, 2), 256, ATT_SMEM>>>(x, out);
}

// round 13
// speedup vs baseline: 1.0586x; 1.0484x over previous
#include <cuda_runtime.h>
#include <cuda_bf16.h>
#include <cstdint>
#include <stdint.h>
#include <math.h>

#define Bz 64
#define Ss 784
#define Cc 256
#define Hh 8
#define BH 512

// ---------------- scratch ----------------
__device__ float g_vconv[Bz*Ss*Cc];
__device__ float g_q[BH*Cc*128];
__device__ float g_k[BH*Cc*128];
__device__ float g_invden[BH*Cc];
__device__ __nv_bfloat16 g_xh[Bz*Ss*Cc];
__device__ __nv_bfloat16 g_xl[Bz*Ss*Cc];
__device__ __nv_bfloat16 g_wth[Cc*2304];
__device__ __nv_bfloat16 g_wtl[Cc*2304];
__device__ __nv_bfloat16 g_qpTh[BH*Cc*112];
__device__ __nv_bfloat16 g_qpTl[BH*Cc*112];
__device__ __nv_bfloat16 g_kpTh[BH*Cc*112];
__device__ __nv_bfloat16 g_kpTl[BH*Cc*112];
__device__ __nv_bfloat16 g_wqkTh[Hh*128*112];
__device__ __nv_bfloat16 g_wqkTl[Hh*128*112];
__device__ __nv_bfloat16 g_qsh[BH*Cc*128];
__device__ __nv_bfloat16 g_qsl[BH*Cc*128];
__device__ __nv_bfloat16 g_ksh[BH*Cc*128];
__device__ __nv_bfloat16 g_ksl[BH*Cc*128];
__device__ __nv_bfloat16 g_wh[(size_t)BH*Cc*Cc];   // weights hi only
__device__ __nv_bfloat16 g_vph[Bz*Ss*Cc + 8192];
__device__ __nv_bfloat16 g_vpl[Bz*Ss*Cc + 8192];

// ---------------- helpers ----------------
__device__ __forceinline__ uint32_t smem_u32(const void* p) {
    uint32_t a;
    asm("{ .reg .u64 t; cvta.to.shared.u64 t, %1; cvt.u32.u64 %0, t; }" : "=r"(a) : "l"(p));
    return a;
}
__device__ __forceinline__ void cp16(uint32_t dst, const void* src, uint32_t srcsize) {
    asm volatile("cp.async.cg.shared.global [%0], [%1], 16, %2;"
                 :: "r"(dst), "l"(src), "r"(srcsize) : "memory");
}
__device__ __forceinline__ void ldsm_x4(uint32_t* r, uint32_t addr) {
    asm volatile("ldmatrix.sync.aligned.m8n8.x4.shared.b16 {%0,%1,%2,%3}, [%4];"
                 : "=r"(r[0]), "=r"(r[1]), "=r"(r[2]), "=r"(r[3]) : "r"(addr));
}
__device__ __forceinline__ void mma16816(float* c, const uint32_t* a, const uint32_t* b) {
    asm volatile("mma.sync.aligned.m16n8k16.row.col.f32.bf16.bf16.f32 "
                 "{%0,%1,%2,%3}, {%4,%5,%6,%7}, {%8,%9}, {%0,%1,%2,%3};"
                 : "+f"(c[0]), "+f"(c[1]), "+f"(c[2]), "+f"(c[3])
                 : "r"(a[0]), "r"(a[1]), "r"(a[2]), "r"(a[3]), "r"(b[0]), "r"(b[1]));
}
__device__ __forceinline__ void split2(float v, __nv_bfloat16& h, __nv_bfloat16& l) {
    h = __float2bfloat16(v);
    l = __float2bfloat16(v - __bfloat162float(h));
}
__device__ __forceinline__ uint32_t pack2(float v0, float v1, uint32_t& lo) {
    __nv_bfloat16 h0, h1, l0, l1;
    split2(v0, h0, l0); split2(v1, h1, l1);
    lo = (uint32_t)__bfloat16_as_ushort(l0) | ((uint32_t)__bfloat16_as_ushort(l1) << 16);
    return (uint32_t)__bfloat16_as_ushort(h0) | ((uint32_t)__bfloat16_as_ushort(h1) << 16);
}

// ---------------- x split ----------------
__global__ __launch_bounds__(256) void split_x_kernel(const float* __restrict__ x) {
    int idx4 = blockIdx.x * 256 + threadIdx.x;
    float4 v = ((const float4*)x)[idx4];
    uint32_t l01, l23;
    uint32_t h01 = pack2(v.x, v.y, l01);
    uint32_t h23 = pack2(v.z, v.w, l23);
    ((uint2*)g_xh)[idx4] = make_uint2(h01, h23);
    ((uint2*)g_xl)[idx4] = make_uint2(l01, l23);
}

// ---------------- conv w split ----------------
__global__ __launch_bounds__(256) void split_w_kernel(const float* __restrict__ w) {
    int k = blockIdx.x;
    int co = threadIdx.x;
    float v = w[(size_t)k * 256 + co];
    __nv_bfloat16 h, l;
    split2(v, h, l);
    g_wth[(size_t)co * 2304 + k] = h;
    g_wtl[(size_t)co * 2304 + k] = l;
}

// ---------------- fused avg/max pool + transpose + split ----------------
__global__ __launch_bounds__(256) void poolqkT_kernel(const float* __restrict__ x) {
    __shared__ float ta[32][33];
    __shared__ float tm[32][33];
    int bh = blockIdx.x;
    int b = bh >> 3, h = bh & 7;
    const float* xb = x + (size_t)b * 784 * 256;
    int t = threadIdx.x;
    int r8 = t >> 5, cl = t & 31;
    for (int dt = 0; dt < 4; dt++) {
        int d0 = dt << 5;
        for (int ct = 0; ct < 8; ct++) {
            int c0 = ct << 5;
            #pragma unroll
            for (int p = 0; p < 4; p++) {
                int dl = r8 + p * 8;
                int d = d0 + dl;
                float sum = 0.f, mx = -INFINITY;
                int cnt = 0;
                if (d < 98) {
                    int s = h * 98 + d;
                    int i = s / 28, j = s - i * 28;
                    #pragma unroll
                    for (int di = -1; di <= 1; di++)
                        #pragma unroll
                        for (int dj = -1; dj <= 1; dj++) {
                            int ii = i + di, jj = j + dj;
                            if ((unsigned)ii < 28u && (unsigned)jj < 28u) {
                                float v = xb[(size_t)(ii * 28 + jj) * 256 + c0 + cl];
                                sum += v;
                                mx = fmaxf(mx, v);
                                cnt++;
                            }
                        }
                    ta[dl][cl] = sum / (float)cnt;
                    tm[dl][cl] = mx;
                } else {
                    ta[dl][cl] = 0.f;
                    tm[dl][cl] = 0.f;
                }
            }
            __syncthreads();
            #pragma unroll
            for (int p = 0; p < 4; p++) {
                int cr = r8 + p * 8;
                int d = d0 + cl;
                if (d < 112) {
                    size_t o = ((size_t)bh * 256 + c0 + cr) * 112 + d;
                    __nv_bfloat16 hh, ll;
                    split2(ta[cl][cr], hh, ll);
                    g_qpTh[o] = hh; g_qpTl[o] = ll;
                    split2(tm[cl][cr], hh, ll);
                    g_kpTh[o] = hh; g_kpTl[o] = ll;
                }
            }
            __syncthreads();
        }
    }
}

// ---------------- conv mma: CTA tile 128x128, K staged 64 ----------------
#define CROW 72
#define CA_HI 0
#define CA_LO 18432
#define CB_HI 36864
#define CB_LO 55296
#define CSTAGE 73728
#define CONV_SMEM (2*CSTAGE)

__device__ __forceinline__ void conv_load_stage(
    int s, uint32_t sb, int row2, int half2, int bb, int pi, int pj, int n0g)
{
    uint32_t bufo = sb + (uint32_t)(s & 1) * CSTAGE;
    int tap = s >> 2;
    int di = tap / 3, dj = tap - di * 3;
    int ii = pi + di - 1, jj = pj + dj - 1;
    bool valid = ((unsigned)ii < 28u) && ((unsigned)jj < 28u);
    int ci0 = ((s & 3) << 6) + half2 * 32;
    size_t ga = ((size_t)(bb * 784 + (valid ? ii * 28 + jj : 0)) << 8) + ci0;
    uint32_t rowoff = (uint32_t)(row2 * CROW + half2 * 32) * 2;
    uint32_t vs = valid ? 16u : 0u;
    #pragma unroll
    for (int q = 0; q < 4; q++) {
        cp16(bufo + CA_HI + rowoff + q * 16, g_xh + ga + q * 8, vs);
        cp16(bufo + CA_LO + rowoff + q * 16, g_xl + ga + q * 8, vs);
    }
    size_t gb = (size_t)(n0g + row2) * 2304 + (size_t)s * 64 + half2 * 32;
    #pragma unroll
    for (int q = 0; q < 4; q++) {
        cp16(bufo + CB_HI + rowoff + q * 16, g_wth + gb + q * 8, 16u);
        cp16(bufo + CB_LO + rowoff + q * 16, g_wtl + gb + q * 8, 16u);
    }
    asm volatile("cp.async.commit_group;" ::: "memory");
}

__global__ __launch_bounds__(256) void conv_mma_kernel(const float* __restrict__ bias) {
    extern __shared__ char smem[];
    uint32_t sb = smem_u32(smem);
    int t = threadIdx.x, lane = t & 31, wid = t >> 5;
    int warp_m = wid >> 2, warp_n = wid & 3;
    int m0 = blockIdx.x << 7;
    int n0g = blockIdx.y << 7;

    int row2 = t >> 1, half2 = t & 1;
    int m = m0 + row2;
    int bb = m / 784;
    int pix = m - bb * 784;
    int pi = pix / 28, pj = pix - pi * 28;

    float c[4][4][4];
    #pragma unroll
    for (int mb = 0; mb < 4; mb++)
        #pragma unroll
        for (int nb = 0; nb < 4; nb++)
            #pragma unroll
            for (int r = 0; r < 4; r++) c[mb][nb][r] = 0.f;

    int a_r = lane & 15;
    int a_c = (lane >> 4) << 3;
    int b_r = (lane & 7) | ((lane & 16) >> 1);
    int b_c = lane & 8;

    conv_load_stage(0, sb, row2, half2, bb, pi, pj, n0g);

    for (int s = 0; s < 36; s++) {
        if (s + 1 < 36) {
            conv_load_stage(s + 1, sb, row2, half2, bb, pi, pj, n0g);
            asm volatile("cp.async.wait_group 1;" ::: "memory");
        } else {
            asm volatile("cp.async.wait_group 0;" ::: "memory");
        }
        __syncthreads();

        uint32_t bufo = sb + (uint32_t)(s & 1) * CSTAGE;
        #pragma unroll
        for (int kk = 0; kk < 4; kk++) {
            int k0 = kk << 4;
            uint32_t a_hi[4][4], a_lo[4][4];
            #pragma unroll
            for (int mb = 0; mb < 4; mb++) {
                uint32_t off = (uint32_t)((warp_m * 64 + mb * 16 + a_r) * CROW + k0 + a_c) * 2;
                ldsm_x4(a_hi[mb], bufo + CA_HI + off);
                ldsm_x4(a_lo[mb], bufo + CA_LO + off);
            }
            uint32_t b_hi[4][2], b_lo[4][2];
            #pragma unroll
            for (int nb2 = 0; nb2 < 2; nb2++) {
                uint32_t off = (uint32_t)((warp_n * 32 + nb2 * 16 + b_r) * CROW + k0 + b_c) * 2;
                uint32_t r4[4];
                ldsm_x4(r4, bufo + CB_HI + off);
                b_hi[nb2*2][0] = r4[0]; b_hi[nb2*2][1] = r4[1];
                b_hi[nb2*2+1][0] = r4[2]; b_hi[nb2*2+1][1] = r4[3];
                ldsm_x4(r4, bufo + CB_LO + off);
                b_lo[nb2*2][0] = r4[0]; b_lo[nb2*2][1] = r4[1];
                b_lo[nb2*2+1][0] = r4[2]; b_lo[nb2*2+1][1] = r4[3];
            }
            #pragma unroll
            for (int mb = 0; mb < 4; mb++)
                #pragma unroll
                for (int nb = 0; nb < 4; nb++) {
                    mma16816(c[mb][nb], a_hi[mb], b_hi[nb]);
                    mma16816(c[mb][nb], a_hi[mb], b_lo[nb]);
                    mma16816(c[mb][nb], a_lo[mb], b_hi[nb]);
                }
        }
        __syncthreads();
    }

    #pragma unroll
    for (int mb = 0; mb < 4; mb++) {
        int rg = m0 + warp_m * 64 + mb * 16 + (lane >> 2);
        #pragma unroll
        for (int nb = 0; nb < 4; nb++) {
            int cg = n0g + warp_n * 32 + nb * 8 + ((lane & 3) << 1);
            float2 bz = *(const float2*)(bias + cg);
            *(float2*)(g_vconv + (size_t)rg * 256 + cg) =
                make_float2(c[mb][nb][0] + bz.x, c[mb][nb][1] + bz.y);
            *(float2*)(g_vconv + (size_t)(rg + 8) * 256 + cg) =
                make_float2(c[mb][nb][2] + bz.x, c[mb][nb][3] + bz.y);
        }
    }
}

// ---------------- pool of conv output -> bf16 splits ----------------
__global__ __launch_bounds__(256) void pool_v_kernel() {
    int bs = blockIdx.x;
    int c  = threadIdx.x;
    int b  = bs / 784;
    int pix = bs - b * 784;
    int i = pix / 28, j = pix - i * 28;
    const float* xb = g_vconv + (size_t)b * 784 * 256;
    float sum = 0.f;
    int cnt = 0;
    #pragma unroll
    for (int di = -1; di <= 1; di++) {
        #pragma unroll
        for (int dj = -1; dj <= 1; dj++) {
            int ii = i + di, jj = j + dj;
            if ((unsigned)ii < 28u && (unsigned)jj < 28u) {
                sum += xb[(size_t)(ii * 28 + jj) * 256 + c];
                cnt++;
            }
        }
    }
    __nv_bfloat16 h, l;
    split2(sum / (float)cnt, h, l);
    size_t o = (size_t)bs * 256 + c;
    g_vph[o] = h;
    g_vpl[o] = l;
}

// ---------------- wqk transpose+split ----------------
__global__ __launch_bounds__(128) void wqkT_kernel(const float* __restrict__ wqk) {
    int h = blockIdx.x;
    int e = threadIdx.x;
    for (int d = 0; d < 112; d++) {
        float v = (d < 98) ? wqk[((size_t)h * 98 + d) * 128 + e] : 0.f;
        __nv_bfloat16 hh, ll;
        split2(v, hh, ll);
        size_t o = ((size_t)h * 128 + e) * 112 + d;
        g_wqkTh[o] = hh;
        g_wqkTl[o] = ll;
    }
}

// ---------------- proj mma ----------------
#define PROW 120
#define PA_HI 0
#define PA_LO 30720
#define PB_HI 61440
#define PB_LO 92160
#define PROJ_SMEM 122880

__global__ __launch_bounds__(256) void proj_mma_kernel(const float* __restrict__ bias) {
    extern __shared__ char smem[];
    uint32_t sb = smem_u32(smem);
    int t = threadIdx.x, lane = t & 31, wid = t >> 5;
    int warp_m = wid >> 1, warp_n = wid & 1;
    int bh = blockIdx.x, chalf = blockIdx.y, which = blockIdx.z;
    int h = bh & 7;
    const __nv_bfloat16* Ah = (which ? g_kpTh : g_qpTh) + ((size_t)bh * 256 + chalf * 128) * 112;
    const __nv_bfloat16* Al = (which ? g_kpTl : g_qpTl) + ((size_t)bh * 256 + chalf * 128) * 112;
    const __nv_bfloat16* Bh = g_wqkTh + (size_t)h * 128 * 112;
    const __nv_bfloat16* Bl = g_wqkTl + (size_t)h * 128 * 112;
    float* outf = which ? g_k : g_q;
    __nv_bfloat16* outh = which ? g_ksh : g_qsh;
    __nv_bfloat16* outl = which ? g_ksl : g_qsl;

    #pragma unroll
    for (int it = 0; it < 7; it++) {
        int idx = t + (it << 8);
        int row = idx / 14, ch = idx - row * 14;
        uint32_t doff = (uint32_t)(row * PROW * 2 + ch * 16);
        cp16(sb + PA_HI + doff, Ah + (size_t)row * 112 + ch * 8, 16u);
        cp16(sb + PA_LO + doff, Al + (size_t)row * 112 + ch * 8, 16u);
        cp16(sb + PB_HI + doff, Bh + (size_t)row * 112 + ch * 8, 16u);
        cp16(sb + PB_LO + doff, Bl + (size_t)row * 112 + ch * 8, 16u);
    }
    asm volatile("cp.async.commit_group;" ::: "memory");
    asm volatile("cp.async.wait_group 0;" ::: "memory");
    __syncthreads();

    float c[2][8][4];
    #pragma unroll
    for (int mb = 0; mb < 2; mb++)
        #pragma unroll
        for (int nb = 0; nb < 8; nb++)
            #pragma unroll
            for (int r = 0; r < 4; r++) c[mb][nb][r] = 0.f;

    int a_r = lane & 15;
    int a_c = (lane >> 4) << 3;
    int b_r = (lane & 7) | ((lane & 16) >> 1);
    int b_c = lane & 8;

    #pragma unroll
    for (int kk = 0; kk < 7; kk++) {
        int k0 = kk << 4;
        uint32_t a_hi[2][4], a_lo[2][4];
        #pragma unroll
        for (int mb = 0; mb < 2; mb++) {
            uint32_t off = (uint32_t)((warp_m * 32 + mb * 16 + a_r) * PROW + k0 + a_c) * 2;
            ldsm_x4(a_hi[mb], sb + PA_HI + off);
            ldsm_x4(a_lo[mb], sb + PA_LO + off);
        }
        uint32_t b_hi[8][2], b_lo[8][2];
        #pragma unroll
        for (int nb2 = 0; nb2 < 4; nb2++) {
            uint32_t off = (uint32_t)((warp_n * 64 + nb2 * 16 + b_r) * PROW + k0 + b_c) * 2;
            uint32_t r4[4];
            ldsm_x4(r4, sb + PB_HI + off);
            b_hi[nb2*2][0] = r4[0]; b_hi[nb2*2][1] = r4[1];
            b_hi[nb2*2+1][0] = r4[2]; b_hi[nb2*2+1][1] = r4[3];
            ldsm_x4(r4, sb + PB_LO + off);
            b_lo[nb2*2][0] = r4[0]; b_lo[nb2*2][1] = r4[1];
            b_lo[nb2*2+1][0] = r4[2]; b_lo[nb2*2+1][1] = r4[3];
        }
        #pragma unroll
        for (int mb = 0; mb < 2; mb++)
            #pragma unroll
            for (int nb = 0; nb < 8; nb++) {
                mma16816(c[mb][nb], a_hi[mb], b_hi[nb]);
                mma16816(c[mb][nb], a_hi[mb], b_lo[nb]);
                mma16816(c[mb][nb], a_lo[mb], b_hi[nb]);
            }
    }

    #pragma unroll
    for (int mb = 0; mb < 2; mb++) {
        #pragma unroll
        for (int half = 0; half < 2; half++) {
            int cr = chalf * 128 + warp_m * 32 + mb * 16 + (lane >> 2) + half * 8;
            size_t rowo = ((size_t)bh * 256 + cr) * 128;
            #pragma unroll
            for (int nb = 0; nb < 8; nb++) {
                int e = warp_n * 64 + nb * 8 + ((lane & 3) << 1);
                float2 bz = *(const float2*)(bias + h * 128 + e);
                float v0 = c[mb][nb][half*2+0] + bz.x;
                float v1 = c[mb][nb][half*2+1] + bz.y;
                *(float2*)(outf + rowo + e) = make_float2(v0, v1);
                uint32_t lo;
                uint32_t hi = pack2(v0, v1, lo);
                *(uint32_t*)(outh + rowo + e) = hi;
                *(uint32_t*)(outl + rowo + e) = lo;
            }
        }
    }
}

// ---------------- temperature ----------------
__global__ __launch_bounds__(256) void temp_kernel(const float* __restrict__ wp_w,
                                                   const float* __restrict__ wp_b) {
    __shared__ float kbar[128];
    __shared__ float part[256];
    __shared__ float rowmean[256];
    int bh = blockIdx.x;
    int t = threadIdx.x;
    const float* kb = g_k + (size_t)bh * Cc * 128;
    const float* qb = g_q + (size_t)bh * Cc * 128;
    {
        int col = t & 127, half = t >> 7;
        float s = 0.f;
        for (int f = half * 128; f < half * 128 + 128; f++) s += kb[(size_t)f * 128 + col];
        part[t] = s;
    }
    __syncthreads();
    if (t < 128) kbar[t] = (part[t] + part[t + 128]) * (1.f / 256.f);
    __syncthreads();
    int w = t >> 5, lane = t & 31;
    float4 kv = *(const float4*)&kbar[lane << 2];
    for (int r = 0; r < 32; r++) {
        int c = (w << 5) + r;
        float4 qv = *(const float4*)(qb + (size_t)c * 128 + (lane << 2));
        float p = qv.x * kv.x + qv.y * kv.y + qv.z * kv.z + qv.w * kv.w;
        #pragma unroll
        for (int o = 16; o; o >>= 1) p += __shfl_xor_sync(0xFFFFFFFFu, p, o);
        if (lane == 0) rowmean[c] = p;
    }
    __syncthreads();
    float s = wp_b[t];
    for (int cc = 0; cc < 256; cc++) s += rowmean[cc] * wp_w[(size_t)cc * 256 + t];
    float sig = 1.f / (1.f + expf(-s));
    g_invden[(size_t)bh * 256 + t] = exp2f(-7.f * (0.2f + sig));
}

// ---------------- fused scores + softmax -> bf16 weights (hi only) ----------------
#define SROW 136
#define SQ_HI 0
#define SQ_LO 17408
#define SK_HI 34816
#define SK_LO 104448
#define SRED  174080
#define SS_SMEM 176128

__global__ __launch_bounds__(256) void scores_softmax_kernel() {
    extern __shared__ char smem[];
    uint32_t sb = smem_u32(smem);
    float* red = (float*)(smem + SRED);
    int t = threadIdx.x, lane = t & 31, wid = t >> 5;
    int warp_m = wid >> 2, warp_n = wid & 3;
    int bh = blockIdx.x, c0 = blockIdx.y << 6;

    #pragma unroll
    for (int it = 0; it < 4; it++) {
        int idx = t + (it << 8);
        int row = idx >> 4, u = idx & 15;
        size_t src = ((size_t)(bh * 256 + c0 + row)) * 128 + u * 8;
        uint32_t off = (uint32_t)(row * SROW + u * 8) * 2;
        *(uint4*)(smem + SQ_HI + off) = *(const uint4*)(g_qsh + src);
        *(uint4*)(smem + SQ_LO + off) = *(const uint4*)(g_qsl + src);
    }
    #pragma unroll
    for (int it = 0; it < 16; it++) {
        int idx = t + (it << 8);
        int row = idx >> 4, u = idx & 15;
        size_t src = ((size_t)(bh * 256 + row)) * 128 + u * 8;
        uint32_t off = (uint32_t)(row * SROW + u * 8) * 2;
        *(uint4*)(smem + SK_HI + off) = *(const uint4*)(g_ksh + src);
        *(uint4*)(smem + SK_LO + off) = *(const uint4*)(g_ksl + src);
    }
    __syncthreads();

    float c[2][8][4];
    #pragma unroll
    for (int mb = 0; mb < 2; mb++)
        #pragma unroll
        for (int nb = 0; nb < 8; nb++)
            #pragma unroll
            for (int r = 0; r < 4; r++) c[mb][nb][r] = 0.f;

    int a_r = lane & 15;
    int a_c = (lane >> 4) << 3;
    int b_r = (lane & 7) | ((lane & 16) >> 1);
    int b_c = lane & 8;

    #pragma unroll
    for (int kk = 0; kk < 8; kk++) {
        int k0 = kk << 4;
        uint32_t a_hi[2][4], a_lo[2][4];
        #pragma unroll
        for (int mb = 0; mb < 2; mb++) {
            uint32_t off = (uint32_t)((warp_m * 32 + mb * 16 + a_r) * SROW + k0 + a_c) * 2;
            ldsm_x4(a_hi[mb], sb + SQ_HI + off);
            ldsm_x4(a_lo[mb], sb + SQ_LO + off);
        }
        uint32_t b_hi[8][2], b_lo[8][2];
        #pragma unroll
        for (int nb2 = 0; nb2 < 4; nb2++) {
            uint32_t off = (uint32_t)((warp_n * 64 + nb2 * 16 + b_r) * SROW + k0 + b_c) * 2;
            uint32_t r4[4];
            ldsm_x4(r4, sb + SK_HI + off);
            b_hi[nb2*2][0] = r4[0]; b_hi[nb2*2][1] = r4[1];
            b_hi[nb2*2+1][0] = r4[2]; b_hi[nb2*2+1][1] = r4[3];
            ldsm_x4(r4, sb + SK_LO + off);
            b_lo[nb2*2][0] = r4[0]; b_lo[nb2*2][1] = r4[1];
            b_lo[nb2*2+1][0] = r4[2]; b_lo[nb2*2+1][1] = r4[3];
        }
        #pragma unroll
        for (int mb = 0; mb < 2; mb++)
            #pragma unroll
            for (int nb = 0; nb < 8; nb++) {
                mma16816(c[mb][nb], a_hi[mb], b_hi[nb]);
                mma16816(c[mb][nb], a_hi[mb], b_lo[nb]);
                mma16816(c[mb][nb], a_lo[mb], b_hi[nb]);
            }
    }

    float invd[2][2];
    #pragma unroll
    for (int mb = 0; mb < 2; mb++) {
        int rb = warp_m * 32 + mb * 16 + (lane >> 2);
        invd[mb][0] = g_invden[(size_t)bh * 256 + c0 + rb];
        invd[mb][1] = g_invden[(size_t)bh * 256 + c0 + rb + 8];
    }
    #pragma unroll
    for (int mb = 0; mb < 2; mb++)
        #pragma unroll
        for (int nb = 0; nb < 8; nb++) {
            c[mb][nb][0] *= invd[mb][0];
            c[mb][nb][1] *= invd[mb][0];
            c[mb][nb][2] *= invd[mb][1];
            c[mb][nb][3] *= invd[mb][1];
        }

    #pragma unroll
    for (int mb = 0; mb < 2; mb++)
        #pragma unroll
        for (int half = 0; half < 2; half++) {
            float mx = -INFINITY;
            #pragma unroll
            for (int nb = 0; nb < 8; nb++) {
                mx = fmaxf(mx, c[mb][nb][half*2+0]);
                mx = fmaxf(mx, c[mb][nb][half*2+1]);
            }
            mx = fmaxf(mx, __shfl_xor_sync(0xFFFFFFFFu, mx, 1));
            mx = fmaxf(mx, __shfl_xor_sync(0xFFFFFFFFu, mx, 2));
            if ((lane & 3) == 0) {
                int r = warp_m * 32 + mb * 16 + (lane >> 2) + half * 8;
                red[r * 8 + warp_n] = mx;
            }
        }
    __syncthreads();
    float bm[2][2];
    #pragma unroll
    for (int mb = 0; mb < 2; mb++)
        #pragma unroll
        for (int half = 0; half < 2; half++) {
            int r = warp_m * 32 + mb * 16 + (lane >> 2) + half * 8;
            bm[mb][half] = fmaxf(fmaxf(red[r*8+0], red[r*8+1]), fmaxf(red[r*8+2], red[r*8+3]));
        }
    #pragma unroll
    for (int mb = 0; mb < 2; mb++)
        #pragma unroll
        for (int half = 0; half < 2; half++) {
            float s = 0.f;
            #pragma unroll
            for (int nb = 0; nb < 8; nb++) {
                float e0 = expf(c[mb][nb][half*2+0] - bm[mb][half]);
                float e1 = expf(c[mb][nb][half*2+1] - bm[mb][half]);
                c[mb][nb][half*2+0] = e0;
                c[mb][nb][half*2+1] = e1;
                s += e0 + e1;
            }
            s += __shfl_xor_sync(0xFFFFFFFFu, s, 1);
            s += __shfl_xor_sync(0xFFFFFFFFu, s, 2);
            if ((lane & 3) == 0) {
                int r = warp_m * 32 + mb * 16 + (lane >> 2) + half * 8;
                red[r * 8 + 4 + warp_n] = s;
            }
        }
    __syncthreads();
    #pragma unroll
    for (int mb = 0; mb < 2; mb++)
        #pragma unroll
        for (int half = 0; half < 2; half++) {
            int r = warp_m * 32 + mb * 16 + (lane >> 2) + half * 8;
            float tot = red[r*8+4] + red[r*8+5] + red[r*8+6] + red[r*8+7];
            float inv = 1.f / tot;
            size_t rowbase = ((size_t)bh * 256 + c0 + r) * 256;
            #pragma unroll
            for (int nb = 0; nb < 8; nb++) {
                int f = warp_n * 64 + nb * 8 + ((lane & 3) << 1);
                uint32_t lo;
                uint32_t hi = pack2(c[mb][nb][half*2+0] * inv, c[mb][nb][half*2+1] * inv, lo);
                *(uint32_t*)(g_wh + rowbase + f) = hi;
            }
        }
}

// ---------------- att mma: A=vpool(hi+lo), B=weights(hi only) ----------------
#define AROW 72
#define AA_HI 0
#define AA_LO 18432
#define AB_HI 36864
#define ASTAGE 55296
#define ATT_SMEM (2*ASTAGE)

__device__ __forceinline__ void att_load_stage(
    uint32_t bufo, int f0, size_t abase, size_t bbase, int lrow, int lch)
{
    #pragma unroll
    for (int p = 0; p < 4; p++) {
        int row = lrow + p * 32;
        size_t asrc = abase + (size_t)row * 256 + f0 + lch * 8;
        size_t bsrc = bbase + (size_t)row * 256 + f0 + lch * 8;
        uint32_t doff = (uint32_t)(row * AROW + lch * 8) * 2;
        cp16(bufo + AA_HI + doff, g_vph + asrc, 16u);
        cp16(bufo + AA_LO + doff, g_vpl + asrc, 16u);
        cp16(bufo + AB_HI + doff, g_wh + bsrc, 16u);
    }
    asm volatile("cp.async.commit_group;" ::: "memory");
}

__global__ __launch_bounds__(256) void att_mma_kernel(const float* __restrict__ x,
                                                      float* __restrict__ out) {
    extern __shared__ char smem[];
    uint32_t sb = smem_u32(smem);
    int t = threadIdx.x, lane = t & 31, wid = t >> 5;
    int warp_m = wid >> 1, warp_n = wid & 1;
    int bh = blockIdx.x, chalf = blockIdx.y;
    int b = bh >> 3, h = bh & 7;
    size_t abase = ((size_t)b * 784 + h * 98) * 256;
    size_t bbase = ((size_t)bh * 256 + chalf * 128) * 256;

    int lrow = t >> 3, lch = t & 7;

    att_load_stage(sb, 0, abase, bbase, lrow, lch);

    float c[2][8][4];
    #pragma unroll
    for (int mb = 0; mb < 2; mb++)
        #pragma unroll
        for (int nb = 0; nb < 8; nb++)
            #pragma unroll
            for (int r = 0; r < 4; r++) c[mb][nb][r] = 0.f;

    int a_r = lane & 15;
    int a_c = (lane >> 4) << 3;
    int b_r = (lane & 7) | ((lane & 16) >> 1);
    int b_c = lane & 8;

    for (int s = 0; s < 4; s++) {
        if (s + 1 < 4) {
            att_load_stage(sb + (uint32_t)((s + 1) & 1) * ASTAGE, (s + 1) << 6,
                           abase, bbase, lrow, lch);
            asm volatile("cp.async.wait_group 1;" ::: "memory");
        } else {
            asm volatile("cp.async.wait_group 0;" ::: "memory");
        }
        __syncthreads();

        uint32_t bufo = sb + (uint32_t)(s & 1) * ASTAGE;
        #pragma unroll
        for (int kk = 0; kk < 4; kk++) {
            int k0 = kk << 4;
            uint32_t a_hi[2][4], a_lo[2][4];
            #pragma unroll
            for (int mb = 0; mb < 2; mb++) {
                uint32_t off = (uint32_t)((warp_m * 32 + mb * 16 + a_r) * AROW + k0 + a_c) * 2;
                ldsm_x4(a_hi[mb], bufo + AA_HI + off);
                ldsm_x4(a_lo[mb], bufo + AA_LO + off);
            }
            uint32_t b_hi[8][2];
            #pragma unroll
            for (int nb2 = 0; nb2 < 4; nb2++) {
                uint32_t off = (uint32_t)((warp_n * 64 + nb2 * 16 + b_r) * AROW + k0 + b_c) * 2;
                uint32_t r4[4];
                ldsm_x4(r4, bufo + AB_HI + off);
                b_hi[nb2*2][0] = r4[0]; b_hi[nb2*2][1] = r4[1];
                b_hi[nb2*2+1][0] = r4[2]; b_hi[nb2*2+1][1] = r4[3];
            }
            #pragma unroll
            for (int mb = 0; mb < 2; mb++)
                #pragma unroll
                for (int nb = 0; nb < 8; nb++) {
                    mma16816(c[mb][nb], a_hi[mb], b_hi[nb]);
                    mma16816(c[mb][nb], a_lo[mb], b_hi[nb]);
                }
        }
        __syncthreads();
    }

    #pragma unroll
    for (int mb = 0; mb < 2; mb++)
        #pragma unroll
        for (int half = 0; half < 2; half++) {
            int d = warp_m * 32 + mb * 16 + (lane >> 2) + half * 8;
            if (d < 98) {
                size_t rowo = abase + (size_t)d * 256 + chalf * 128;
                #pragma unroll
                for (int nb = 0; nb < 8; nb++) {
                    int cg = warp_n * 64 + nb * 8 + ((lane & 3) << 1);
                    float2 xv = *(const float2*)(x + rowo + cg);
                    *(float2*)(out + rowo + cg) =
                        make_float2(xv.x + c[mb][nb][half*2+0], xv.y + c[mb][nb][half*2+1]);
                }
            }
        }
}

// ---------------- launch: two-stream overlap (graph-capturable fork/join) ----------------
extern "C" void kernel_launch(void* const* d_in, const int* in_sizes, int n_in,
                              void* d_out, int out_size) {
    const float* x     = (const float*)d_in[0];
    const float* wqk_w = (const float*)d_in[1];
    const float* wqk_b = (const float*)d_in[2];
    const float* wp_w  = (const float*)d_in[3];
    const float* wp_b  = (const float*)d_in[4];
    const float* wv_w  = (const float*)d_in[5];
    const float* wv_b  = (const float*)d_in[6];
    float* out = (float*)d_out;

    cudaFuncSetAttribute(conv_mma_kernel, cudaFuncAttributeMaxDynamicSharedMemorySize, CONV_SMEM);
    cudaFuncSetAttribute(scores_softmax_kernel, cudaFuncAttributeMaxDynamicSharedMemorySize, SS_SMEM);
    cudaFuncSetAttribute(proj_mma_kernel, cudaFuncAttributeMaxDynamicSharedMemorySize, PROJ_SMEM);
    cudaFuncSetAttribute(att_mma_kernel, cudaFuncAttributeMaxDynamicSharedMemorySize, ATT_SMEM);

    cudaStream_t sB;
    cudaStreamCreateWithFlags(&sB, cudaStreamNonBlocking);
    cudaEvent_t eFork, eJoin;
    cudaEventCreateWithFlags(&eFork, cudaEventDisableTiming);
    cudaEventCreateWithFlags(&eJoin, cudaEventDisableTiming);

    // fork: QK chain on side stream
    cudaEventRecord(eFork, (cudaStream_t)0);
    cudaStreamWaitEvent(sB, eFork, 0);
    poolqkT_kernel<<<512, 256, 0, sB>>>(x);
    wqkT_kernel<<<8, 128, 0, sB>>>(wqk_w);
    proj_mma_kernel<<<dim3(512, 2, 2), 256, PROJ_SMEM, sB>>>(wqk_b);
    temp_kernel<<<512, 256, 0, sB>>>(wp_w, wp_b);
    scores_softmax_kernel<<<dim3(512, 4), 256, SS_SMEM, sB>>>();
    cudaEventRecord(eJoin, sB);

    // V chain on main stream
    split_x_kernel<<<12544, 256>>>(x);
    split_w_kernel<<<2304, 256>>>(wv_w);
    conv_mma_kernel<<<dim3(392, 2), 256, CONV_SMEM>>>(wv_b);
    pool_v_kernel<<<Bz * Ss, 256>>>();

    // join and finish
    cudaStreamWaitEvent((cudaStream_t)0, eJoin, 0);
    att_mma_kernel<<<dim3(512, 2), 256, ATT_SMEM>>>(x, out);

    cudaEventDestroy(eFork);
    cudaEventDestroy(eJoin);
    cudaStreamDestroy(sB);
}

// round 14
// speedup vs baseline: 1.2291x; 1.1610x over previous
#include <cuda_runtime.h>
#include <cuda_bf16.h>
#include <cuda_fp16.h>
#include <cstdint>
#include <stdint.h>
#include <math.h>

#define Bz 64
#define Ss 784
#define Cc 256
#define Hh 8
#define BH 512

// ---------------- scratch ----------------
__device__ float g_vconv[Bz*Ss*Cc];
__device__ float g_q[BH*Cc*128];
__device__ float g_k[BH*Cc*128];
__device__ float g_invden[BH*Cc];
__device__ __half g_xf[Bz*Ss*Cc];               // x as single fp16
__device__ __half g_wth[Cc*2304];               // w^T fp16 hi
__device__ __half g_wtl[Cc*2304];               // w^T fp16 lo
__device__ __nv_bfloat16 g_qpTh[BH*Cc*112];
__device__ __nv_bfloat16 g_qpTl[BH*Cc*112];
__device__ __nv_bfloat16 g_kpTh[BH*Cc*112];
__device__ __nv_bfloat16 g_kpTl[BH*Cc*112];
__device__ __nv_bfloat16 g_wqkTh[Hh*128*112];
__device__ __nv_bfloat16 g_wqkTl[Hh*128*112];
__device__ __nv_bfloat16 g_qsh[BH*Cc*128];
__device__ __nv_bfloat16 g_qsl[BH*Cc*128];
__device__ __nv_bfloat16 g_ksh[BH*Cc*128];
__device__ __nv_bfloat16 g_ksl[BH*Cc*128];
__device__ __nv_bfloat16 g_wh[(size_t)BH*Cc*Cc];   // weights hi only
__device__ __nv_bfloat16 g_vph[Bz*Ss*Cc + 8192];
__device__ __nv_bfloat16 g_vpl[Bz*Ss*Cc + 8192];

// ---------------- helpers ----------------
__device__ __forceinline__ uint32_t smem_u32(const void* p) {
    uint32_t a;
    asm("{ .reg .u64 t; cvta.to.shared.u64 t, %1; cvt.u32.u64 %0, t; }" : "=r"(a) : "l"(p));
    return a;
}
__device__ __forceinline__ void cp16(uint32_t dst, const void* src, uint32_t srcsize) {
    asm volatile("cp.async.cg.shared.global [%0], [%1], 16, %2;"
                 :: "r"(dst), "l"(src), "r"(srcsize) : "memory");
}
__device__ __forceinline__ void ldsm_x4(uint32_t* r, uint32_t addr) {
    asm volatile("ldmatrix.sync.aligned.m8n8.x4.shared.b16 {%0,%1,%2,%3}, [%4];"
                 : "=r"(r[0]), "=r"(r[1]), "=r"(r[2]), "=r"(r[3]) : "r"(addr));
}
__device__ __forceinline__ void mma16816(float* c, const uint32_t* a, const uint32_t* b) {
    asm volatile("mma.sync.aligned.m16n8k16.row.col.f32.bf16.bf16.f32 "
                 "{%0,%1,%2,%3}, {%4,%5,%6,%7}, {%8,%9}, {%0,%1,%2,%3};"
                 : "+f"(c[0]), "+f"(c[1]), "+f"(c[2]), "+f"(c[3])
                 : "r"(a[0]), "r"(a[1]), "r"(a[2]), "r"(a[3]), "r"(b[0]), "r"(b[1]));
}
__device__ __forceinline__ void mma16816h(float* c, const uint32_t* a, const uint32_t* b) {
    asm volatile("mma.sync.aligned.m16n8k16.row.col.f32.f16.f16.f32 "
                 "{%0,%1,%2,%3}, {%4,%5,%6,%7}, {%8,%9}, {%0,%1,%2,%3};"
                 : "+f"(c[0]), "+f"(c[1]), "+f"(c[2]), "+f"(c[3])
                 : "r"(a[0]), "r"(a[1]), "r"(a[2]), "r"(a[3]), "r"(b[0]), "r"(b[1]));
}
__device__ __forceinline__ void split2(float v, __nv_bfloat16& h, __nv_bfloat16& l) {
    h = __float2bfloat16(v);
    l = __float2bfloat16(v - __bfloat162float(h));
}
__device__ __forceinline__ void split2h(float v, __half& h, __half& l) {
    h = __float2half(v);
    l = __float2half(v - __half2float(h));
}
__device__ __forceinline__ uint32_t pack2(float v0, float v1, uint32_t& lo) {
    __nv_bfloat16 h0, h1, l0, l1;
    split2(v0, h0, l0); split2(v1, h1, l1);
    lo = (uint32_t)__bfloat16_as_ushort(l0) | ((uint32_t)__bfloat16_as_ushort(l1) << 16);
    return (uint32_t)__bfloat16_as_ushort(h0) | ((uint32_t)__bfloat16_as_ushort(h1) << 16);
}

// ---------------- x -> fp16 (single) ----------------
__global__ __launch_bounds__(256) void split_x_kernel(const float* __restrict__ x) {
    int idx4 = blockIdx.x * 256 + threadIdx.x;
    float4 v = ((const float4*)x)[idx4];
    ushort4 hp;
    hp.x = __half_as_ushort(__float2half(v.x));
    hp.y = __half_as_ushort(__float2half(v.y));
    hp.z = __half_as_ushort(__float2half(v.z));
    hp.w = __half_as_ushort(__float2half(v.w));
    ((ushort4*)g_xf)[idx4] = hp;
}

// ---------------- conv w fp16 split ----------------
__global__ __launch_bounds__(256) void split_w_kernel(const float* __restrict__ w) {
    int k = blockIdx.x;
    int co = threadIdx.x;
    float v = w[(size_t)k * 256 + co];
    __half h, l;
    split2h(v, h, l);
    g_wth[(size_t)co * 2304 + k] = h;
    g_wtl[(size_t)co * 2304 + k] = l;
}

// ---------------- fused avg/max pool + transpose + split ----------------
__global__ __launch_bounds__(256) void poolqkT_kernel(const float* __restrict__ x) {
    __shared__ float ta[32][33];
    __shared__ float tm[32][33];
    int bh = blockIdx.x;
    int b = bh >> 3, h = bh & 7;
    const float* xb = x + (size_t)b * 784 * 256;
    int t = threadIdx.x;
    int r8 = t >> 5, cl = t & 31;
    for (int dt = 0; dt < 4; dt++) {
        int d0 = dt << 5;
        for (int ct = 0; ct < 8; ct++) {
            int c0 = ct << 5;
            #pragma unroll
            for (int p = 0; p < 4; p++) {
                int dl = r8 + p * 8;
                int d = d0 + dl;
                float sum = 0.f, mx = -INFINITY;
                int cnt = 0;
                if (d < 98) {
                    int s = h * 98 + d;
                    int i = s / 28, j = s - i * 28;
                    #pragma unroll
                    for (int di = -1; di <= 1; di++)
                        #pragma unroll
                        for (int dj = -1; dj <= 1; dj++) {
                            int ii = i + di, jj = j + dj;
                            if ((unsigned)ii < 28u && (unsigned)jj < 28u) {
                                float v = xb[(size_t)(ii * 28 + jj) * 256 + c0 + cl];
                                sum += v;
                                mx = fmaxf(mx, v);
                                cnt++;
                            }
                        }
                    ta[dl][cl] = sum / (float)cnt;
                    tm[dl][cl] = mx;
                } else {
                    ta[dl][cl] = 0.f;
                    tm[dl][cl] = 0.f;
                }
            }
            __syncthreads();
            #pragma unroll
            for (int p = 0; p < 4; p++) {
                int cr = r8 + p * 8;
                int d = d0 + cl;
                if (d < 112) {
                    size_t o = ((size_t)bh * 256 + c0 + cr) * 112 + d;
                    __nv_bfloat16 hh, ll;
                    split2(ta[cl][cr], hh, ll);
                    g_qpTh[o] = hh; g_qpTl[o] = ll;
                    split2(tm[cl][cr], hh, ll);
                    g_kpTh[o] = hh; g_kpTl[o] = ll;
                }
            }
            __syncthreads();
        }
    }
}

// ---------------- conv mma (fp16): CTA 128x128, K staged 64, 2 MMAs/tile ----------------
#define CROW 72
#define CA 0
#define CB_HI 18432
#define CB_LO 36864
#define CSTAGE 55296
#define CONV_SMEM (2*CSTAGE)

__device__ __forceinline__ void conv_load_stage(
    int s, uint32_t sb, int row2, int half2, int bb, int pi, int pj, int n0g)
{
    uint32_t bufo = sb + (uint32_t)(s & 1) * CSTAGE;
    int tap = s >> 2;
    int di = tap / 3, dj = tap - di * 3;
    int ii = pi + di - 1, jj = pj + dj - 1;
    bool valid = ((unsigned)ii < 28u) && ((unsigned)jj < 28u);
    int ci0 = ((s & 3) << 6) + half2 * 32;
    size_t ga = ((size_t)(bb * 784 + (valid ? ii * 28 + jj : 0)) << 8) + ci0;
    uint32_t rowoff = (uint32_t)(row2 * CROW + half2 * 32) * 2;
    uint32_t vs = valid ? 16u : 0u;
    #pragma unroll
    for (int q = 0; q < 4; q++)
        cp16(bufo + CA + rowoff + q * 16, g_xf + ga + q * 8, vs);
    size_t gb = (size_t)(n0g + row2) * 2304 + (size_t)s * 64 + half2 * 32;
    #pragma unroll
    for (int q = 0; q < 4; q++) {
        cp16(bufo + CB_HI + rowoff + q * 16, g_wth + gb + q * 8, 16u);
        cp16(bufo + CB_LO + rowoff + q * 16, g_wtl + gb + q * 8, 16u);
    }
    asm volatile("cp.async.commit_group;" ::: "memory");
}

__global__ __launch_bounds__(256) void conv_mma_kernel(const float* __restrict__ bias) {
    extern __shared__ char smem[];
    uint32_t sb = smem_u32(smem);
    int t = threadIdx.x, lane = t & 31, wid = t >> 5;
    int warp_m = wid >> 2, warp_n = wid & 3;
    int m0 = blockIdx.x << 7;
    int n0g = blockIdx.y << 7;

    int row2 = t >> 1, half2 = t & 1;
    int m = m0 + row2;
    int bb = m / 784;
    int pix = m - bb * 784;
    int pi = pix / 28, pj = pix - pi * 28;

    float c[4][4][4];
    #pragma unroll
    for (int mb = 0; mb < 4; mb++)
        #pragma unroll
        for (int nb = 0; nb < 4; nb++)
            #pragma unroll
            for (int r = 0; r < 4; r++) c[mb][nb][r] = 0.f;

    int a_r = lane & 15;
    int a_c = (lane >> 4) << 3;
    int b_r = (lane & 7) | ((lane & 16) >> 1);
    int b_c = lane & 8;

    conv_load_stage(0, sb, row2, half2, bb, pi, pj, n0g);

    for (int s = 0; s < 36; s++) {
        if (s + 1 < 36) {
            conv_load_stage(s + 1, sb, row2, half2, bb, pi, pj, n0g);
            asm volatile("cp.async.wait_group 1;" ::: "memory");
        } else {
            asm volatile("cp.async.wait_group 0;" ::: "memory");
        }
        __syncthreads();

        uint32_t bufo = sb + (uint32_t)(s & 1) * CSTAGE;
        #pragma unroll
        for (int kk = 0; kk < 4; kk++) {
            int k0 = kk << 4;
            uint32_t a[4][4];
            #pragma unroll
            for (int mb = 0; mb < 4; mb++) {
                uint32_t off = (uint32_t)((warp_m * 64 + mb * 16 + a_r) * CROW + k0 + a_c) * 2;
                ldsm_x4(a[mb], bufo + CA + off);
            }
            uint32_t b_hi[4][2], b_lo[4][2];
            #pragma unroll
            for (int nb2 = 0; nb2 < 2; nb2++) {
                uint32_t off = (uint32_t)((warp_n * 32 + nb2 * 16 + b_r) * CROW + k0 + b_c) * 2;
                uint32_t r4[4];
                ldsm_x4(r4, bufo + CB_HI + off);
                b_hi[nb2*2][0] = r4[0]; b_hi[nb2*2][1] = r4[1];
                b_hi[nb2*2+1][0] = r4[2]; b_hi[nb2*2+1][1] = r4[3];
                ldsm_x4(r4, bufo + CB_LO + off);
                b_lo[nb2*2][0] = r4[0]; b_lo[nb2*2][1] = r4[1];
                b_lo[nb2*2+1][0] = r4[2]; b_lo[nb2*2+1][1] = r4[3];
            }
            #pragma unroll
            for (int mb = 0; mb < 4; mb++)
                #pragma unroll
                for (int nb = 0; nb < 4; nb++) {
                    mma16816h(c[mb][nb], a[mb], b_hi[nb]);
                    mma16816h(c[mb][nb], a[mb], b_lo[nb]);
                }
        }
        __syncthreads();
    }

    #pragma unroll
    for (int mb = 0; mb < 4; mb++) {
        int rg = m0 + warp_m * 64 + mb * 16 + (lane >> 2);
        #pragma unroll
        for (int nb = 0; nb < 4; nb++) {
            int cg = n0g + warp_n * 32 + nb * 8 + ((lane & 3) << 1);
            float2 bz = *(const float2*)(bias + cg);
            *(float2*)(g_vconv + (size_t)rg * 256 + cg) =
                make_float2(c[mb][nb][0] + bz.x, c[mb][nb][1] + bz.y);
            *(float2*)(g_vconv + (size_t)(rg + 8) * 256 + cg) =
                make_float2(c[mb][nb][2] + bz.x, c[mb][nb][3] + bz.y);
        }
    }
}

// ---------------- pool of conv output -> bf16 splits ----------------
__global__ __launch_bounds__(256) void pool_v_kernel() {
    int bs = blockIdx.x;
    int c  = threadIdx.x;
    int b  = bs / 784;
    int pix = bs - b * 784;
    int i = pix / 28, j = pix - i * 28;
    const float* xb = g_vconv + (size_t)b * 784 * 256;
    float sum = 0.f;
    int cnt = 0;
    #pragma unroll
    for (int di = -1; di <= 1; di++) {
        #pragma unroll
        for (int dj = -1; dj <= 1; dj++) {
            int ii = i + di, jj = j + dj;
            if ((unsigned)ii < 28u && (unsigned)jj < 28u) {
                sum += xb[(size_t)(ii * 28 + jj) * 256 + c];
                cnt++;
            }
        }
    }
    __nv_bfloat16 h, l;
    split2(sum / (float)cnt, h, l);
    size_t o = (size_t)bs * 256 + c;
    g_vph[o] = h;
    g_vpl[o] = l;
}

// ---------------- wqk transpose+split ----------------
__global__ __launch_bounds__(128) void wqkT_kernel(const float* __restrict__ wqk) {
    int h = blockIdx.x;
    int e = threadIdx.x;
    for (int d = 0; d < 112; d++) {
        float v = (d < 98) ? wqk[((size_t)h * 98 + d) * 128 + e] : 0.f;
        __nv_bfloat16 hh, ll;
        split2(v, hh, ll);
        size_t o = ((size_t)h * 128 + e) * 112 + d;
        g_wqkTh[o] = hh;
        g_wqkTl[o] = ll;
    }
}

// ---------------- proj mma ----------------
#define PROW 120
#define PA_HI 0
#define PA_LO 30720
#define PB_HI 61440
#define PB_LO 92160
#define PROJ_SMEM 122880

__global__ __launch_bounds__(256) void proj_mma_kernel(const float* __restrict__ bias) {
    extern __shared__ char smem[];
    uint32_t sb = smem_u32(smem);
    int t = threadIdx.x, lane = t & 31, wid = t >> 5;
    int warp_m = wid >> 1, warp_n = wid & 1;
    int bh = blockIdx.x, chalf = blockIdx.y, which = blockIdx.z;
    int h = bh & 7;
    const __nv_bfloat16* Ah = (which ? g_kpTh : g_qpTh) + ((size_t)bh * 256 + chalf * 128) * 112;
    const __nv_bfloat16* Al = (which ? g_kpTl : g_qpTl) + ((size_t)bh * 256 + chalf * 128) * 112;
    const __nv_bfloat16* Bh = g_wqkTh + (size_t)h * 128 * 112;
    const __nv_bfloat16* Bl = g_wqkTl + (size_t)h * 128 * 112;
    float* outf = which ? g_k : g_q;
    __nv_bfloat16* outh = which ? g_ksh : g_qsh;
    __nv_bfloat16* outl = which ? g_ksl : g_qsl;

    #pragma unroll
    for (int it = 0; it < 7; it++) {
        int idx = t + (it << 8);
        int row = idx / 14, ch = idx - row * 14;
        uint32_t doff = (uint32_t)(row * PROW * 2 + ch * 16);
        cp16(sb + PA_HI + doff, Ah + (size_t)row * 112 + ch * 8, 16u);
        cp16(sb + PA_LO + doff, Al + (size_t)row * 112 + ch * 8, 16u);
        cp16(sb + PB_HI + doff, Bh + (size_t)row * 112 + ch * 8, 16u);
        cp16(sb + PB_LO + doff, Bl + (size_t)row * 112 + ch * 8, 16u);
    }
    asm volatile("cp.async.commit_group;" ::: "memory");
    asm volatile("cp.async.wait_group 0;" ::: "memory");
    __syncthreads();

    float c[2][8][4];
    #pragma unroll
    for (int mb = 0; mb < 2; mb++)
        #pragma unroll
        for (int nb = 0; nb < 8; nb++)
            #pragma unroll
            for (int r = 0; r < 4; r++) c[mb][nb][r] = 0.f;

    int a_r = lane & 15;
    int a_c = (lane >> 4) << 3;
    int b_r = (lane & 7) | ((lane & 16) >> 1);
    int b_c = lane & 8;

    #pragma unroll
    for (int kk = 0; kk < 7; kk++) {
        int k0 = kk << 4;
        uint32_t a_hi[2][4], a_lo[2][4];
        #pragma unroll
        for (int mb = 0; mb < 2; mb++) {
            uint32_t off = (uint32_t)((warp_m * 32 + mb * 16 + a_r) * PROW + k0 + a_c) * 2;
            ldsm_x4(a_hi[mb], sb + PA_HI + off);
            ldsm_x4(a_lo[mb], sb + PA_LO + off);
        }
        uint32_t b_hi[8][2], b_lo[8][2];
        #pragma unroll
        for (int nb2 = 0; nb2 < 4; nb2++) {
            uint32_t off = (uint32_t)((warp_n * 64 + nb2 * 16 + b_r) * PROW + k0 + b_c) * 2;
            uint32_t r4[4];
            ldsm_x4(r4, sb + PB_HI + off);
            b_hi[nb2*2][0] = r4[0]; b_hi[nb2*2][1] = r4[1];
            b_hi[nb2*2+1][0] = r4[2]; b_hi[nb2*2+1][1] = r4[3];
            ldsm_x4(r4, sb + PB_LO + off);
            b_lo[nb2*2][0] = r4[0]; b_lo[nb2*2][1] = r4[1];
            b_lo[nb2*2+1][0] = r4[2]; b_lo[nb2*2+1][1] = r4[3];
        }
        #pragma unroll
        for (int mb = 0; mb < 2; mb++)
            #pragma unroll
            for (int nb = 0; nb < 8; nb++) {
                mma16816(c[mb][nb], a_hi[mb], b_hi[nb]);
                mma16816(c[mb][nb], a_hi[mb], b_lo[nb]);
                mma16816(c[mb][nb], a_lo[mb], b_hi[nb]);
            }
    }

    #pragma unroll
    for (int mb = 0; mb < 2; mb++) {
        #pragma unroll
        for (int half = 0; half < 2; half++) {
            int cr = chalf * 128 + warp_m * 32 + mb * 16 + (lane >> 2) + half * 8;
            size_t rowo = ((size_t)bh * 256 + cr) * 128;
            #pragma unroll
            for (int nb = 0; nb < 8; nb++) {
                int e = warp_n * 64 + nb * 8 + ((lane & 3) << 1);
                float2 bz = *(const float2*)(bias + h * 128 + e);
                float v0 = c[mb][nb][half*2+0] + bz.x;
                float v1 = c[mb][nb][half*2+1] + bz.y;
                *(float2*)(outf + rowo + e) = make_float2(v0, v1);
                uint32_t lo;
                uint32_t hi = pack2(v0, v1, lo);
                *(uint32_t*)(outh + rowo + e) = hi;
                *(uint32_t*)(outl + rowo + e) = lo;
            }
        }
    }
}

// ---------------- temperature ----------------
__global__ __launch_bounds__(256) void temp_kernel(const float* __restrict__ wp_w,
                                                   const float* __restrict__ wp_b) {
    __shared__ float kbar[128];
    __shared__ float part[256];
    __shared__ float rowmean[256];
    int bh = blockIdx.x;
    int t = threadIdx.x;
    const float* kb = g_k + (size_t)bh * Cc * 128;
    const float* qb = g_q + (size_t)bh * Cc * 128;
    {
        int col = t & 127, half = t >> 7;
        float s = 0.f;
        for (int f = half * 128; f < half * 128 + 128; f++) s += kb[(size_t)f * 128 + col];
        part[t] = s;
    }
    __syncthreads();
    if (t < 128) kbar[t] = (part[t] + part[t + 128]) * (1.f / 256.f);
    __syncthreads();
    int w = t >> 5, lane = t & 31;
    float4 kv = *(const float4*)&kbar[lane << 2];
    for (int r = 0; r < 32; r++) {
        int c = (w << 5) + r;
        float4 qv = *(const float4*)(qb + (size_t)c * 128 + (lane << 2));
        float p = qv.x * kv.x + qv.y * kv.y + qv.z * kv.z + qv.w * kv.w;
        #pragma unroll
        for (int o = 16; o; o >>= 1) p += __shfl_xor_sync(0xFFFFFFFFu, p, o);
        if (lane == 0) rowmean[c] = p;
    }
    __syncthreads();
    float s = wp_b[t];
    for (int cc = 0; cc < 256; cc++) s += rowmean[cc] * wp_w[(size_t)cc * 256 + t];
    float sig = 1.f / (1.f + expf(-s));
    g_invden[(size_t)bh * 256 + t] = exp2f(-7.f * (0.2f + sig));
}

// ---------------- fused scores + softmax -> bf16 weights (hi only) ----------------
#define SROW 136
#define SQ_HI 0
#define SQ_LO 17408
#define SK_HI 34816
#define SK_LO 104448
#define SRED  174080
#define SS_SMEM 176128

__global__ __launch_bounds__(256) void scores_softmax_kernel() {
    extern __shared__ char smem[];
    uint32_t sb = smem_u32(smem);
    float* red = (float*)(smem + SRED);
    int t = threadIdx.x, lane = t & 31, wid = t >> 5;
    int warp_m = wid >> 2, warp_n = wid & 3;
    int bh = blockIdx.x, c0 = blockIdx.y << 6;

    #pragma unroll
    for (int it = 0; it < 4; it++) {
        int idx = t + (it << 8);
        int row = idx >> 4, u = idx & 15;
        size_t src = ((size_t)(bh * 256 + c0 + row)) * 128 + u * 8;
        uint32_t off = (uint32_t)(row * SROW + u * 8) * 2;
        *(uint4*)(smem + SQ_HI + off) = *(const uint4*)(g_qsh + src);
        *(uint4*)(smem + SQ_LO + off) = *(const uint4*)(g_qsl + src);
    }
    #pragma unroll
    for (int it = 0; it < 16; it++) {
        int idx = t + (it << 8);
        int row = idx >> 4, u = idx & 15;
        size_t src = ((size_t)(bh * 256 + row)) * 128 + u * 8;
        uint32_t off = (uint32_t)(row * SROW + u * 8) * 2;
        *(uint4*)(smem + SK_HI + off) = *(const uint4*)(g_ksh + src);
        *(uint4*)(smem + SK_LO + off) = *(const uint4*)(g_ksl + src);
    }
    __syncthreads();

    float c[2][8][4];
    #pragma unroll
    for (int mb = 0; mb < 2; mb++)
        #pragma unroll
        for (int nb = 0; nb < 8; nb++)
            #pragma unroll
            for (int r = 0; r < 4; r++) c[mb][nb][r] = 0.f;

    int a_r = lane & 15;
    int a_c = (lane >> 4) << 3;
    int b_r = (lane & 7) | ((lane & 16) >> 1);
    int b_c = lane & 8;

    #pragma unroll
    for (int kk = 0; kk < 8; kk++) {
        int k0 = kk << 4;
        uint32_t a_hi[2][4], a_lo[2][4];
        #pragma unroll
        for (int mb = 0; mb < 2; mb++) {
            uint32_t off = (uint32_t)((warp_m * 32 + mb * 16 + a_r) * SROW + k0 + a_c) * 2;
            ldsm_x4(a_hi[mb], sb + SQ_HI + off);
            ldsm_x4(a_lo[mb], sb + SQ_LO + off);
        }
        uint32_t b_hi[8][2], b_lo[8][2];
        #pragma unroll
        for (int nb2 = 0; nb2 < 4; nb2++) {
            uint32_t off = (uint32_t)((warp_n * 64 + nb2 * 16 + b_r) * SROW + k0 + b_c) * 2;
            uint32_t r4[4];
            ldsm_x4(r4, sb + SK_HI + off);
            b_hi[nb2*2][0] = r4[0]; b_hi[nb2*2][1] = r4[1];
            b_hi[nb2*2+1][0] = r4[2]; b_hi[nb2*2+1][1] = r4[3];
            ldsm_x4(r4, sb + SK_LO + off);
            b_lo[nb2*2][0] = r4[0]; b_lo[nb2*2][1] = r4[1];
            b_lo[nb2*2+1][0] = r4[2]; b_lo[nb2*2+1][1] = r4[3];
        }
        #pragma unroll
        for (int mb = 0; mb < 2; mb++)
            #pragma unroll
            for (int nb = 0; nb < 8; nb++) {
                mma16816(c[mb][nb], a_hi[mb], b_hi[nb]);
                mma16816(c[mb][nb], a_hi[mb], b_lo[nb]);
                mma16816(c[mb][nb], a_lo[mb], b_hi[nb]);
            }
    }

    float invd[2][2];
    #pragma unroll
    for (int mb = 0; mb < 2; mb++) {
        int rb = warp_m * 32 + mb * 16 + (lane >> 2);
        invd[mb][0] = g_invden[(size_t)bh * 256 + c0 + rb];
        invd[mb][1] = g_invden[(size_t)bh * 256 + c0 + rb + 8];
    }
    #pragma unroll
    for (int mb = 0; mb < 2; mb++)
        #pragma unroll
        for (int nb = 0; nb < 8; nb++) {
            c[mb][nb][0] *= invd[mb][0];
            c[mb][nb][1] *= invd[mb][0];
            c[mb][nb][2] *= invd[mb][1];
            c[mb][nb][3] *= invd[mb][1];
        }

    #pragma unroll
    for (int mb = 0; mb < 2; mb++)
        #pragma unroll
        for (int half = 0; half < 2; half++) {
            float mx = -INFINITY;
            #pragma unroll
            for (int nb = 0; nb < 8; nb++) {
                mx = fmaxf(mx, c[mb][nb][half*2+0]);
                mx = fmaxf(mx, c[mb][nb][half*2+1]);
            }
            mx = fmaxf(mx, __shfl_xor_sync(0xFFFFFFFFu, mx, 1));
            mx = fmaxf(mx, __shfl_xor_sync(0xFFFFFFFFu, mx, 2));
            if ((lane & 3) == 0) {
                int r = warp_m * 32 + mb * 16 + (lane >> 2) + half * 8;
                red[r * 8 + warp_n] = mx;
            }
        }
    __syncthreads();
    float bm[2][2];
    #pragma unroll
    for (int mb = 0; mb < 2; mb++)
        #pragma unroll
        for (int half = 0; half < 2; half++) {
            int r = warp_m * 32 + mb * 16 + (lane >> 2) + half * 8;
            bm[mb][half] = fmaxf(fmaxf(red[r*8+0], red[r*8+1]), fmaxf(red[r*8+2], red[r*8+3]));
        }
    #pragma unroll
    for (int mb = 0; mb < 2; mb++)
        #pragma unroll
        for (int half = 0; half < 2; half++) {
            float s = 0.f;
            #pragma unroll
            for (int nb = 0; nb < 8; nb++) {
                float e0 = expf(c[mb][nb][half*2+0] - bm[mb][half]);
                float e1 = expf(c[mb][nb][half*2+1] - bm[mb][half]);
                c[mb][nb][half*2+0] = e0;
                c[mb][nb][half*2+1] = e1;
                s += e0 + e1;
            }
            s += __shfl_xor_sync(0xFFFFFFFFu, s, 1);
            s += __shfl_xor_sync(0xFFFFFFFFu, s, 2);
            if ((lane & 3) == 0) {
                int r = warp_m * 32 + mb * 16 + (lane >> 2) + half * 8;
                red[r * 8 + 4 + warp_n] = s;
            }
        }
    __syncthreads();
    #pragma unroll
    for (int mb = 0; mb < 2; mb++)
        #pragma unroll
        for (int half = 0; half < 2; half++) {
            int r = warp_m * 32 + mb * 16 + (lane >> 2) + half * 8;
            float tot = red[r*8+4] + red[r*8+5] + red[r*8+6] + red[r*8+7];
            float inv = 1.f / tot;
            size_t rowbase = ((size_t)bh * 256 + c0 + r) * 256;
            #pragma unroll
            for (int nb = 0; nb < 8; nb++) {
                int f = warp_n * 64 + nb * 8 + ((lane & 3) << 1);
                uint32_t lo;
                uint32_t hi = pack2(c[mb][nb][half*2+0] * inv, c[mb][nb][half*2+1] * inv, lo);
                *(uint32_t*)(g_wh + rowbase + f) = hi;
            }
        }
}

// ---------------- att mma: A=vpool(hi+lo), B=weights(hi only) ----------------
#define AROW 72
#define AA_HI 0
#define AA_LO 18432
#define AB_HI 36864
#define ASTAGE 55296
#define ATT_SMEM (2*ASTAGE)

__device__ __forceinline__ void att_load_stage(
    uint32_t bufo, int f0, size_t abase, size_t bbase, int lrow, int lch)
{
    #pragma unroll
    for (int p = 0; p < 4; p++) {
        int row = lrow + p * 32;
        size_t asrc = abase + (size_t)row * 256 + f0 + lch * 8;
        size_t bsrc = bbase + (size_t)row * 256 + f0 + lch * 8;
        uint32_t doff = (uint32_t)(row * AROW + lch * 8) * 2;
        cp16(bufo + AA_HI + doff, g_vph + asrc, 16u);
        cp16(bufo + AA_LO + doff, g_vpl + asrc, 16u);
        cp16(bufo + AB_HI + doff, g_wh + bsrc, 16u);
    }
    asm volatile("cp.async.commit_group;" ::: "memory");
}

__global__ __launch_bounds__(256) void att_mma_kernel(const float* __restrict__ x,
                                                      float* __restrict__ out) {
    extern __shared__ char smem[];
    uint32_t sb = smem_u32(smem);
    int t = threadIdx.x, lane = t & 31, wid = t >> 5;
    int warp_m = wid >> 1, warp_n = wid & 1;
    int bh = blockIdx.x, chalf = blockIdx.y;
    int b = bh >> 3, h = bh & 7;
    size_t abase = ((size_t)b * 784 + h * 98) * 256;
    size_t bbase = ((size_t)bh * 256 + chalf * 128) * 256;

    int lrow = t >> 3, lch = t & 7;

    att_load_stage(sb, 0, abase, bbase, lrow, lch);

    float c[2][8][4];
    #pragma unroll
    for (int mb = 0; mb < 2; mb++)
        #pragma unroll
        for (int nb = 0; nb < 8; nb++)
            #pragma unroll
            for (int r = 0; r < 4; r++) c[mb][nb][r] = 0.f;

    int a_r = lane & 15;
    int a_c = (lane >> 4) << 3;
    int b_r = (lane & 7) | ((lane & 16) >> 1);
    int b_c = lane & 8;

    for (int s = 0; s < 4; s++) {
        if (s + 1 < 4) {
            att_load_stage(sb + (uint32_t)((s + 1) & 1) * ASTAGE, (s + 1) << 6,
                           abase, bbase, lrow, lch);
            asm volatile("cp.async.wait_group 1;" ::: "memory");
        } else {
            asm volatile("cp.async.wait_group 0;" ::: "memory");
        }
        __syncthreads();

        uint32_t bufo = sb + (uint32_t)(s & 1) * ASTAGE;
        #pragma unroll
        for (int kk = 0; kk < 4; kk++) {
            int k0 = kk << 4;
            uint32_t a_hi[2][4], a_lo[2][4];
            #pragma unroll
            for (int mb = 0; mb < 2; mb++) {
                uint32_t off = (uint32_t)((warp_m * 32 + mb * 16 + a_r) * AROW + k0 + a_c) * 2;
                ldsm_x4(a_hi[mb], bufo + AA_HI + off);
                ldsm_x4(a_lo[mb], bufo + AA_LO + off);
            }
            uint32_t b_hi[8][2];
            #pragma unroll
            for (int nb2 = 0; nb2 < 4; nb2++) {
                uint32_t off = (uint32_t)((warp_n * 64 + nb2 * 16 + b_r) * AROW + k0 + b_c) * 2;
                uint32_t r4[4];
                ldsm_x4(r4, bufo + AB_HI + off);
                b_hi[nb2*2][0] = r4[0]; b_hi[nb2*2][1] = r4[1];
                b_hi[nb2*2+1][0] = r4[2]; b_hi[nb2*2+1][1] = r4[3];
            }
            #pragma unroll
            for (int mb = 0; mb < 2; mb++)
                #pragma unroll
                for (int nb = 0; nb < 8; nb++) {
                    mma16816(c[mb][nb], a_hi[mb], b_hi[nb]);
                    mma16816(c[mb][nb], a_lo[mb], b_hi[nb]);
                }
        }
        __syncthreads();
    }

    #pragma unroll
    for (int mb = 0; mb < 2; mb++)
        #pragma unroll
        for (int half = 0; half < 2; half++) {
            int d = warp_m * 32 + mb * 16 + (lane >> 2) + half * 8;
            if (d < 98) {
                size_t rowo = abase + (size_t)d * 256 + chalf * 128;
                #pragma unroll
                for (int nb = 0; nb < 8; nb++) {
                    int cg = warp_n * 64 + nb * 8 + ((lane & 3) << 1);
                    float2 xv = *(const float2*)(x + rowo + cg);
                    *(float2*)(out + rowo + cg) =
                        make_float2(xv.x + c[mb][nb][half*2+0], xv.y + c[mb][nb][half*2+1]);
                }
            }
        }
}

// ---------------- launch: two-stream overlap ----------------
extern "C" void kernel_launch(void* const* d_in, const int* in_sizes, int n_in,
                              void* d_out, int out_size) {
    const float* x     = (const float*)d_in[0];
    const float* wqk_w = (const float*)d_in[1];
    const float* wqk_b = (const float*)d_in[2];
    const float* wp_w  = (const float*)d_in[3];
    const float* wp_b  = (const float*)d_in[4];
    const float* wv_w  = (const float*)d_in[5];
    const float* wv_b  = (const float*)d_in[6];
    float* out = (float*)d_out;

    cudaFuncSetAttribute(conv_mma_kernel, cudaFuncAttributeMaxDynamicSharedMemorySize, CONV_SMEM);
    cudaFuncSetAttribute(scores_softmax_kernel, cudaFuncAttributeMaxDynamicSharedMemorySize, SS_SMEM);
    cudaFuncSetAttribute(proj_mma_kernel, cudaFuncAttributeMaxDynamicSharedMemorySize, PROJ_SMEM);
    cudaFuncSetAttribute(att_mma_kernel, cudaFuncAttributeMaxDynamicSharedMemorySize, ATT_SMEM);

    cudaStream_t sB;
    cudaStreamCreateWithFlags(&sB, cudaStreamNonBlocking);
    cudaEvent_t eFork, eJoin;
    cudaEventCreateWithFlags(&eFork, cudaEventDisableTiming);
    cudaEventCreateWithFlags(&eJoin, cudaEventDisableTiming);

    cudaEventRecord(eFork, (cudaStream_t)0);
    cudaStreamWaitEvent(sB, eFork, 0);
    poolqkT_kernel<<<512, 256, 0, sB>>>(x);
    wqkT_kernel<<<8, 128, 0, sB>>>(wqk_w);
    proj_mma_kernel<<<dim3(512, 2, 2), 256, PROJ_SMEM, sB>>>(wqk_b);
    temp_kernel<<<512, 256, 0, sB>>>(wp_w, wp_b);
    scores_softmax_kernel<<<dim3(512, 4), 256, SS_SMEM, sB>>>();
    cudaEventRecord(eJoin, sB);

    split_x_kernel<<<12544, 256>>>(x);
    split_w_kernel<<<2304, 256>>>(wv_w);
    conv_mma_kernel<<<dim3(392, 2), 256, CONV_SMEM>>>(wv_b);
    pool_v_kernel<<<Bz * Ss, 256>>>();

    cudaStreamWaitEvent((cudaStream_t)0, eJoin, 0);
    att_mma_kernel<<<dim3(512, 2), 256, ATT_SMEM>>>(x, out);

    cudaEventDestroy(eFork);
    cudaEventDestroy(eJoin);
    cudaStreamDestroy(sB);
}

// round 15
// speedup vs baseline: 1.9679x; 1.6012x over previous
#include <cuda_runtime.h>
#include <cuda_bf16.h>
#include <cuda_fp16.h>
#include <cstdint>
#include <stdint.h>
#include <math.h>

#define Bz 64
#define Ss 784
#define Cc 256
#define Hh 8
#define BH 512

// ---------------- scratch ----------------
__device__ float g_vconv[Bz*Ss*Cc];
__device__ float g_q[BH*Cc*128];
__device__ float g_k[BH*Cc*128];
__device__ float g_invden[BH*Cc];
__device__ __half g_xf[Bz*Ss*Cc];            // x fp16
__device__ __half g_wt[Cc*2304];             // w^T fp16
__device__ __half g_qpT[BH*Cc*112];          // avg-pool^T fp16
__device__ __half g_kpT[BH*Cc*112];          // max-pool^T fp16
__device__ __half g_wqkT[Hh*128*112];        // wqk^T fp16
__device__ __half g_qs[BH*Cc*128];           // q fp16
__device__ __half g_ks[BH*Cc*128];           // k fp16
__device__ __half g_w[(size_t)BH*Cc*Cc];     // softmax weights fp16
__device__ __half g_vp[Bz*Ss*Cc + 8192];     // pooled v fp16

// ---------------- helpers ----------------
__device__ __forceinline__ uint32_t smem_u32(const void* p) {
    uint32_t a;
    asm("{ .reg .u64 t; cvta.to.shared.u64 t, %1; cvt.u32.u64 %0, t; }" : "=r"(a) : "l"(p));
    return a;
}
__device__ __forceinline__ void cp16(uint32_t dst, const void* src, uint32_t srcsize) {
    asm volatile("cp.async.cg.shared.global [%0], [%1], 16, %2;"
                 :: "r"(dst), "l"(src), "r"(srcsize) : "memory");
}
__device__ __forceinline__ void ldsm_x4(uint32_t* r, uint32_t addr) {
    asm volatile("ldmatrix.sync.aligned.m8n8.x4.shared.b16 {%0,%1,%2,%3}, [%4];"
                 : "=r"(r[0]), "=r"(r[1]), "=r"(r[2]), "=r"(r[3]) : "r"(addr));
}
__device__ __forceinline__ void mma16816h(float* c, const uint32_t* a, const uint32_t* b) {
    asm volatile("mma.sync.aligned.m16n8k16.row.col.f32.f16.f16.f32 "
                 "{%0,%1,%2,%3}, {%4,%5,%6,%7}, {%8,%9}, {%0,%1,%2,%3};"
                 : "+f"(c[0]), "+f"(c[1]), "+f"(c[2]), "+f"(c[3])
                 : "r"(a[0]), "r"(a[1]), "r"(a[2]), "r"(a[3]), "r"(b[0]), "r"(b[1]));
}
__device__ __forceinline__ uint32_t pack2h(float v0, float v1) {
    __half2 h = __floats2half2_rn(v0, v1);
    return *(uint32_t*)&h;
}

// ---------------- x -> fp16 ----------------
__global__ __launch_bounds__(256) void split_x_kernel(const float* __restrict__ x) {
    int idx4 = blockIdx.x * 256 + threadIdx.x;
    float4 v = ((const float4*)x)[idx4];
    ushort4 hp;
    hp.x = __half_as_ushort(__float2half(v.x));
    hp.y = __half_as_ushort(__float2half(v.y));
    hp.z = __half_as_ushort(__float2half(v.z));
    hp.w = __half_as_ushort(__float2half(v.w));
    ((ushort4*)g_xf)[idx4] = hp;
}

// ---------------- conv w -> fp16 transpose ----------------
__global__ __launch_bounds__(256) void split_w_kernel(const float* __restrict__ w) {
    int k = blockIdx.x;
    int co = threadIdx.x;
    g_wt[(size_t)co * 2304 + k] = __float2half(w[(size_t)k * 256 + co]);
}

// ---------------- fused avg/max pool + transpose -> fp16 ----------------
__global__ __launch_bounds__(256) void poolqkT_kernel(const float* __restrict__ x) {
    __shared__ float ta[32][33];
    __shared__ float tm[32][33];
    int bh = blockIdx.x;
    int b = bh >> 3, h = bh & 7;
    const float* xb = x + (size_t)b * 784 * 256;
    int t = threadIdx.x;
    int r8 = t >> 5, cl = t & 31;
    for (int dt = 0; dt < 4; dt++) {
        int d0 = dt << 5;
        for (int ct = 0; ct < 8; ct++) {
            int c0 = ct << 5;
            #pragma unroll
            for (int p = 0; p < 4; p++) {
                int dl = r8 + p * 8;
                int d = d0 + dl;
                float sum = 0.f, mx = -INFINITY;
                int cnt = 0;
                if (d < 98) {
                    int s = h * 98 + d;
                    int i = s / 28, j = s - i * 28;
                    #pragma unroll
                    for (int di = -1; di <= 1; di++)
                        #pragma unroll
                        for (int dj = -1; dj <= 1; dj++) {
                            int ii = i + di, jj = j + dj;
                            if ((unsigned)ii < 28u && (unsigned)jj < 28u) {
                                float v = xb[(size_t)(ii * 28 + jj) * 256 + c0 + cl];
                                sum += v;
                                mx = fmaxf(mx, v);
                                cnt++;
                            }
                        }
                    ta[dl][cl] = sum / (float)cnt;
                    tm[dl][cl] = mx;
                } else {
                    ta[dl][cl] = 0.f;
                    tm[dl][cl] = 0.f;
                }
            }
            __syncthreads();
            #pragma unroll
            for (int p = 0; p < 4; p++) {
                int cr = r8 + p * 8;
                int d = d0 + cl;
                if (d < 112) {
                    size_t o = ((size_t)bh * 256 + c0 + cr) * 112 + d;
                    g_qpT[o] = __float2half(ta[cl][cr]);
                    g_kpT[o] = __float2half(tm[cl][cr]);
                }
            }
            __syncthreads();
        }
    }
}

// ---------------- conv mma (fp16 single): CTA 128x128, 1 MMA/tile ----------------
#define CROW 72
#define CA 0
#define CB 18432
#define CSTAGE 36864
#define CONV_SMEM (2*CSTAGE)

__device__ __forceinline__ void conv_load_stage(
    int s, uint32_t sb, int row2, int half2, int bb, int pi, int pj, int n0g)
{
    uint32_t bufo = sb + (uint32_t)(s & 1) * CSTAGE;
    int tap = s >> 2;
    int di = tap / 3, dj = tap - di * 3;
    int ii = pi + di - 1, jj = pj + dj - 1;
    bool valid = ((unsigned)ii < 28u) && ((unsigned)jj < 28u);
    int ci0 = ((s & 3) << 6) + half2 * 32;
    size_t ga = ((size_t)(bb * 784 + (valid ? ii * 28 + jj : 0)) << 8) + ci0;
    uint32_t rowoff = (uint32_t)(row2 * CROW + half2 * 32) * 2;
    uint32_t vs = valid ? 16u : 0u;
    #pragma unroll
    for (int q = 0; q < 4; q++)
        cp16(bufo + CA + rowoff + q * 16, g_xf + ga + q * 8, vs);
    size_t gb = (size_t)(n0g + row2) * 2304 + (size_t)s * 64 + half2 * 32;
    #pragma unroll
    for (int q = 0; q < 4; q++)
        cp16(bufo + CB + rowoff + q * 16, g_wt + gb + q * 8, 16u);
    asm volatile("cp.async.commit_group;" ::: "memory");
}

__global__ __launch_bounds__(256) void conv_mma_kernel(const float* __restrict__ bias) {
    extern __shared__ char smem[];
    uint32_t sb = smem_u32(smem);
    int t = threadIdx.x, lane = t & 31, wid = t >> 5;
    int warp_m = wid >> 2, warp_n = wid & 3;
    int m0 = blockIdx.x << 7;
    int n0g = blockIdx.y << 7;

    int row2 = t >> 1, half2 = t & 1;
    int m = m0 + row2;
    int bb = m / 784;
    int pix = m - bb * 784;
    int pi = pix / 28, pj = pix - pi * 28;

    float c[4][4][4];
    #pragma unroll
    for (int mb = 0; mb < 4; mb++)
        #pragma unroll
        for (int nb = 0; nb < 4; nb++)
            #pragma unroll
            for (int r = 0; r < 4; r++) c[mb][nb][r] = 0.f;

    int a_r = lane & 15;
    int a_c = (lane >> 4) << 3;
    int b_r = (lane & 7) | ((lane & 16) >> 1);
    int b_c = lane & 8;

    conv_load_stage(0, sb, row2, half2, bb, pi, pj, n0g);

    for (int s = 0; s < 36; s++) {
        if (s + 1 < 36) {
            conv_load_stage(s + 1, sb, row2, half2, bb, pi, pj, n0g);
            asm volatile("cp.async.wait_group 1;" ::: "memory");
        } else {
            asm volatile("cp.async.wait_group 0;" ::: "memory");
        }
        __syncthreads();

        uint32_t bufo = sb + (uint32_t)(s & 1) * CSTAGE;
        #pragma unroll
        for (int kk = 0; kk < 4; kk++) {
            int k0 = kk << 4;
            uint32_t a[4][4];
            #pragma unroll
            for (int mb = 0; mb < 4; mb++) {
                uint32_t off = (uint32_t)((warp_m * 64 + mb * 16 + a_r) * CROW + k0 + a_c) * 2;
                ldsm_x4(a[mb], bufo + CA + off);
            }
            uint32_t bfr[4][2];
            #pragma unroll
            for (int nb2 = 0; nb2 < 2; nb2++) {
                uint32_t off = (uint32_t)((warp_n * 32 + nb2 * 16 + b_r) * CROW + k0 + b_c) * 2;
                uint32_t r4[4];
                ldsm_x4(r4, bufo + CB + off);
                bfr[nb2*2][0] = r4[0]; bfr[nb2*2][1] = r4[1];
                bfr[nb2*2+1][0] = r4[2]; bfr[nb2*2+1][1] = r4[3];
            }
            #pragma unroll
            for (int mb = 0; mb < 4; mb++)
                #pragma unroll
                for (int nb = 0; nb < 4; nb++)
                    mma16816h(c[mb][nb], a[mb], bfr[nb]);
        }
        __syncthreads();
    }

    #pragma unroll
    for (int mb = 0; mb < 4; mb++) {
        int rg = m0 + warp_m * 64 + mb * 16 + (lane >> 2);
        #pragma unroll
        for (int nb = 0; nb < 4; nb++) {
            int cg = n0g + warp_n * 32 + nb * 8 + ((lane & 3) << 1);
            float2 bz = *(const float2*)(bias + cg);
            *(float2*)(g_vconv + (size_t)rg * 256 + cg) =
                make_float2(c[mb][nb][0] + bz.x, c[mb][nb][1] + bz.y);
            *(float2*)(g_vconv + (size_t)(rg + 8) * 256 + cg) =
                make_float2(c[mb][nb][2] + bz.x, c[mb][nb][3] + bz.y);
        }
    }
}

// ---------------- pool of conv output -> fp16 ----------------
__global__ __launch_bounds__(256) void pool_v_kernel() {
    int bs = blockIdx.x;
    int c  = threadIdx.x;
    int b  = bs / 784;
    int pix = bs - b * 784;
    int i = pix / 28, j = pix - i * 28;
    const float* xb = g_vconv + (size_t)b * 784 * 256;
    float sum = 0.f;
    int cnt = 0;
    #pragma unroll
    for (int di = -1; di <= 1; di++) {
        #pragma unroll
        for (int dj = -1; dj <= 1; dj++) {
            int ii = i + di, jj = j + dj;
            if ((unsigned)ii < 28u && (unsigned)jj < 28u) {
                sum += xb[(size_t)(ii * 28 + jj) * 256 + c];
                cnt++;
            }
        }
    }
    g_vp[(size_t)bs * 256 + c] = __float2half(sum / (float)cnt);
}

// ---------------- wqk transpose -> fp16 ----------------
__global__ __launch_bounds__(128) void wqkT_kernel(const float* __restrict__ wqk) {
    int h = blockIdx.x;
    int e = threadIdx.x;
    for (int d = 0; d < 112; d++) {
        float v = (d < 98) ? wqk[((size_t)h * 98 + d) * 128 + e] : 0.f;
        g_wqkT[((size_t)h * 128 + e) * 112 + d] = __float2half(v);
    }
}

// ---------------- proj mma (fp16 single, 1 MMA/tile) ----------------
#define PROW 120
#define PA 0
#define PB 30720
#define PROJ_SMEM 61440

__global__ __launch_bounds__(256) void proj_mma_kernel(const float* __restrict__ bias) {
    extern __shared__ char smem[];
    uint32_t sb = smem_u32(smem);
    int t = threadIdx.x, lane = t & 31, wid = t >> 5;
    int warp_m = wid >> 1, warp_n = wid & 1;
    int bh = blockIdx.x, chalf = blockIdx.y, which = blockIdx.z;
    int h = bh & 7;
    const __half* A = (which ? g_kpT : g_qpT) + ((size_t)bh * 256 + chalf * 128) * 112;
    const __half* B = g_wqkT + (size_t)h * 128 * 112;
    float* outf = which ? g_k : g_q;
    __half* outs = which ? g_ks : g_qs;

    #pragma unroll
    for (int it = 0; it < 7; it++) {
        int idx = t + (it << 8);
        int row = idx / 14, ch = idx - row * 14;
        uint32_t doff = (uint32_t)(row * PROW * 2 + ch * 16);
        cp16(sb + PA + doff, A + (size_t)row * 112 + ch * 8, 16u);
        cp16(sb + PB + doff, B + (size_t)row * 112 + ch * 8, 16u);
    }
    asm volatile("cp.async.commit_group;" ::: "memory");
    asm volatile("cp.async.wait_group 0;" ::: "memory");
    __syncthreads();

    float c[2][8][4];
    #pragma unroll
    for (int mb = 0; mb < 2; mb++)
        #pragma unroll
        for (int nb = 0; nb < 8; nb++)
            #pragma unroll
            for (int r = 0; r < 4; r++) c[mb][nb][r] = 0.f;

    int a_r = lane & 15;
    int a_c = (lane >> 4) << 3;
    int b_r = (lane & 7) | ((lane & 16) >> 1);
    int b_c = lane & 8;

    #pragma unroll
    for (int kk = 0; kk < 7; kk++) {
        int k0 = kk << 4;
        uint32_t a[2][4];
        #pragma unroll
        for (int mb = 0; mb < 2; mb++) {
            uint32_t off = (uint32_t)((warp_m * 32 + mb * 16 + a_r) * PROW + k0 + a_c) * 2;
            ldsm_x4(a[mb], sb + PA + off);
        }
        uint32_t bfr[8][2];
        #pragma unroll
        for (int nb2 = 0; nb2 < 4; nb2++) {
            uint32_t off = (uint32_t)((warp_n * 64 + nb2 * 16 + b_r) * PROW + k0 + b_c) * 2;
            uint32_t r4[4];
            ldsm_x4(r4, sb + PB + off);
            bfr[nb2*2][0] = r4[0]; bfr[nb2*2][1] = r4[1];
            bfr[nb2*2+1][0] = r4[2]; bfr[nb2*2+1][1] = r4[3];
        }
        #pragma unroll
        for (int mb = 0; mb < 2; mb++)
            #pragma unroll
            for (int nb = 0; nb < 8; nb++)
                mma16816h(c[mb][nb], a[mb], bfr[nb]);
    }

    #pragma unroll
    for (int mb = 0; mb < 2; mb++) {
        #pragma unroll
        for (int half = 0; half < 2; half++) {
            int cr = chalf * 128 + warp_m * 32 + mb * 16 + (lane >> 2) + half * 8;
            size_t rowo = ((size_t)bh * 256 + cr) * 128;
            #pragma unroll
            for (int nb = 0; nb < 8; nb++) {
                int e = warp_n * 64 + nb * 8 + ((lane & 3) << 1);
                float2 bz = *(const float2*)(bias + h * 128 + e);
                float v0 = c[mb][nb][half*2+0] + bz.x;
                float v1 = c[mb][nb][half*2+1] + bz.y;
                *(float2*)(outf + rowo + e) = make_float2(v0, v1);
                *(uint32_t*)(outs + rowo + e) = pack2h(v0, v1);
            }
        }
    }
}

// ---------------- temperature ----------------
__global__ __launch_bounds__(256) void temp_kernel(const float* __restrict__ wp_w,
                                                   const float* __restrict__ wp_b) {
    __shared__ float kbar[128];
    __shared__ float part[256];
    __shared__ float rowmean[256];
    int bh = blockIdx.x;
    int t = threadIdx.x;
    const float* kb = g_k + (size_t)bh * Cc * 128;
    const float* qb = g_q + (size_t)bh * Cc * 128;
    {
        int col = t & 127, half = t >> 7;
        float s = 0.f;
        for (int f = half * 128; f < half * 128 + 128; f++) s += kb[(size_t)f * 128 + col];
        part[t] = s;
    }
    __syncthreads();
    if (t < 128) kbar[t] = (part[t] + part[t + 128]) * (1.f / 256.f);
    __syncthreads();
    int w = t >> 5, lane = t & 31;
    float4 kv = *(const float4*)&kbar[lane << 2];
    for (int r = 0; r < 32; r++) {
        int c = (w << 5) + r;
        float4 qv = *(const float4*)(qb + (size_t)c * 128 + (lane << 2));
        float p = qv.x * kv.x + qv.y * kv.y + qv.z * kv.z + qv.w * kv.w;
        #pragma unroll
        for (int o = 16; o; o >>= 1) p += __shfl_xor_sync(0xFFFFFFFFu, p, o);
        if (lane == 0) rowmean[c] = p;
    }
    __syncthreads();
    float s = wp_b[t];
    for (int cc = 0; cc < 256; cc++) s += rowmean[cc] * wp_w[(size_t)cc * 256 + t];
    float sig = 1.f / (1.f + expf(-s));
    g_invden[(size_t)bh * 256 + t] = exp2f(-7.f * (0.2f + sig));
}

// ---------------- fused scores + softmax (fp16 single, 1 MMA/tile) ----------------
#define SROW 136
#define SQ 0
#define SK 17408
#define SRED 87040
#define SS_SMEM 89088

__global__ __launch_bounds__(256) void scores_softmax_kernel() {
    extern __shared__ char smem[];
    uint32_t sb = smem_u32(smem);
    float* red = (float*)(smem + SRED);
    int t = threadIdx.x, lane = t & 31, wid = t >> 5;
    int warp_m = wid >> 2, warp_n = wid & 3;
    int bh = blockIdx.x, c0 = blockIdx.y << 6;

    #pragma unroll
    for (int it = 0; it < 4; it++) {
        int idx = t + (it << 8);
        int row = idx >> 4, u = idx & 15;
        size_t src = ((size_t)(bh * 256 + c0 + row)) * 128 + u * 8;
        uint32_t off = (uint32_t)(row * SROW + u * 8) * 2;
        *(uint4*)(smem + SQ + off) = *(const uint4*)(g_qs + src);
    }
    #pragma unroll
    for (int it = 0; it < 16; it++) {
        int idx = t + (it << 8);
        int row = idx >> 4, u = idx & 15;
        size_t src = ((size_t)(bh * 256 + row)) * 128 + u * 8;
        uint32_t off = (uint32_t)(row * SROW + u * 8) * 2;
        *(uint4*)(smem + SK + off) = *(const uint4*)(g_ks + src);
    }
    __syncthreads();

    float c[2][8][4];
    #pragma unroll
    for (int mb = 0; mb < 2; mb++)
        #pragma unroll
        for (int nb = 0; nb < 8; nb++)
            #pragma unroll
            for (int r = 0; r < 4; r++) c[mb][nb][r] = 0.f;

    int a_r = lane & 15;
    int a_c = (lane >> 4) << 3;
    int b_r = (lane & 7) | ((lane & 16) >> 1);
    int b_c = lane & 8;

    #pragma unroll
    for (int kk = 0; kk < 8; kk++) {
        int k0 = kk << 4;
        uint32_t a[2][4];
        #pragma unroll
        for (int mb = 0; mb < 2; mb++) {
            uint32_t off = (uint32_t)((warp_m * 32 + mb * 16 + a_r) * SROW + k0 + a_c) * 2;
            ldsm_x4(a[mb], sb + SQ + off);
        }
        uint32_t bfr[8][2];
        #pragma unroll
        for (int nb2 = 0; nb2 < 4; nb2++) {
            uint32_t off = (uint32_t)((warp_n * 64 + nb2 * 16 + b_r) * SROW + k0 + b_c) * 2;
            uint32_t r4[4];
            ldsm_x4(r4, sb + SK + off);
            bfr[nb2*2][0] = r4[0]; bfr[nb2*2][1] = r4[1];
            bfr[nb2*2+1][0] = r4[2]; bfr[nb2*2+1][1] = r4[3];
        }
        #pragma unroll
        for (int mb = 0; mb < 2; mb++)
            #pragma unroll
            for (int nb = 0; nb < 8; nb++)
                mma16816h(c[mb][nb], a[mb], bfr[nb]);
    }

    float invd[2][2];
    #pragma unroll
    for (int mb = 0; mb < 2; mb++) {
        int rb = warp_m * 32 + mb * 16 + (lane >> 2);
        invd[mb][0] = g_invden[(size_t)bh * 256 + c0 + rb];
        invd[mb][1] = g_invden[(size_t)bh * 256 + c0 + rb + 8];
    }
    #pragma unroll
    for (int mb = 0; mb < 2; mb++)
        #pragma unroll
        for (int nb = 0; nb < 8; nb++) {
            c[mb][nb][0] *= invd[mb][0];
            c[mb][nb][1] *= invd[mb][0];
            c[mb][nb][2] *= invd[mb][1];
            c[mb][nb][3] *= invd[mb][1];
        }

    #pragma unroll
    for (int mb = 0; mb < 2; mb++)
        #pragma unroll
        for (int half = 0; half < 2; half++) {
            float mx = -INFINITY;
            #pragma unroll
            for (int nb = 0; nb < 8; nb++) {
                mx = fmaxf(mx, c[mb][nb][half*2+0]);
                mx = fmaxf(mx, c[mb][nb][half*2+1]);
            }
            mx = fmaxf(mx, __shfl_xor_sync(0xFFFFFFFFu, mx, 1));
            mx = fmaxf(mx, __shfl_xor_sync(0xFFFFFFFFu, mx, 2));
            if ((lane & 3) == 0) {
                int r = warp_m * 32 + mb * 16 + (lane >> 2) + half * 8;
                red[r * 8 + warp_n] = mx;
            }
        }
    __syncthreads();
    float bm[2][2];
    #pragma unroll
    for (int mb = 0; mb < 2; mb++)
        #pragma unroll
        for (int half = 0; half < 2; half++) {
            int r = warp_m * 32 + mb * 16 + (lane >> 2) + half * 8;
            bm[mb][half] = fmaxf(fmaxf(red[r*8+0], red[r*8+1]), fmaxf(red[r*8+2], red[r*8+3]));
        }
    #pragma unroll
    for (int mb = 0; mb < 2; mb++)
        #pragma unroll
        for (int half = 0; half < 2; half++) {
            float s = 0.f;
            #pragma unroll
            for (int nb = 0; nb < 8; nb++) {
                float e0 = expf(c[mb][nb][half*2+0] - bm[mb][half]);
                float e1 = expf(c[mb][nb][half*2+1] - bm[mb][half]);
                c[mb][nb][half*2+0] = e0;
                c[mb][nb][half*2+1] = e1;
                s += e0 + e1;
            }
            s += __shfl_xor_sync(0xFFFFFFFFu, s, 1);
            s += __shfl_xor_sync(0xFFFFFFFFu, s, 2);
            if ((lane & 3) == 0) {
                int r = warp_m * 32 + mb * 16 + (lane >> 2) + half * 8;
                red[r * 8 + 4 + warp_n] = s;
            }
        }
    __syncthreads();
    #pragma unroll
    for (int mb = 0; mb < 2; mb++)
        #pragma unroll
        for (int half = 0; half < 2; half++) {
            int r = warp_m * 32 + mb * 16 + (lane >> 2) + half * 8;
            float tot = red[r*8+4] + red[r*8+5] + red[r*8+6] + red[r*8+7];
            float inv = 1.f / tot;
            size_t rowbase = ((size_t)bh * 256 + c0 + r) * 256;
            #pragma unroll
            for (int nb = 0; nb < 8; nb++) {
                int f = warp_n * 64 + nb * 8 + ((lane & 3) << 1);
                *(uint32_t*)(g_w + rowbase + f) =
                    pack2h(c[mb][nb][half*2+0] * inv, c[mb][nb][half*2+1] * inv);
            }
        }
}

// ---------------- att mma (fp16 single, 1 MMA/tile) ----------------
#define AROW 72
#define AA 0
#define AB 18432
#define ASTAGE 36864
#define ATT_SMEM (2*ASTAGE)

__device__ __forceinline__ void att_load_stage(
    uint32_t bufo, int f0, size_t abase, size_t bbase, int lrow, int lch)
{
    #pragma unroll
    for (int p = 0; p < 4; p++) {
        int row = lrow + p * 32;
        size_t asrc = abase + (size_t)row * 256 + f0 + lch * 8;
        size_t bsrc = bbase + (size_t)row * 256 + f0 + lch * 8;
        uint32_t doff = (uint32_t)(row * AROW + lch * 8) * 2;
        cp16(bufo + AA + doff, g_vp + asrc, 16u);
        cp16(bufo + AB + doff, g_w + bsrc, 16u);
    }
    asm volatile("cp.async.commit_group;" ::: "memory");
}

__global__ __launch_bounds__(256) void att_mma_kernel(const float* __restrict__ x,
                                                      float* __restrict__ out) {
    extern __shared__ char smem[];
    uint32_t sb = smem_u32(smem);
    int t = threadIdx.x, lane = t & 31, wid = t >> 5;
    int warp_m = wid >> 1, warp_n = wid & 1;
    int bh = blockIdx.x, chalf = blockIdx.y;
    int b = bh >> 3, h = bh & 7;
    size_t abase = ((size_t)b * 784 + h * 98) * 256;
    size_t bbase = ((size_t)bh * 256 + chalf * 128) * 256;

    int lrow = t >> 3, lch = t & 7;

    att_load_stage(sb, 0, abase, bbase, lrow, lch);

    float c[2][8][4];
    #pragma unroll
    for (int mb = 0; mb < 2; mb++)
        #pragma unroll
        for (int nb = 0; nb < 8; nb++)
            #pragma unroll
            for (int r = 0; r < 4; r++) c[mb][nb][r] = 0.f;

    int a_r = lane & 15;
    int a_c = (lane >> 4) << 3;
    int b_r = (lane & 7) | ((lane & 16) >> 1);
    int b_c = lane & 8;

    for (int s = 0; s < 4; s++) {
        if (s + 1 < 4) {
            att_load_stage(sb + (uint32_t)((s + 1) & 1) * ASTAGE, (s + 1) << 6,
                           abase, bbase, lrow, lch);
            asm volatile("cp.async.wait_group 1;" ::: "memory");
        } else {
            asm volatile("cp.async.wait_group 0;" ::: "memory");
        }
        __syncthreads();

        uint32_t bufo = sb + (uint32_t)(s & 1) * ASTAGE;
        #pragma unroll
        for (int kk = 0; kk < 4; kk++) {
            int k0 = kk << 4;
            uint32_t a[2][4];
            #pragma unroll
            for (int mb = 0; mb < 2; mb++) {
                uint32_t off = (uint32_t)((warp_m * 32 + mb * 16 + a_r) * AROW + k0 + a_c) * 2;
                ldsm_x4(a[mb], bufo + AA + off);
            }
            uint32_t bfr[8][2];
            #pragma unroll
            for (int nb2 = 0; nb2 < 4; nb2++) {
                uint32_t off = (uint32_t)((warp_n * 64 + nb2 * 16 + b_r) * AROW + k0 + b_c) * 2;
                uint32_t r4[4];
                ldsm_x4(r4, bufo + AB + off);
                bfr[nb2*2][0] = r4[0]; bfr[nb2*2][1] = r4[1];
                bfr[nb2*2+1][0] = r4[2]; bfr[nb2*2+1][1] = r4[3];
            }
            #pragma unroll
            for (int mb = 0; mb < 2; mb++)
                #pragma unroll
                for (int nb = 0; nb < 8; nb++)
                    mma16816h(c[mb][nb], a[mb], bfr[nb]);
        }
        __syncthreads();
    }

    #pragma unroll
    for (int mb = 0; mb < 2; mb++)
        #pragma unroll
        for (int half = 0; half < 2; half++) {
            int d = warp_m * 32 + mb * 16 + (lane >> 2) + half * 8;
            if (d < 98) {
                size_t rowo = abase + (size_t)d * 256 + chalf * 128;
                #pragma unroll
                for (int nb = 0; nb < 8; nb++) {
                    int cg = warp_n * 64 + nb * 8 + ((lane & 3) << 1);
                    float2 xv = *(const float2*)(x + rowo + cg);
                    *(float2*)(out + rowo + cg) =
                        make_float2(xv.x + c[mb][nb][half*2+0], xv.y + c[mb][nb][half*2+1]);
                }
            }
        }
}

// ---------------- launch: two-stream overlap ----------------
extern "C" void kernel_launch(void* const* d_in, const int* in_sizes, int n_in,
                              void* d_out, int out_size) {
    const float* x     = (const float*)d_in[0];
    const float* wqk_w = (const float*)d_in[1];
    const float* wqk_b = (const float*)d_in[2];
    const float* wp_w  = (const float*)d_in[3];
    const float* wp_b  = (const float*)d_in[4];
    const float* wv_w  = (const float*)d_in[5];
    const float* wv_b  = (const float*)d_in[6];
    float* out = (float*)d_out;

    cudaFuncSetAttribute(conv_mma_kernel, cudaFuncAttributeMaxDynamicSharedMemorySize, CONV_SMEM);
    cudaFuncSetAttribute(scores_softmax_kernel, cudaFuncAttributeMaxDynamicSharedMemorySize, SS_SMEM);
    cudaFuncSetAttribute(proj_mma_kernel, cudaFuncAttributeMaxDynamicSharedMemorySize, PROJ_SMEM);
    cudaFuncSetAttribute(att_mma_kernel, cudaFuncAttributeMaxDynamicSharedMemorySize, ATT_SMEM);

    cudaStream_t sB;
    cudaStreamCreateWithFlags(&sB, cudaStreamNonBlocking);
    cudaEvent_t eFork, eJoin;
    cudaEventCreateWithFlags(&eFork, cudaEventDisableTiming);
    cudaEventCreateWithFlags(&eJoin, cudaEventDisableTiming);

    cudaEventRecord(eFork, (cudaStream_t)0);
    cudaStreamWaitEvent(sB, eFork, 0);
    poolqkT_kernel<<<512, 256, 0, sB>>>(x);
    wqkT_kernel<<<8, 128, 0, sB>>>(wqk_w);
    proj_mma_kernel<<<dim3(512, 2, 2), 256, PROJ_SMEM, sB>>>(wqk_b);
    temp_kernel<<<512, 256, 0, sB>>>(wp_w, wp_b);
    scores_softmax_kernel<<<dim3(512, 4), 256, SS_SMEM, sB>>>();
    cudaEventRecord(eJoin, sB);

    split_x_kernel<<<12544, 256>>>(x);
    split_w_kernel<<<2304, 256>>>(wv_w);
    conv_mma_kernel<<<dim3(392, 2), 256, CONV_SMEM>>>(wv_b);
    pool_v_kernel<<<Bz * Ss, 256>>>();

    cudaStreamWaitEvent((cudaStream_t)0, eJoin, 0);
    att_mma_kernel<<<dim3(512, 2), 256, ATT_SMEM>>>(x, out);

    cudaEventDestroy(eFork);
    cudaEventDestroy(eJoin);
    cudaStreamDestroy(sB);
}

// round 16
// speedup vs baseline: 2.0375x; 1.0353x over previous
#include <cuda_runtime.h>
#include <cuda_bf16.h>
#include <cuda_fp16.h>
#include <cstdint>
#include <stdint.h>
#include <math.h>

#define Bz 64
#define Ss 784
#define Cc 256
#define Hh 8
#define BH 512

// ---------------- scratch ----------------
__device__ float g_invden[BH*Cc];
__device__ __half g_xf[Bz*Ss*Cc];            // x fp16
__device__ __half g_wt[Cc*2304];             // w^T fp16
__device__ __half g_vch[Bz*Ss*Cc];           // conv out fp16
__device__ __half g_qpT[BH*Cc*112];          // avg-pool^T fp16
__device__ __half g_kpT[BH*Cc*112];          // max-pool^T fp16
__device__ __half g_wqkT[Hh*128*112];        // wqk^T fp16
__device__ __half g_qs[BH*Cc*128];           // q fp16
__device__ __half g_ks[BH*Cc*128];           // k fp16
__device__ __half g_w[(size_t)BH*Cc*Cc];     // softmax weights fp16
__device__ __half g_vp[Bz*Ss*Cc + 8192];     // pooled v fp16

// ---------------- helpers ----------------
__device__ __forceinline__ uint32_t smem_u32(const void* p) {
    uint32_t a;
    asm("{ .reg .u64 t; cvta.to.shared.u64 t, %1; cvt.u32.u64 %0, t; }" : "=r"(a) : "l"(p));
    return a;
}
__device__ __forceinline__ void cp16(uint32_t dst, const void* src, uint32_t srcsize) {
    asm volatile("cp.async.cg.shared.global [%0], [%1], 16, %2;"
                 :: "r"(dst), "l"(src), "r"(srcsize) : "memory");
}
__device__ __forceinline__ void ldsm_x4(uint32_t* r, uint32_t addr) {
    asm volatile("ldmatrix.sync.aligned.m8n8.x4.shared.b16 {%0,%1,%2,%3}, [%4];"
                 : "=r"(r[0]), "=r"(r[1]), "=r"(r[2]), "=r"(r[3]) : "r"(addr));
}
__device__ __forceinline__ void mma16816h(float* c, const uint32_t* a, const uint32_t* b) {
    asm volatile("mma.sync.aligned.m16n8k16.row.col.f32.f16.f16.f32 "
                 "{%0,%1,%2,%3}, {%4,%5,%6,%7}, {%8,%9}, {%0,%1,%2,%3};"
                 : "+f"(c[0]), "+f"(c[1]), "+f"(c[2]), "+f"(c[3])
                 : "r"(a[0]), "r"(a[1]), "r"(a[2]), "r"(a[3]), "r"(b[0]), "r"(b[1]));
}
__device__ __forceinline__ uint32_t pack2h(float v0, float v1) {
    __half2 h = __floats2half2_rn(v0, v1);
    return *(uint32_t*)&h;
}

// ---------------- x -> fp16 ----------------
__global__ __launch_bounds__(256) void split_x_kernel(const float* __restrict__ x) {
    int idx4 = blockIdx.x * 256 + threadIdx.x;
    float4 v = ((const float4*)x)[idx4];
    ushort4 hp;
    hp.x = __half_as_ushort(__float2half(v.x));
    hp.y = __half_as_ushort(__float2half(v.y));
    hp.z = __half_as_ushort(__float2half(v.z));
    hp.w = __half_as_ushort(__float2half(v.w));
    ((ushort4*)g_xf)[idx4] = hp;
}

// ---------------- conv w -> fp16 transpose ----------------
__global__ __launch_bounds__(256) void split_w_kernel(const float* __restrict__ w) {
    int k = blockIdx.x;
    int co = threadIdx.x;
    g_wt[(size_t)co * 2304 + k] = __float2half(w[(size_t)k * 256 + co]);
}

// ---------------- fused avg/max pool + transpose -> fp16 ----------------
__global__ __launch_bounds__(256) void poolqkT_kernel(const float* __restrict__ x) {
    __shared__ float ta[32][33];
    __shared__ float tm[32][33];
    int bh = blockIdx.x;
    int b = bh >> 3, h = bh & 7;
    const float* xb = x + (size_t)b * 784 * 256;
    int t = threadIdx.x;
    int r8 = t >> 5, cl = t & 31;
    for (int dt = 0; dt < 4; dt++) {
        int d0 = dt << 5;
        for (int ct = 0; ct < 8; ct++) {
            int c0 = ct << 5;
            #pragma unroll
            for (int p = 0; p < 4; p++) {
                int dl = r8 + p * 8;
                int d = d0 + dl;
                float sum = 0.f, mx = -INFINITY;
                int cnt = 0;
                if (d < 98) {
                    int s = h * 98 + d;
                    int i = s / 28, j = s - i * 28;
                    #pragma unroll
                    for (int di = -1; di <= 1; di++)
                        #pragma unroll
                        for (int dj = -1; dj <= 1; dj++) {
                            int ii = i + di, jj = j + dj;
                            if ((unsigned)ii < 28u && (unsigned)jj < 28u) {
                                float v = xb[(size_t)(ii * 28 + jj) * 256 + c0 + cl];
                                sum += v;
                                mx = fmaxf(mx, v);
                                cnt++;
                            }
                        }
                    ta[dl][cl] = sum / (float)cnt;
                    tm[dl][cl] = mx;
                } else {
                    ta[dl][cl] = 0.f;
                    tm[dl][cl] = 0.f;
                }
            }
            __syncthreads();
            #pragma unroll
            for (int p = 0; p < 4; p++) {
                int cr = r8 + p * 8;
                int d = d0 + cl;
                if (d < 112) {
                    size_t o = ((size_t)bh * 256 + c0 + cr) * 112 + d;
                    g_qpT[o] = __float2half(ta[cl][cr]);
                    g_kpT[o] = __float2half(tm[cl][cr]);
                }
            }
            __syncthreads();
        }
    }
}

// ---------------- conv mma (fp16 single): CTA 128x128, 1 MMA/tile ----------------
#define CROW 72
#define CA 0
#define CB 18432
#define CSTAGE 36864
#define CONV_SMEM (2*CSTAGE)

__device__ __forceinline__ void conv_load_stage(
    int s, uint32_t sb, int row2, int half2, int bb, int pi, int pj, int n0g)
{
    uint32_t bufo = sb + (uint32_t)(s & 1) * CSTAGE;
    int tap = s >> 2;
    int di = tap / 3, dj = tap - di * 3;
    int ii = pi + di - 1, jj = pj + dj - 1;
    bool valid = ((unsigned)ii < 28u) && ((unsigned)jj < 28u);
    int ci0 = ((s & 3) << 6) + half2 * 32;
    size_t ga = ((size_t)(bb * 784 + (valid ? ii * 28 + jj : 0)) << 8) + ci0;
    uint32_t rowoff = (uint32_t)(row2 * CROW + half2 * 32) * 2;
    uint32_t vs = valid ? 16u : 0u;
    #pragma unroll
    for (int q = 0; q < 4; q++)
        cp16(bufo + CA + rowoff + q * 16, g_xf + ga + q * 8, vs);
    size_t gb = (size_t)(n0g + row2) * 2304 + (size_t)s * 64 + half2 * 32;
    #pragma unroll
    for (int q = 0; q < 4; q++)
        cp16(bufo + CB + rowoff + q * 16, g_wt + gb + q * 8, 16u);
    asm volatile("cp.async.commit_group;" ::: "memory");
}

__global__ __launch_bounds__(256) void conv_mma_kernel(const float* __restrict__ bias) {
    extern __shared__ char smem[];
    uint32_t sb = smem_u32(smem);
    int t = threadIdx.x, lane = t & 31, wid = t >> 5;
    int warp_m = wid >> 2, warp_n = wid & 3;
    int m0 = blockIdx.x << 7;
    int n0g = blockIdx.y << 7;

    int row2 = t >> 1, half2 = t & 1;
    int m = m0 + row2;
    int bb = m / 784;
    int pix = m - bb * 784;
    int pi = pix / 28, pj = pix - pi * 28;

    float c[4][4][4];
    #pragma unroll
    for (int mb = 0; mb < 4; mb++)
        #pragma unroll
        for (int nb = 0; nb < 4; nb++)
            #pragma unroll
            for (int r = 0; r < 4; r++) c[mb][nb][r] = 0.f;

    int a_r = lane & 15;
    int a_c = (lane >> 4) << 3;
    int b_r = (lane & 7) | ((lane & 16) >> 1);
    int b_c = lane & 8;

    conv_load_stage(0, sb, row2, half2, bb, pi, pj, n0g);

    for (int s = 0; s < 36; s++) {
        if (s + 1 < 36) {
            conv_load_stage(s + 1, sb, row2, half2, bb, pi, pj, n0g);
            asm volatile("cp.async.wait_group 1;" ::: "memory");
        } else {
            asm volatile("cp.async.wait_group 0;" ::: "memory");
        }
        __syncthreads();

        uint32_t bufo = sb + (uint32_t)(s & 1) * CSTAGE;
        #pragma unroll
        for (int kk = 0; kk < 4; kk++) {
            int k0 = kk << 4;
            uint32_t a[4][4];
            #pragma unroll
            for (int mb = 0; mb < 4; mb++) {
                uint32_t off = (uint32_t)((warp_m * 64 + mb * 16 + a_r) * CROW + k0 + a_c) * 2;
                ldsm_x4(a[mb], bufo + CA + off);
            }
            uint32_t bfr[4][2];
            #pragma unroll
            for (int nb2 = 0; nb2 < 2; nb2++) {
                uint32_t off = (uint32_t)((warp_n * 32 + nb2 * 16 + b_r) * CROW + k0 + b_c) * 2;
                uint32_t r4[4];
                ldsm_x4(r4, bufo + CB + off);
                bfr[nb2*2][0] = r4[0]; bfr[nb2*2][1] = r4[1];
                bfr[nb2*2+1][0] = r4[2]; bfr[nb2*2+1][1] = r4[3];
            }
            #pragma unroll
            for (int mb = 0; mb < 4; mb++)
                #pragma unroll
                for (int nb = 0; nb < 4; nb++)
                    mma16816h(c[mb][nb], a[mb], bfr[nb]);
        }
        __syncthreads();
    }

    // epilogue: bias add, store fp16
    #pragma unroll
    for (int mb = 0; mb < 4; mb++) {
        int rg = m0 + warp_m * 64 + mb * 16 + (lane >> 2);
        #pragma unroll
        for (int nb = 0; nb < 4; nb++) {
            int cg = n0g + warp_n * 32 + nb * 8 + ((lane & 3) << 1);
            float2 bz = *(const float2*)(bias + cg);
            *(uint32_t*)(g_vch + (size_t)rg * 256 + cg) =
                pack2h(c[mb][nb][0] + bz.x, c[mb][nb][1] + bz.y);
            *(uint32_t*)(g_vch + (size_t)(rg + 8) * 256 + cg) =
                pack2h(c[mb][nb][2] + bz.x, c[mb][nb][3] + bz.y);
        }
    }
}

// ---------------- pool of conv output (fp16 in/out) ----------------
__global__ __launch_bounds__(256) void pool_v_kernel() {
    int bs = blockIdx.x;
    int c  = threadIdx.x;
    int b  = bs / 784;
    int pix = bs - b * 784;
    int i = pix / 28, j = pix - i * 28;
    const __half* xb = g_vch + (size_t)b * 784 * 256;
    float sum = 0.f;
    int cnt = 0;
    #pragma unroll
    for (int di = -1; di <= 1; di++) {
        #pragma unroll
        for (int dj = -1; dj <= 1; dj++) {
            int ii = i + di, jj = j + dj;
            if ((unsigned)ii < 28u && (unsigned)jj < 28u) {
                sum += __half2float(xb[(size_t)(ii * 28 + jj) * 256 + c]);
                cnt++;
            }
        }
    }
    g_vp[(size_t)bs * 256 + c] = __float2half(sum / (float)cnt);
}

// ---------------- wqk transpose -> fp16 ----------------
__global__ __launch_bounds__(128) void wqkT_kernel(const float* __restrict__ wqk) {
    int h = blockIdx.x;
    int e = threadIdx.x;
    for (int d = 0; d < 112; d++) {
        float v = (d < 98) ? wqk[((size_t)h * 98 + d) * 128 + e] : 0.f;
        g_wqkT[((size_t)h * 128 + e) * 112 + d] = __float2half(v);
    }
}

// ---------------- proj mma (fp16 single; fp16 out only) ----------------
#define PROW 120
#define PA 0
#define PB 30720
#define PROJ_SMEM 61440

__global__ __launch_bounds__(256) void proj_mma_kernel(const float* __restrict__ bias) {
    extern __shared__ char smem[];
    uint32_t sb = smem_u32(smem);
    int t = threadIdx.x, lane = t & 31, wid = t >> 5;
    int warp_m = wid >> 1, warp_n = wid & 1;
    int bh = blockIdx.x, chalf = blockIdx.y, which = blockIdx.z;
    int h = bh & 7;
    const __half* A = (which ? g_kpT : g_qpT) + ((size_t)bh * 256 + chalf * 128) * 112;
    const __half* B = g_wqkT + (size_t)h * 128 * 112;
    __half* outs = which ? g_ks : g_qs;

    #pragma unroll
    for (int it = 0; it < 7; it++) {
        int idx = t + (it << 8);
        int row = idx / 14, ch = idx - row * 14;
        uint32_t doff = (uint32_t)(row * PROW * 2 + ch * 16);
        cp16(sb + PA + doff, A + (size_t)row * 112 + ch * 8, 16u);
        cp16(sb + PB + doff, B + (size_t)row * 112 + ch * 8, 16u);
    }
    asm volatile("cp.async.commit_group;" ::: "memory");
    asm volatile("cp.async.wait_group 0;" ::: "memory");
    __syncthreads();

    float c[2][8][4];
    #pragma unroll
    for (int mb = 0; mb < 2; mb++)
        #pragma unroll
        for (int nb = 0; nb < 8; nb++)
            #pragma unroll
            for (int r = 0; r < 4; r++) c[mb][nb][r] = 0.f;

    int a_r = lane & 15;
    int a_c = (lane >> 4) << 3;
    int b_r = (lane & 7) | ((lane & 16) >> 1);
    int b_c = lane & 8;

    #pragma unroll
    for (int kk = 0; kk < 7; kk++) {
        int k0 = kk << 4;
        uint32_t a[2][4];
        #pragma unroll
        for (int mb = 0; mb < 2; mb++) {
            uint32_t off = (uint32_t)((warp_m * 32 + mb * 16 + a_r) * PROW + k0 + a_c) * 2;
            ldsm_x4(a[mb], sb + PA + off);
        }
        uint32_t bfr[8][2];
        #pragma unroll
        for (int nb2 = 0; nb2 < 4; nb2++) {
            uint32_t off = (uint32_t)((warp_n * 64 + nb2 * 16 + b_r) * PROW + k0 + b_c) * 2;
            uint32_t r4[4];
            ldsm_x4(r4, sb + PB + off);
            bfr[nb2*2][0] = r4[0]; bfr[nb2*2][1] = r4[1];
            bfr[nb2*2+1][0] = r4[2]; bfr[nb2*2+1][1] = r4[3];
        }
        #pragma unroll
        for (int mb = 0; mb < 2; mb++)
            #pragma unroll
            for (int nb = 0; nb < 8; nb++)
                mma16816h(c[mb][nb], a[mb], bfr[nb]);
    }

    #pragma unroll
    for (int mb = 0; mb < 2; mb++) {
        #pragma unroll
        for (int half = 0; half < 2; half++) {
            int cr = chalf * 128 + warp_m * 32 + mb * 16 + (lane >> 2) + half * 8;
            size_t rowo = ((size_t)bh * 256 + cr) * 128;
            #pragma unroll
            for (int nb = 0; nb < 8; nb++) {
                int e = warp_n * 64 + nb * 8 + ((lane & 3) << 1);
                float2 bz = *(const float2*)(bias + h * 128 + e);
                *(uint32_t*)(outs + rowo + e) =
                    pack2h(c[mb][nb][half*2+0] + bz.x, c[mb][nb][half*2+1] + bz.y);
            }
        }
    }
}

// ---------------- temperature (reads fp16 q/k) ----------------
__global__ __launch_bounds__(256) void temp_kernel(const float* __restrict__ wp_w,
                                                   const float* __restrict__ wp_b) {
    __shared__ float kbar[128];
    __shared__ float part[256];
    __shared__ float rowmean[256];
    int bh = blockIdx.x;
    int t = threadIdx.x;
    const __half* kb = g_ks + (size_t)bh * Cc * 128;
    const __half* qb = g_qs + (size_t)bh * Cc * 128;
    {
        int col = t & 127, half = t >> 7;
        float s = 0.f;
        for (int f = half * 128; f < half * 128 + 128; f++)
            s += __half2float(kb[(size_t)f * 128 + col]);
        part[t] = s;
    }
    __syncthreads();
    if (t < 128) kbar[t] = (part[t] + part[t + 128]) * (1.f / 256.f);
    __syncthreads();
    int w = t >> 5, lane = t & 31;
    float4 kv = *(const float4*)&kbar[lane << 2];
    for (int r = 0; r < 32; r++) {
        int c = (w << 5) + r;
        uint2 qraw = *(const uint2*)(qb + (size_t)c * 128 + (lane << 2));
        __half2 q01 = *(__half2*)&qraw.x;
        __half2 q23 = *(__half2*)&qraw.y;
        float2 f01 = __half22float2(q01);
        float2 f23 = __half22float2(q23);
        float p = f01.x * kv.x + f01.y * kv.y + f23.x * kv.z + f23.y * kv.w;
        #pragma unroll
        for (int o = 16; o; o >>= 1) p += __shfl_xor_sync(0xFFFFFFFFu, p, o);
        if (lane == 0) rowmean[c] = p;
    }
    __syncthreads();
    float s = wp_b[t];
    for (int cc = 0; cc < 256; cc++) s += rowmean[cc] * wp_w[(size_t)cc * 256 + t];
    float sig = 1.f / (1.f + expf(-s));
    g_invden[(size_t)bh * 256 + t] = exp2f(-7.f * (0.2f + sig));
}

// ---------------- fused scores + softmax (fp16 single) ----------------
#define SROW 136
#define SQ 0
#define SK 17408
#define SRED 87040
#define SS_SMEM 89088

__global__ __launch_bounds__(256) void scores_softmax_kernel() {
    extern __shared__ char smem[];
    uint32_t sb = smem_u32(smem);
    float* red = (float*)(smem + SRED);
    int t = threadIdx.x, lane = t & 31, wid = t >> 5;
    int warp_m = wid >> 2, warp_n = wid & 3;
    int bh = blockIdx.x, c0 = blockIdx.y << 6;

    #pragma unroll
    for (int it = 0; it < 4; it++) {
        int idx = t + (it << 8);
        int row = idx >> 4, u = idx & 15;
        size_t src = ((size_t)(bh * 256 + c0 + row)) * 128 + u * 8;
        uint32_t off = (uint32_t)(row * SROW + u * 8) * 2;
        *(uint4*)(smem + SQ + off) = *(const uint4*)(g_qs + src);
    }
    #pragma unroll
    for (int it = 0; it < 16; it++) {
        int idx = t + (it << 8);
        int row = idx >> 4, u = idx & 15;
        size_t src = ((size_t)(bh * 256 + row)) * 128 + u * 8;
        uint32_t off = (uint32_t)(row * SROW + u * 8) * 2;
        *(uint4*)(smem + SK + off) = *(const uint4*)(g_ks + src);
    }
    __syncthreads();

    float c[2][8][4];
    #pragma unroll
    for (int mb = 0; mb < 2; mb++)
        #pragma unroll
        for (int nb = 0; nb < 8; nb++)
            #pragma unroll
            for (int r = 0; r < 4; r++) c[mb][nb][r] = 0.f;

    int a_r = lane & 15;
    int a_c = (lane >> 4) << 3;
    int b_r = (lane & 7) | ((lane & 16) >> 1);
    int b_c = lane & 8;

    #pragma unroll
    for (int kk = 0; kk < 8; kk++) {
        int k0 = kk << 4;
        uint32_t a[2][4];
        #pragma unroll
        for (int mb = 0; mb < 2; mb++) {
            uint32_t off = (uint32_t)((warp_m * 32 + mb * 16 + a_r) * SROW + k0 + a_c) * 2;
            ldsm_x4(a[mb], sb + SQ + off);
        }
        uint32_t bfr[8][2];
        #pragma unroll
        for (int nb2 = 0; nb2 < 4; nb2++) {
            uint32_t off = (uint32_t)((warp_n * 64 + nb2 * 16 + b_r) * SROW + k0 + b_c) * 2;
            uint32_t r4[4];
            ldsm_x4(r4, sb + SK + off);
            bfr[nb2*2][0] = r4[0]; bfr[nb2*2][1] = r4[1];
            bfr[nb2*2+1][0] = r4[2]; bfr[nb2*2+1][1] = r4[3];
        }
        #pragma unroll
        for (int mb = 0; mb < 2; mb++)
            #pragma unroll
            for (int nb = 0; nb < 8; nb++)
                mma16816h(c[mb][nb], a[mb], bfr[nb]);
    }

    float invd[2][2];
    #pragma unroll
    for (int mb = 0; mb < 2; mb++) {
        int rb = warp_m * 32 + mb * 16 + (lane >> 2);
        invd[mb][0] = g_invden[(size_t)bh * 256 + c0 + rb];
        invd[mb][1] = g_invden[(size_t)bh * 256 + c0 + rb + 8];
    }
    #pragma unroll
    for (int mb = 0; mb < 2; mb++)
        #pragma unroll
        for (int nb = 0; nb < 8; nb++) {
            c[mb][nb][0] *= invd[mb][0];
            c[mb][nb][1] *= invd[mb][0];
            c[mb][nb][2] *= invd[mb][1];
            c[mb][nb][3] *= invd[mb][1];
        }

    #pragma unroll
    for (int mb = 0; mb < 2; mb++)
        #pragma unroll
        for (int half = 0; half < 2; half++) {
            float mx = -INFINITY;
            #pragma unroll
            for (int nb = 0; nb < 8; nb++) {
                mx = fmaxf(mx, c[mb][nb][half*2+0]);
                mx = fmaxf(mx, c[mb][nb][half*2+1]);
            }
            mx = fmaxf(mx, __shfl_xor_sync(0xFFFFFFFFu, mx, 1));
            mx = fmaxf(mx, __shfl_xor_sync(0xFFFFFFFFu, mx, 2));
            if ((lane & 3) == 0) {
                int r = warp_m * 32 + mb * 16 + (lane >> 2) + half * 8;
                red[r * 8 + warp_n] = mx;
            }
        }
    __syncthreads();
    float bm[2][2];
    #pragma unroll
    for (int mb = 0; mb < 2; mb++)
        #pragma unroll
        for (int half = 0; half < 2; half++) {
            int r = warp_m * 32 + mb * 16 + (lane >> 2) + half * 8;
            bm[mb][half] = fmaxf(fmaxf(red[r*8+0], red[r*8+1]), fmaxf(red[r*8+2], red[r*8+3]));
        }
    #pragma unroll
    for (int mb = 0; mb < 2; mb++)
        #pragma unroll
        for (int half = 0; half < 2; half++) {
            float s = 0.f;
            #pragma unroll
            for (int nb = 0; nb < 8; nb++) {
                float e0 = expf(c[mb][nb][half*2+0] - bm[mb][half]);
                float e1 = expf(c[mb][nb][half*2+1] - bm[mb][half]);
                c[mb][nb][half*2+0] = e0;
                c[mb][nb][half*2+1] = e1;
                s += e0 + e1;
            }
            s += __shfl_xor_sync(0xFFFFFFFFu, s, 1);
            s += __shfl_xor_sync(0xFFFFFFFFu, s, 2);
            if ((lane & 3) == 0) {
                int r = warp_m * 32 + mb * 16 + (lane >> 2) + half * 8;
                red[r * 8 + 4 + warp_n] = s;
            }
        }
    __syncthreads();
    #pragma unroll
    for (int mb = 0; mb < 2; mb++)
        #pragma unroll
        for (int half = 0; half < 2; half++) {
            int r = warp_m * 32 + mb * 16 + (lane >> 2) + half * 8;
            float tot = red[r*8+4] + red[r*8+5] + red[r*8+6] + red[r*8+7];
            float inv = 1.f / tot;
            size_t rowbase = ((size_t)bh * 256 + c0 + r) * 256;
            #pragma unroll
            for (int nb = 0; nb < 8; nb++) {
                int f = warp_n * 64 + nb * 8 + ((lane & 3) << 1);
                *(uint32_t*)(g_w + rowbase + f) =
                    pack2h(c[mb][nb][half*2+0] * inv, c[mb][nb][half*2+1] * inv);
            }
        }
}

// ---------------- att mma (fp16 single) ----------------
#define AROW 72
#define AA 0
#define AB 18432
#define ASTAGE 36864
#define ATT_SMEM (2*ASTAGE)

__device__ __forceinline__ void att_load_stage(
    uint32_t bufo, int f0, size_t abase, size_t bbase, int lrow, int lch)
{
    #pragma unroll
    for (int p = 0; p < 4; p++) {
        int row = lrow + p * 32;
        size_t asrc = abase + (size_t)row * 256 + f0 + lch * 8;
        size_t bsrc = bbase + (size_t)row * 256 + f0 + lch * 8;
        uint32_t doff = (uint32_t)(row * AROW + lch * 8) * 2;
        cp16(bufo + AA + doff, g_vp + asrc, 16u);
        cp16(bufo + AB + doff, g_w + bsrc, 16u);
    }
    asm volatile("cp.async.commit_group;" ::: "memory");
}

__global__ __launch_bounds__(256) void att_mma_kernel(const float* __restrict__ x,
                                                      float* __restrict__ out) {
    extern __shared__ char smem[];
    uint32_t sb = smem_u32(smem);
    int t = threadIdx.x, lane = t & 31, wid = t >> 5;
    int warp_m = wid >> 1, warp_n = wid & 1;
    int bh = blockIdx.x, chalf = blockIdx.y;
    int b = bh >> 3, h = bh & 7;
    size_t abase = ((size_t)b * 784 + h * 98) * 256;
    size_t bbase = ((size_t)bh * 256 + chalf * 128) * 256;

    int lrow = t >> 3, lch = t & 7;

    att_load_stage(sb, 0, abase, bbase, lrow, lch);

    float c[2][8][4];
    #pragma unroll
    for (int mb = 0; mb < 2; mb++)
        #pragma unroll
        for (int nb = 0; nb < 8; nb++)
            #pragma unroll
            for (int r = 0; r < 4; r++) c[mb][nb][r] = 0.f;

    int a_r = lane & 15;
    int a_c = (lane >> 4) << 3;
    int b_r = (lane & 7) | ((lane & 16) >> 1);
    int b_c = lane & 8;

    for (int s = 0; s < 4; s++) {
        if (s + 1 < 4) {
            att_load_stage(sb + (uint32_t)((s + 1) & 1) * ASTAGE, (s + 1) << 6,
                           abase, bbase, lrow, lch);
            asm volatile("cp.async.wait_group 1;" ::: "memory");
        } else {
            asm volatile("cp.async.wait_group 0;" ::: "memory");
        }
        __syncthreads();

        uint32_t bufo = sb + (uint32_t)(s & 1) * ASTAGE;
        #pragma unroll
        for (int kk = 0; kk < 4; kk++) {
            int k0 = kk << 4;
            uint32_t a[2][4];
            #pragma unroll
            for (int mb = 0; mb < 2; mb++) {
                uint32_t off = (uint32_t)((warp_m * 32 + mb * 16 + a_r) * AROW + k0 + a_c) * 2;
                ldsm_x4(a[mb], bufo + AA + off);
            }
            uint32_t bfr[8][2];
            #pragma unroll
            for (int nb2 = 0; nb2 < 4; nb2++) {
                uint32_t off = (uint32_t)((warp_n * 64 + nb2 * 16 + b_r) * AROW + k0 + b_c) * 2;
                uint32_t r4[4];
                ldsm_x4(r4, bufo + AB + off);
                bfr[nb2*2][0] = r4[0]; bfr[nb2*2][1] = r4[1];
                bfr[nb2*2+1][0] = r4[2]; bfr[nb2*2+1][1] = r4[3];
            }
            #pragma unroll
            for (int mb = 0; mb < 2; mb++)
                #pragma unroll
                for (int nb = 0; nb < 8; nb++)
                    mma16816h(c[mb][nb], a[mb], bfr[nb]);
        }
        __syncthreads();
    }

    #pragma unroll
    for (int mb = 0; mb < 2; mb++)
        #pragma unroll
        for (int half = 0; half < 2; half++) {
            int d = warp_m * 32 + mb * 16 + (lane >> 2) + half * 8;
            if (d < 98) {
                size_t rowo = abase + (size_t)d * 256 + chalf * 128;
                #pragma unroll
                for (int nb = 0; nb < 8; nb++) {
                    int cg = warp_n * 64 + nb * 8 + ((lane & 3) << 1);
                    float2 xv = *(const float2*)(x + rowo + cg);
                    *(float2*)(out + rowo + cg) =
                        make_float2(xv.x + c[mb][nb][half*2+0], xv.y + c[mb][nb][half*2+1]);
                }
            }
        }
}

// ---------------- launch: two-stream overlap ----------------
extern "C" void kernel_launch(void* const* d_in, const int* in_sizes, int n_in,
                              void* d_out, int out_size) {
    const float* x     = (const float*)d_in[0];
    const float* wqk_w = (const float*)d_in[1];
    const float* wqk_b = (const float*)d_in[2];
    const float* wp_w  = (const float*)d_in[3];
    const float* wp_b  = (const float*)d_in[4];
    const float* wv_w  = (const float*)d_in[5];
    const float* wv_b  = (const float*)d_in[6];
    float* out = (float*)d_out;

    cudaFuncSetAttribute(conv_mma_kernel, cudaFuncAttributeMaxDynamicSharedMemorySize, CONV_SMEM);
    cudaFuncSetAttribute(scores_softmax_kernel, cudaFuncAttributeMaxDynamicSharedMemorySize, SS_SMEM);
    cudaFuncSetAttribute(proj_mma_kernel, cudaFuncAttributeMaxDynamicSharedMemorySize, PROJ_SMEM);
    cudaFuncSetAttribute(att_mma_kernel, cudaFuncAttributeMaxDynamicSharedMemorySize, ATT_SMEM);

    cudaStream_t sB;
    cudaStreamCreateWithFlags(&sB, cudaStreamNonBlocking);
    cudaEvent_t eFork, eJoin;
    cudaEventCreateWithFlags(&eFork, cudaEventDisableTiming);
    cudaEventCreateWithFlags(&eJoin, cudaEventDisableTiming);

    cudaEventRecord(eFork, (cudaStream_t)0);
    cudaStreamWaitEvent(sB, eFork, 0);
    poolqkT_kernel<<<512, 256, 0, sB>>>(x);
    wqkT_kernel<<<8, 128, 0, sB>>>(wqk_w);
    proj_mma_kernel<<<dim3(512, 2, 2), 256, PROJ_SMEM, sB>>>(wqk_b);
    temp_kernel<<<512, 256, 0, sB>>>(wp_w, wp_b);
    scores_softmax_kernel<<<dim3(512, 4), 256, SS_SMEM, sB>>>();
    cudaEventRecord(eJoin, sB);

    split_x_kernel<<<12544, 256>>>(x);
    split_w_kernel<<<2304, 256>>>(wv_w);
    conv_mma_kernel<<<dim3(392, 2), 256, CONV_SMEM>>>(wv_b);
    pool_v_kernel<<<Bz * Ss, 256>>>();

    cudaStreamWaitEvent((cudaStream_t)0, eJoin, 0);
    att_mma_kernel<<<dim3(512, 2), 256, ATT_SMEM>>>(x, out);

    cudaEventDestroy(eFork);
    cudaEventDestroy(eJoin);
    cudaStreamDestroy(sB);
}